// round 7
// baseline (speedup 1.0000x reference)
#include <cuda_runtime.h>
#include <cuda_fp16.h>
#include <math.h>
#include <cstdint>

#define BATCH   2
#define S_LEN   2048
#define D_MODEL 2048
#define NHEADS  32
#define NKVH    8
#define HDIM    64
#define GSIZE   (NHEADS / NKVH)
#define KVD     (NKVH * HDIM)        // 512
#define MROWS   (BATCH * S_LEN)      // 4096
#define KDIM    2048
#define KEFF2   (2 * KDIM)           // 4096 stacked K (hi|lo)
#define NKV2    (2 * KVD)            // 1024 fused K|V output width

// ---------------- scratch (device globals) ----------------------------------
__device__ float g_q  [MROWS * D_MODEL];
__device__ float g_kv [MROWS * NKV2];               // [K | V] fused fp32
__device__ float g_ctx[MROWS * D_MODEL];
__device__ __half g_ahat[(size_t)MROWS  * KEFF2];   // activations: hi|lo
__device__ __half g_wq [(size_t)D_MODEL * KDIM];    // weights: hi only (transposed)
__device__ __half g_wkv[(size_t)NKV2    * KDIM];    // [Wk^T ; Wv^T]
__device__ __half g_wo [(size_t)D_MODEL * KDIM];
__device__ float g_cos[S_LEN * 32];
__device__ float g_sin[S_LEN * 32];
__device__ __half g_qhi[MROWS * D_MODEL];
__device__ __half g_qlo[MROWS * D_MODEL];
__device__ __half g_khi[MROWS * KVD];
__device__ __half g_vhi[MROWS * KVD];

// ---------------- helpers ------------------------------------------------
__device__ __forceinline__ uint32_t smem_u32(const void* p) {
    uint32_t a;
    asm("{ .reg .u64 t; cvta.to.shared.u64 t, %1; cvt.u32.u64 %0, t; }"
        : "=r"(a) : "l"(p));
    return a;
}

__device__ __forceinline__ void cp16(uint32_t saddr, const void* gaddr) {
    asm volatile("cp.async.cg.shared.global [%0], [%1], 16;"
                 :: "r"(saddr), "l"(gaddr) : "memory");
}
#define CP_COMMIT() asm volatile("cp.async.commit_group;" ::: "memory")
#define CP_WAIT(n)  asm volatile("cp.async.wait_group %0;" :: "n"(n) : "memory")

__device__ __forceinline__ void ldsm4(uint32_t& r0, uint32_t& r1, uint32_t& r2,
                                      uint32_t& r3, uint32_t addr) {
    asm volatile("ldmatrix.sync.aligned.m8n8.x4.shared.b16 {%0,%1,%2,%3}, [%4];"
                 : "=r"(r0), "=r"(r1), "=r"(r2), "=r"(r3) : "r"(addr));
}
__device__ __forceinline__ void ldsm4t(uint32_t& r0, uint32_t& r1, uint32_t& r2,
                                       uint32_t& r3, uint32_t addr) {
    asm volatile("ldmatrix.sync.aligned.m8n8.x4.trans.shared.b16 {%0,%1,%2,%3}, [%4];"
                 : "=r"(r0), "=r"(r1), "=r"(r2), "=r"(r3) : "r"(addr));
}

__device__ __forceinline__ void mma16816(float* d, const uint32_t* a, const uint32_t* b) {
    asm volatile(
        "mma.sync.aligned.m16n8k16.row.col.f32.f16.f16.f32 "
        "{%0,%1,%2,%3}, {%4,%5,%6,%7}, {%8,%9}, {%0,%1,%2,%3};"
        : "+f"(d[0]), "+f"(d[1]), "+f"(d[2]), "+f"(d[3])
        : "r"(a[0]), "r"(a[1]), "r"(a[2]), "r"(a[3]), "r"(b[0]), "r"(b[1]));
}

__device__ __forceinline__ uint32_t pack2h(float lo_e, float hi_e) {
    __half2 h = __floats2half2_rn(lo_e, hi_e);
    return *reinterpret_cast<uint32_t*>(&h);
}

// ---------------- conversion kernels -----------------------------------------
__global__ void conv_split(const float* __restrict__ in, __half* __restrict__ out,
                           int total)
{
    int i = blockIdx.x * blockDim.x + threadIdx.x;
    if (i >= total) return;
    int row = i / KDIM, col = i - row * KDIM;
    float v = in[i];
    __half hi = __float2half_rn(v);
    __half lo = __float2half_rn(v - __half2float(hi));
    size_t base = (size_t)row * KEFF2 + col;
    out[base]        = hi;
    out[base + KDIM] = lo;
}

__global__ void conv_wt(const float* __restrict__ W, __half* __restrict__ out, int N)
{
    __shared__ float tile[32][33];
    int k0 = blockIdx.y * 32, n0 = blockIdx.x * 32;
    int tx = threadIdx.x, ty = threadIdx.y;
    tile[ty][tx] = W[(size_t)(k0 + ty) * N + n0 + tx];
    __syncthreads();
    out[(size_t)(n0 + ty) * KDIM + k0 + tx] = __float2half_rn(tile[tx][ty]);
}

// ---------------- multistage cp.async HMMA GEMM (128x256, warp 64x64) --------
#define BMG 128
#define BNG 256
#define KC 32
#define NCHUNK (KEFF2 / KC)    // 128
#define STAGES 4
#define STG_A  10240           // 128 rows * 80 B
#define STG_B  20480           // 256 rows * 80 B
#define STG_SZ (STG_A + STG_B) // 30720
#define GSMEM  (STAGES * STG_SZ)   // 122880

__global__ __launch_bounds__(256, 1)
void gemm_hmma(const __half* __restrict__ A, const __half* __restrict__ B,
               float* __restrict__ C, int N)
{
    extern __shared__ char gsm[];
    const uint32_t sbase = smem_u32(gsm);

    const int tid  = threadIdx.x;
    const int wid  = tid >> 5;
    const int lane = tid & 31;
    const int bm   = blockIdx.y * BMG;
    const int bn   = blockIdx.x * BNG;
    const int wm   = (wid & 1) * 64;      // 2 warps in M
    const int wn   = (wid >> 1) * 64;     // 4 warps in N

    float acc[4][8][4];
    #pragma unroll
    for (int i = 0; i < 4; i++)
        #pragma unroll
        for (int j = 0; j < 8; j++)
            #pragma unroll
            for (int t = 0; t < 4; t++) acc[i][j][t] = 0.f;

    const int r0 = tid >> 2;       // 0..63
    const int s0 = tid & 3;        // 0..3

    const __half* Ab = A + (size_t)bm * KEFF2;
    const __half* Bb = B + (size_t)bn * KDIM;

    const int a_row  = wm + (lane & 15);
    const int a_koff = ((lane >> 4) & 1) * 8;
    const int b_row_base = wn + (lane & 7) + ((lane >> 4) & 1) * 8;
    const int b_koff = ((lane >> 3) & 1) * 8;

    auto fill = [&](int c, int slot) {
        const int kposA = c * KC;
        const int kposB = kposA & (KDIM - 1);   // B wraps: hi reused for lo half
        const uint32_t abase = sbase + slot * STG_SZ;
        const uint32_t bbase = abase + STG_A;
        // A: 128 rows x 4 segs = 512 -> 2/thread
        #pragma unroll
        for (int i = 0; i < 2; i++) {
            int u = tid + 256 * i;
            int row = u >> 2, seg = u & 3;
            cp16(abase + row * 80 + seg * 16, Ab + (size_t)row * KEFF2 + kposA + seg * 8);
        }
        // B: 256 rows x 4 segs = 1024 -> 4/thread
        #pragma unroll
        for (int i = 0; i < 4; i++) {
            int u = tid + 256 * i;
            int row = u >> 2, seg = u & 3;
            cp16(bbase + row * 80 + seg * 16, Bb + (size_t)row * KDIM + kposB + seg * 8);
        }
    };

    #pragma unroll
    for (int s = 0; s < STAGES - 1; s++) {
        fill(s, s);
        CP_COMMIT();
    }

    for (int c = 0; c < NCHUNK; c++) {
        CP_WAIT(STAGES - 2);
        __syncthreads();

        if (c + STAGES - 1 < NCHUNK)
            fill(c + STAGES - 1, (c + STAGES - 1) % STAGES);
        CP_COMMIT();

        const int slot = c % STAGES;
        const uint32_t abase = sbase + slot * STG_SZ;
        const uint32_t bbase = abase + STG_A;
        #pragma unroll
        for (int ks = 0; ks < 2; ks++) {
            const int kp = ks * 16;
            uint32_t af[4][4];
            #pragma unroll
            for (int mt = 0; mt < 4; mt++) {
                uint32_t addr = abase + (a_row + mt * 16) * 80 + (kp + a_koff) * 2;
                ldsm4(af[mt][0], af[mt][1], af[mt][2], af[mt][3], addr);
            }
            uint32_t bf[8][2];
            #pragma unroll
            for (int bt = 0; bt < 4; bt++) {
                uint32_t addr = bbase + (b_row_base + bt * 16) * 80 + (kp + b_koff) * 2;
                ldsm4(bf[2*bt][0], bf[2*bt][1], bf[2*bt+1][0], bf[2*bt+1][1], addr);
            }
            #pragma unroll
            for (int mt = 0; mt < 4; mt++)
                #pragma unroll
                for (int nt = 0; nt < 8; nt++)
                    mma16816(acc[mt][nt], af[mt], bf[nt]);
        }
    }

    const int cr = lane >> 2;
    const int cc = (lane & 3) * 2;
    #pragma unroll
    for (int mt = 0; mt < 4; mt++) {
        #pragma unroll
        for (int nt = 0; nt < 8; nt++) {
            float* p0 = C + (size_t)(bm + wm + mt * 16 + cr) * N + bn + wn + nt * 8 + cc;
            float* p1 = p0 + 8 * (size_t)N;
            p0[0] = acc[mt][nt][0]; p0[1] = acc[mt][nt][1];
            p1[0] = acc[mt][nt][2]; p1[1] = acc[mt][nt][3];
        }
    }
}

// ---------------- RoPE --------------------------------------------------------
__global__ void rope_table()
{
    int i = blockIdx.x * blockDim.x + threadIdx.x;
    if (i >= S_LEN * 32) return;
    int s = i >> 5, j = i & 31;
    float inv = (float)exp(-(double)j * (log(10000.0) / 32.0));
    float ang = (float)s * inv;
    float c, sn;
    sincosf(ang, &sn, &c);
    g_cos[i] = c;
    g_sin[i] = sn;
}

__global__ void rope_split_q(const float* __restrict__ src,
                             __half* __restrict__ hi, __half* __restrict__ lo,
                             int total_pairs)
{
    int idx = blockIdx.x * blockDim.x + threadIdx.x;
    if (idx >= total_pairs) return;
    int j   = idx & 31;
    int t   = idx >> 5;
    int h   = t % NHEADS;
    int row = t / NHEADS;
    int s   = row & (S_LEN - 1);
    float c  = g_cos[(s << 5) + j];
    float sn = g_sin[(s << 5) + j];
    size_t off = (size_t)row * D_MODEL + h * HDIM + j;
    float x1 = src[off], x2 = src[off + 32];
    float y1 = (x1 * c - x2 * sn) * 0.125f;
    float y2 = (x2 * c + x1 * sn) * 0.125f;
    __half h1 = __float2half_rn(y1);
    __half h2 = __float2half_rn(y2);
    hi[off]      = h1;
    hi[off + 32] = h2;
    lo[off]      = __float2half_rn(y1 - __half2float(h1));
    lo[off + 32] = __float2half_rn(y2 - __half2float(h2));
}

// k from fused kv buffer (row stride 1024, k at cols 0..511)
__global__ void rope_half_k(const float* __restrict__ kv, __half* __restrict__ hi,
                            int total_pairs)
{
    int idx = blockIdx.x * blockDim.x + threadIdx.x;
    if (idx >= total_pairs) return;
    int j   = idx & 31;
    int t   = idx >> 5;
    int h   = t % NKVH;
    int row = t / NKVH;
    int s   = row & (S_LEN - 1);
    float c  = g_cos[(s << 5) + j];
    float sn = g_sin[(s << 5) + j];
    size_t soff = (size_t)row * NKV2 + h * HDIM + j;
    size_t doff = (size_t)row * KVD  + h * HDIM + j;
    float x1 = kv[soff], x2 = kv[soff + 32];
    hi[doff]      = __float2half_rn(x1 * c - x2 * sn);
    hi[doff + 32] = __float2half_rn(x2 * c + x1 * sn);
}

// v from fused kv buffer (cols 512..1023)
__global__ void v_half(const float* __restrict__ kv, __half* __restrict__ hi, int total)
{
    int i = blockIdx.x * blockDim.x + threadIdx.x;
    if (i >= total) return;
    int row = i >> 9, c = i & 511;
    hi[i] = __float2half_rn(kv[(size_t)row * NKV2 + KVD + c]);
}

// ---------------- HMMA causal GQA flash attention (unchanged from R6) --------
#define AT_STRB 144

__global__ __launch_bounds__(256, 1)
void attn_hmma(const __half* __restrict__ qhi, const __half* __restrict__ qlo,
               const __half* __restrict__ khi, const __half* __restrict__ vhi,
               float* __restrict__ ctx)
{
    __shared__ __align__(16) char sm[2 * 128 * AT_STRB];

    const int qb  = gridDim.x - 1 - blockIdx.x;
    const int h   = blockIdx.y;
    const int b   = blockIdx.z;
    const int kvh = h / GSIZE;
    const int tid = threadIdx.x;
    const int wid = tid >> 5;
    const int lane = tid & 31;
    const int qrow0 = qb * 128;
    const int wm = wid * 16;

    const uint32_t sbase = smem_u32(sm);

    {
        const __half* srcs[2] = {qhi, qlo};
        #pragma unroll
        for (int arr = 0; arr < 2; arr++) {
            const __half* s = srcs[arr];
            #pragma unroll
            for (int i = 0; i < 4; i++) {
                int u = tid + 256 * i;
                int row = u >> 3, seg = u & 7;
                uint4 v = *(const uint4*)(s + ((size_t)(b * S_LEN + qrow0 + row)) * D_MODEL
                                            + h * HDIM + seg * 8);
                *(uint4*)(sm + arr * (128 * AT_STRB) + row * AT_STRB + seg * 16) = v;
            }
        }
    }
    __syncthreads();

    uint32_t qh[4][4], ql[4][4];
    {
        uint32_t arow = (uint32_t)(wm + (lane & 15));
        uint32_t koff = ((lane >> 4) & 1) * 8;
        #pragma unroll
        for (int kc = 0; kc < 4; kc++) {
            uint32_t a0 = sbase + arow * AT_STRB + (kc * 16 + koff) * 2;
            ldsm4(qh[kc][0], qh[kc][1], qh[kc][2], qh[kc][3], a0);
            ldsm4(ql[kc][0], ql[kc][1], ql[kc][2], ql[kc][3], a0 + 128 * AT_STRB);
        }
    }

    float m0 = -1e30f, m1 = -1e30f, l0 = 0.f, l1 = 0.f;
    float ctxa[8][4];
    #pragma unroll
    for (int t = 0; t < 8; t++)
        #pragma unroll
        for (int j = 0; j < 4; j++) ctxa[t][j] = 0.f;

    const int nkt = 2 * qb + 2;
    const int VOFF = 64 * AT_STRB;

    for (int kt = 0; kt < nkt; kt++) {
        const int k0 = kt * 64;
        __syncthreads();
        {
            const __half* srcs[2] = {khi, vhi};
            #pragma unroll
            for (int arr = 0; arr < 2; arr++) {
                const __half* s = srcs[arr];
                #pragma unroll
                for (int i = 0; i < 2; i++) {
                    int u = tid + 256 * i;
                    int row = u >> 3, seg = u & 7;
                    uint4 v = *(const uint4*)(s + ((size_t)(b * S_LEN + k0 + row)) * KVD
                                                + kvh * HDIM + seg * 8);
                    *(uint4*)(sm + arr * VOFF + row * AT_STRB + seg * 16) = v;
                }
            }
        }
        __syncthreads();

        if (k0 <= qrow0 + wm + 15) {
            float sc[8][4];
            #pragma unroll
            for (int t = 0; t < 8; t++)
                #pragma unroll
                for (int j = 0; j < 4; j++) sc[t][j] = 0.f;

            #pragma unroll
            for (int g = 0; g < 4; g++) {
                uint32_t kh[4][4];
                #pragma unroll
                for (int kc = 0; kc < 4; kc++) {
                    uint32_t addr = sbase
                        + (g * 16 + (lane & 7) + ((lane >> 4) & 1) * 8) * AT_STRB
                        + (kc * 16 + ((lane >> 3) & 1) * 8) * 2;
                    ldsm4(kh[kc][0], kh[kc][1], kh[kc][2], kh[kc][3], addr);
                }
                #pragma unroll
                for (int kc = 0; kc < 4; kc++) {
                    uint32_t bh0[2] = {kh[kc][0], kh[kc][1]};
                    uint32_t bh1[2] = {kh[kc][2], kh[kc][3]};
                    mma16816(sc[2*g],   qh[kc], bh0);
                    mma16816(sc[2*g],   ql[kc], bh0);
                    mma16816(sc[2*g+1], qh[kc], bh1);
                    mma16816(sc[2*g+1], ql[kc], bh1);
                }
            }

            const int rtop = qrow0 + wm + (lane >> 2);
            const int rbot = rtop + 8;
            if (kt >= nkt - 2) {
                #pragma unroll
                for (int t = 0; t < 8; t++) {
                    int kg = k0 + t * 8 + (lane & 3) * 2;
                    if (kg     > rtop) sc[t][0] = -1e30f;
                    if (kg + 1 > rtop) sc[t][1] = -1e30f;
                    if (kg     > rbot) sc[t][2] = -1e30f;
                    if (kg + 1 > rbot) sc[t][3] = -1e30f;
                }
            }

            float tm0 = -1e30f, tm1 = -1e30f;
            #pragma unroll
            for (int t = 0; t < 8; t++) {
                tm0 = fmaxf(tm0, fmaxf(sc[t][0], sc[t][1]));
                tm1 = fmaxf(tm1, fmaxf(sc[t][2], sc[t][3]));
            }
            tm0 = fmaxf(tm0, __shfl_xor_sync(0xFFFFFFFFu, tm0, 1));
            tm0 = fmaxf(tm0, __shfl_xor_sync(0xFFFFFFFFu, tm0, 2));
            tm1 = fmaxf(tm1, __shfl_xor_sync(0xFFFFFFFFu, tm1, 1));
            tm1 = fmaxf(tm1, __shfl_xor_sync(0xFFFFFFFFu, tm1, 2));
            float mn0 = fmaxf(m0, tm0), mn1 = fmaxf(m1, tm1);
            float c0 = __expf(m0 - mn0), c1 = __expf(m1 - mn1);
            m0 = mn0; m1 = mn1;
            l0 *= c0;  l1 *= c1;
            #pragma unroll
            for (int t = 0; t < 8; t++) {
                ctxa[t][0] *= c0; ctxa[t][1] *= c0;
                ctxa[t][2] *= c1; ctxa[t][3] *= c1;
            }

            float ps0 = 0.f, ps1 = 0.f;
            uint32_t ph[4][4], pl[4][4];
            #pragma unroll
            for (int t = 0; t < 8; t++) {
                float p0 = __expf(sc[t][0] - mn0);
                float p1 = __expf(sc[t][1] - mn0);
                float p2 = __expf(sc[t][2] - mn1);
                float p3 = __expf(sc[t][3] - mn1);
                ps0 += p0 + p1; ps1 += p2 + p3;
                uint32_t hp01 = pack2h(p0, p1);
                uint32_t hp23 = pack2h(p2, p3);
                __half2 h01 = *reinterpret_cast<__half2*>(&hp01);
                __half2 h23 = *reinterpret_cast<__half2*>(&hp23);
                uint32_t lp01 = pack2h(p0 - __low2float(h01), p1 - __high2float(h01));
                uint32_t lp23 = pack2h(p2 - __low2float(h23), p3 - __high2float(h23));
                int kc = t >> 1, hf = (t & 1) * 2;
                ph[kc][hf]     = hp01;  ph[kc][hf + 1] = hp23;
                pl[kc][hf]     = lp01;  pl[kc][hf + 1] = lp23;
            }
            ps0 += __shfl_xor_sync(0xFFFFFFFFu, ps0, 1);
            ps0 += __shfl_xor_sync(0xFFFFFFFFu, ps0, 2);
            ps1 += __shfl_xor_sync(0xFFFFFFFFu, ps1, 1);
            ps1 += __shfl_xor_sync(0xFFFFFFFFu, ps1, 2);
            l0 += ps0; l1 += ps1;

            #pragma unroll
            for (int kc = 0; kc < 4; kc++) {
                #pragma unroll
                for (int g = 0; g < 4; g++) {
                    uint32_t vh[4];
                    uint32_t addr = sbase + VOFF
                        + (kc * 16 + (lane & 7) + ((lane >> 3) & 1) * 8) * AT_STRB
                        + (g * 16 + ((lane >> 4) & 1) * 8) * 2;
                    ldsm4t(vh[0], vh[1], vh[2], vh[3], addr);
                    uint32_t bh0[2] = {vh[0], vh[1]};
                    uint32_t bh1[2] = {vh[2], vh[3]};
                    mma16816(ctxa[2*g],   ph[kc], bh0);
                    mma16816(ctxa[2*g],   pl[kc], bh0);
                    mma16816(ctxa[2*g+1], ph[kc], bh1);
                    mma16816(ctxa[2*g+1], pl[kc], bh1);
                }
            }
        }
    }

    float il0 = 1.f / l0, il1 = 1.f / l1;
    const int rtop = qrow0 + wm + (lane >> 2);
    float* c0p = ctx + ((size_t)(b * S_LEN) + rtop) * D_MODEL + h * HDIM;
    float* c1p = c0p + 8 * (size_t)D_MODEL;
    #pragma unroll
    for (int t = 0; t < 8; t++) {
        int col = t * 8 + (lane & 3) * 2;
        c0p[col]     = ctxa[t][0] * il0;
        c0p[col + 1] = ctxa[t][1] * il0;
        c1p[col]     = ctxa[t][2] * il1;
        c1p[col + 1] = ctxa[t][3] * il1;
    }
}

// ---------------- host launch -------------------------------------------------
extern "C" void kernel_launch(void* const* d_in, const int* in_sizes, int n_in,
                              void* d_out, int out_size)
{
    const float* x  = (const float*)d_in[0];
    const float* Wq = (const float*)d_in[1];
    const float* Wk = (const float*)d_in[2];
    const float* Wv = (const float*)d_in[3];
    const float* Wo = (const float*)d_in[4];
    float* out = (float*)d_out;

    float *q, *kv, *ctx;
    __half *ahat, *wq, *wkv, *wo, *qhi, *qlo, *khi, *vhi;
    cudaGetSymbolAddress((void**)&q,    g_q);
    cudaGetSymbolAddress((void**)&kv,   g_kv);
    cudaGetSymbolAddress((void**)&ctx,  g_ctx);
    cudaGetSymbolAddress((void**)&ahat, g_ahat);
    cudaGetSymbolAddress((void**)&wq,   g_wq);
    cudaGetSymbolAddress((void**)&wkv,  g_wkv);
    cudaGetSymbolAddress((void**)&wo,   g_wo);
    cudaGetSymbolAddress((void**)&qhi,  g_qhi);
    cudaGetSymbolAddress((void**)&qlo,  g_qlo);
    cudaGetSymbolAddress((void**)&khi,  g_khi);
    cudaGetSymbolAddress((void**)&vhi,  g_vhi);

    static int smem_set = 0;
    if (!smem_set) {
        cudaFuncSetAttribute(gemm_hmma, cudaFuncAttributeMaxDynamicSharedMemorySize, GSMEM);
        smem_set = 1;
    }

    // conversions
    {
        int total = MROWS * KDIM;
        conv_split<<<(total + 255) / 256, 256>>>(x, ahat, total);
        dim3 blk(32, 32);
        conv_wt<<<dim3(D_MODEL / 32, KDIM / 32), blk>>>(Wq, wq, D_MODEL);
        conv_wt<<<dim3(KVD / 32,     KDIM / 32), blk>>>(Wk, wkv, KVD);
        conv_wt<<<dim3(KVD / 32,     KDIM / 32), blk>>>(Wv, wkv + (size_t)KVD * KDIM, KVD);
        conv_wt<<<dim3(D_MODEL / 32, KDIM / 32), blk>>>(Wo, wo, D_MODEL);
        rope_table<<<(S_LEN * 32 + 255) / 256, 256>>>();
    }

    // projections: Q (N=2048) and fused K|V (N=1024)
    gemm_hmma<<<dim3(D_MODEL / BNG, MROWS / BMG), 256, GSMEM>>>(ahat, wq, q, D_MODEL);
    gemm_hmma<<<dim3(NKV2 / BNG,    MROWS / BMG), 256, GSMEM>>>(ahat, wkv, kv, NKV2);

    // RoPE + fp16 conversion
    {
        int pairs_q = MROWS * NHEADS * 32;
        int pairs_k = MROWS * NKVH  * 32;
        rope_split_q<<<(pairs_q + 255) / 256, 256>>>(q, qhi, qlo, pairs_q);
        rope_half_k<<<(pairs_k + 255) / 256, 256>>>(kv, khi, pairs_k);
        int tv = MROWS * KVD;
        v_half<<<(tv + 255) / 256, 256>>>(kv, vhi, tv);
    }

    // attention
    attn_hmma<<<dim3(S_LEN / 128, NHEADS, BATCH), 256>>>(qhi, qlo, khi, vhi, ctx);

    // output projection
    {
        int total = MROWS * KDIM;
        conv_split<<<(total + 255) / 256, 256>>>(ctx, ahat, total);
        gemm_hmma<<<dim3(D_MODEL / BNG, MROWS / BMG), 256, GSMEM>>>(ahat, wo, out, D_MODEL);
    }
}

// round 8
// speedup vs baseline: 1.3397x; 1.3397x over previous
#include <cuda_runtime.h>
#include <cuda_fp16.h>
#include <math.h>
#include <cstdint>

#define BATCH   2
#define S_LEN   2048
#define D_MODEL 2048
#define NHEADS  32
#define NKVH    8
#define HDIM    64
#define GSIZE   (NHEADS / NKVH)
#define KVD     (NKVH * HDIM)        // 512
#define MROWS   (BATCH * S_LEN)      // 4096
#define KDIM    2048
#define KEFF2   (2 * KDIM)           // 4096 stacked K (hi|lo)
#define NKV2    (2 * KVD)            // 1024 fused K|V width

// ---------------- scratch (device globals) ----------------------------------
__device__ __half g_ahat[(size_t)MROWS  * KEFF2];   // activations hi|lo (x, later ctx)
__device__ __half g_wq [(size_t)D_MODEL * KDIM];
__device__ __half g_wkv[(size_t)NKV2    * KDIM];    // [Wk^T ; Wv^T]
__device__ __half g_wo [(size_t)D_MODEL * KDIM];
__device__ float g_cos[S_LEN * 32];
__device__ float g_sin[S_LEN * 32];
__device__ __half g_qhi[MROWS * D_MODEL];
__device__ __half g_qlo[MROWS * D_MODEL];
__device__ __half g_khi[MROWS * KVD];
__device__ __half g_vhi[MROWS * KVD];

// ---------------- helpers ------------------------------------------------
__device__ __forceinline__ uint32_t smem_u32(const void* p) {
    uint32_t a;
    asm("{ .reg .u64 t; cvta.to.shared.u64 t, %1; cvt.u32.u64 %0, t; }"
        : "=r"(a) : "l"(p));
    return a;
}

__device__ __forceinline__ void cp16(uint32_t saddr, const void* gaddr) {
    asm volatile("cp.async.cg.shared.global [%0], [%1], 16;"
                 :: "r"(saddr), "l"(gaddr) : "memory");
}
#define CP_COMMIT() asm volatile("cp.async.commit_group;" ::: "memory")
#define CP_WAIT(n)  asm volatile("cp.async.wait_group %0;" :: "n"(n) : "memory")

__device__ __forceinline__ void ldsm4(uint32_t& r0, uint32_t& r1, uint32_t& r2,
                                      uint32_t& r3, uint32_t addr) {
    asm volatile("ldmatrix.sync.aligned.m8n8.x4.shared.b16 {%0,%1,%2,%3}, [%4];"
                 : "=r"(r0), "=r"(r1), "=r"(r2), "=r"(r3) : "r"(addr));
}
__device__ __forceinline__ void ldsm4t(uint32_t& r0, uint32_t& r1, uint32_t& r2,
                                       uint32_t& r3, uint32_t addr) {
    asm volatile("ldmatrix.sync.aligned.m8n8.x4.trans.shared.b16 {%0,%1,%2,%3}, [%4];"
                 : "=r"(r0), "=r"(r1), "=r"(r2), "=r"(r3) : "r"(addr));
}

__device__ __forceinline__ void mma16816(float* d, const uint32_t* a, const uint32_t* b) {
    asm volatile(
        "mma.sync.aligned.m16n8k16.row.col.f32.f16.f16.f32 "
        "{%0,%1,%2,%3}, {%4,%5,%6,%7}, {%8,%9}, {%0,%1,%2,%3};"
        : "+f"(d[0]), "+f"(d[1]), "+f"(d[2]), "+f"(d[3])
        : "r"(a[0]), "r"(a[1]), "r"(a[2]), "r"(a[3]), "r"(b[0]), "r"(b[1]));
}

__device__ __forceinline__ uint32_t pack2h(float lo_e, float hi_e) {
    __half2 h = __floats2half2_rn(lo_e, hi_e);
    return *reinterpret_cast<uint32_t*>(&h);
}

// store y (2 adjacent floats) as hi half2 + lo half2
__device__ __forceinline__ void store_split2(__half* hi, __half* lo, size_t off,
                                             float ya, float yb) {
    __half2 h = __floats2half2_rn(ya, yb);
    *reinterpret_cast<__half2*>(hi + off) = h;
    __half2 l = __floats2half2_rn(ya - __low2float(h), yb - __high2float(h));
    *reinterpret_cast<__half2*>(lo + off) = l;
}

// ---------------- conversion kernels -----------------------------------------
__global__ void conv_split(const float* __restrict__ in, __half* __restrict__ out,
                           int total)
{
    int i = blockIdx.x * blockDim.x + threadIdx.x;
    if (i >= total) return;
    int row = i / KDIM, col = i - row * KDIM;
    float v = in[i];
    __half hi = __float2half_rn(v);
    __half lo = __float2half_rn(v - __half2float(hi));
    size_t base = (size_t)row * KEFF2 + col;
    out[base]        = hi;
    out[base + KDIM] = lo;
}

__global__ void conv_wt(const float* __restrict__ W, __half* __restrict__ out, int N)
{
    __shared__ float tile[32][33];
    int k0 = blockIdx.y * 32, n0 = blockIdx.x * 32;
    int tx = threadIdx.x, ty = threadIdx.y;
    tile[ty][tx] = W[(size_t)(k0 + ty) * N + n0 + tx];
    __syncthreads();
    out[(size_t)(n0 + ty) * KDIM + k0 + tx] = __float2half_rn(tile[tx][ty]);
}

__global__ void rope_table()
{
    int i = blockIdx.x * blockDim.x + threadIdx.x;
    if (i >= S_LEN * 32) return;
    int s = i >> 5, j = i & 31;
    float inv = (float)exp(-(double)j * (log(10000.0) / 32.0));
    float ang = (float)s * inv;
    float c, sn;
    sincosf(ang, &sn, &c);
    g_cos[i] = c;
    g_sin[i] = sn;
}

// ---------------- multistage cp.async HMMA GEMM (R6 shape) -------------------
// 128x128 CTA, 8 warps (4M x 2N), warp tile 32x64, KC=32, 4 stages.
// MODE 0: fp32 C store; MODE 1: Q epilogue (RoPE+scale+split -> H1/H2);
// MODE 2: KV epilogue (K: RoPE->H1 ; V: convert->H2)
#define BM 128
#define BN 128
#define KC 32
#define NCHUNK (KEFF2 / KC)    // 128
#define STAGES 4
#define STG_A  10240
#define STG_SZ 20480
#define GSMEM  (STAGES * STG_SZ)   // 81920

template<int MODE>
__global__ __launch_bounds__(256)
void gemm_hmma(const __half* __restrict__ A, const __half* __restrict__ B,
               float* __restrict__ C, __half* __restrict__ H1,
               __half* __restrict__ H2, int N)
{
    extern __shared__ char gsm[];
    const uint32_t sbase = smem_u32(gsm);

    const int tid  = threadIdx.x;
    const int wid  = tid >> 5;
    const int lane = tid & 31;
    const int bm   = blockIdx.y * BM;
    const int bn   = blockIdx.x * BN;
    const int wm   = (wid & 3) * 32;
    const int wn   = (wid >> 2) * 64;

    float acc[2][8][4];
    #pragma unroll
    for (int i = 0; i < 2; i++)
        #pragma unroll
        for (int j = 0; j < 8; j++)
            #pragma unroll
            for (int t = 0; t < 4; t++) acc[i][j][t] = 0.f;

    const int r0 = tid >> 2;
    const int s0 = tid & 3;

    const __half* Ab = A + (size_t)bm * KEFF2;
    const __half* Bb = B + (size_t)bn * KDIM;

    const int a_row  = wm + (lane & 15);
    const int a_koff = ((lane >> 4) & 1) * 8;
    const int b_row_base = wn + (lane & 7) + ((lane >> 4) & 1) * 8;
    const int b_koff = ((lane >> 3) & 1) * 8;

    auto fill = [&](int c, int slot) {
        const int kposA = c * KC;
        const int kposB = kposA & (KDIM - 1);
        const uint32_t abase = sbase + slot * STG_SZ;
        const uint32_t bbase = abase + STG_A;
        #pragma unroll
        for (int i = 0; i < 2; i++) {
            int u = tid + 256 * i;
            int row = u >> 2, seg = u & 3;
            cp16(abase + row * 80 + seg * 16, Ab + (size_t)row * KEFF2 + kposA + seg * 8);
            cp16(bbase + row * 80 + seg * 16, Bb + (size_t)row * KDIM  + kposB + seg * 8);
        }
    };

    #pragma unroll
    for (int s = 0; s < STAGES - 1; s++) {
        fill(s, s);
        CP_COMMIT();
    }

    for (int c = 0; c < NCHUNK; c++) {
        CP_WAIT(STAGES - 2);
        __syncthreads();

        if (c + STAGES - 1 < NCHUNK)
            fill(c + STAGES - 1, (c + STAGES - 1) % STAGES);
        CP_COMMIT();

        const int slot = c % STAGES;
        const uint32_t abase = sbase + slot * STG_SZ;
        const uint32_t bbase = abase + STG_A;
        #pragma unroll
        for (int ks = 0; ks < 2; ks++) {
            const int kp = ks * 16;
            uint32_t af[2][4];
            #pragma unroll
            for (int mt = 0; mt < 2; mt++) {
                uint32_t addr = abase + (a_row + mt * 16) * 80 + (kp + a_koff) * 2;
                ldsm4(af[mt][0], af[mt][1], af[mt][2], af[mt][3], addr);
            }
            uint32_t bf[8][2];
            #pragma unroll
            for (int bt = 0; bt < 4; bt++) {
                uint32_t addr = bbase + (b_row_base + bt * 16) * 80 + (kp + b_koff) * 2;
                ldsm4(bf[2*bt][0], bf[2*bt][1], bf[2*bt+1][0], bf[2*bt+1][1], addr);
            }
            #pragma unroll
            for (int mt = 0; mt < 2; mt++)
                #pragma unroll
                for (int nt = 0; nt < 8; nt++)
                    mma16816(acc[mt][nt], af[mt], bf[nt]);
        }
    }

    const int cr = lane >> 2;
    const int cc = (lane & 3) * 2;

    if (MODE == 0) {
        #pragma unroll
        for (int mt = 0; mt < 2; mt++) {
            #pragma unroll
            for (int nt = 0; nt < 8; nt++) {
                float* p0 = C + (size_t)(bm + wm + mt * 16 + cr) * N + bn + wn + nt * 8 + cc;
                float* p1 = p0 + 8 * (size_t)N;
                p0[0] = acc[mt][nt][0]; p0[1] = acc[mt][nt][1];
                p1[0] = acc[mt][nt][2]; p1[1] = acc[mt][nt][3];
            }
        }
    } else if (MODE == 1) {
        // Q: RoPE + 0.125 prescale + hi/lo split. Warp tile = one head.
        const int head = (bn + wn) >> 6;
        #pragma unroll
        for (int mt = 0; mt < 2; mt++) {
            #pragma unroll
            for (int r = 0; r < 2; r++) {
                const int row = bm + wm + mt * 16 + cr + r * 8;
                const int s = row & (S_LEN - 1);
                #pragma unroll
                for (int nt = 0; nt < 4; nt++) {
                    const int j = nt * 8 + cc;
                    float c0 = g_cos[(s << 5) + j],     sn0 = g_sin[(s << 5) + j];
                    float c1 = g_cos[(s << 5) + j + 1], sn1 = g_sin[(s << 5) + j + 1];
                    float x1a = acc[mt][nt][2*r],     x1b = acc[mt][nt][2*r + 1];
                    float x2a = acc[mt][nt+4][2*r],   x2b = acc[mt][nt+4][2*r + 1];
                    float y1a = (x1a * c0 - x2a * sn0) * 0.125f;
                    float y1b = (x1b * c1 - x2b * sn1) * 0.125f;
                    float y2a = (x2a * c0 + x1a * sn0) * 0.125f;
                    float y2b = (x2b * c1 + x1b * sn1) * 0.125f;
                    size_t off = (size_t)row * D_MODEL + head * HDIM + j;
                    store_split2(H1, H2, off,      y1a, y1b);
                    store_split2(H1, H2, off + 32, y2a, y2b);
                }
            }
        }
    } else {
        // KV: heads 0..7 = K (RoPE -> H1 hi only), 8..15 = V (convert -> H2)
        const int hh = (bn + wn) >> 6;
        if (hh < NKVH) {
            #pragma unroll
            for (int mt = 0; mt < 2; mt++) {
                #pragma unroll
                for (int r = 0; r < 2; r++) {
                    const int row = bm + wm + mt * 16 + cr + r * 8;
                    const int s = row & (S_LEN - 1);
                    #pragma unroll
                    for (int nt = 0; nt < 4; nt++) {
                        const int j = nt * 8 + cc;
                        float c0 = g_cos[(s << 5) + j],     sn0 = g_sin[(s << 5) + j];
                        float c1 = g_cos[(s << 5) + j + 1], sn1 = g_sin[(s << 5) + j + 1];
                        float x1a = acc[mt][nt][2*r],   x1b = acc[mt][nt][2*r + 1];
                        float x2a = acc[mt][nt+4][2*r], x2b = acc[mt][nt+4][2*r + 1];
                        size_t off = (size_t)row * KVD + hh * HDIM + j;
                        *reinterpret_cast<__half2*>(H1 + off) =
                            __floats2half2_rn(x1a * c0 - x2a * sn0, x1b * c1 - x2b * sn1);
                        *reinterpret_cast<__half2*>(H1 + off + 32) =
                            __floats2half2_rn(x2a * c0 + x1a * sn0, x2b * c1 + x1b * sn1);
                    }
                }
            }
        } else {
            const int vh = hh - NKVH;
            #pragma unroll
            for (int mt = 0; mt < 2; mt++) {
                #pragma unroll
                for (int r = 0; r < 2; r++) {
                    const int row = bm + wm + mt * 16 + cr + r * 8;
                    #pragma unroll
                    for (int nt = 0; nt < 8; nt++) {
                        size_t off = (size_t)row * KVD + vh * HDIM + nt * 8 + cc;
                        *reinterpret_cast<__half2*>(H2 + off) =
                            __floats2half2_rn(acc[mt][nt][2*r], acc[mt][nt][2*r + 1]);
                    }
                }
            }
        }
    }
}

// ---------------- HMMA causal GQA flash attention ----------------------------
// Epilogue writes ahat hi|lo stacked layout directly.
#define AT_STRB 144

__global__ __launch_bounds__(256, 1)
void attn_hmma(const __half* __restrict__ qhi, const __half* __restrict__ qlo,
               const __half* __restrict__ khi, const __half* __restrict__ vhi,
               __half* __restrict__ ahat)
{
    __shared__ __align__(16) char sm[2 * 128 * AT_STRB];

    const int qb  = gridDim.x - 1 - blockIdx.x;
    const int h   = blockIdx.y;
    const int b   = blockIdx.z;
    const int kvh = h / GSIZE;
    const int tid = threadIdx.x;
    const int wid = tid >> 5;
    const int lane = tid & 31;
    const int qrow0 = qb * 128;
    const int wm = wid * 16;

    const uint32_t sbase = smem_u32(sm);

    {
        const __half* srcs[2] = {qhi, qlo};
        #pragma unroll
        for (int arr = 0; arr < 2; arr++) {
            const __half* s = srcs[arr];
            #pragma unroll
            for (int i = 0; i < 4; i++) {
                int u = tid + 256 * i;
                int row = u >> 3, seg = u & 7;
                uint4 v = *(const uint4*)(s + ((size_t)(b * S_LEN + qrow0 + row)) * D_MODEL
                                            + h * HDIM + seg * 8);
                *(uint4*)(sm + arr * (128 * AT_STRB) + row * AT_STRB + seg * 16) = v;
            }
        }
    }
    __syncthreads();

    uint32_t qh[4][4], ql[4][4];
    {
        uint32_t arow = (uint32_t)(wm + (lane & 15));
        uint32_t koff = ((lane >> 4) & 1) * 8;
        #pragma unroll
        for (int kc = 0; kc < 4; kc++) {
            uint32_t a0 = sbase + arow * AT_STRB + (kc * 16 + koff) * 2;
            ldsm4(qh[kc][0], qh[kc][1], qh[kc][2], qh[kc][3], a0);
            ldsm4(ql[kc][0], ql[kc][1], ql[kc][2], ql[kc][3], a0 + 128 * AT_STRB);
        }
    }

    float m0 = -1e30f, m1 = -1e30f, l0 = 0.f, l1 = 0.f;
    float ctxa[8][4];
    #pragma unroll
    for (int t = 0; t < 8; t++)
        #pragma unroll
        for (int j = 0; j < 4; j++) ctxa[t][j] = 0.f;

    const int nkt = 2 * qb + 2;
    const int VOFF = 64 * AT_STRB;

    for (int kt = 0; kt < nkt; kt++) {
        const int k0 = kt * 64;
        __syncthreads();
        {
            const __half* srcs[2] = {khi, vhi};
            #pragma unroll
            for (int arr = 0; arr < 2; arr++) {
                const __half* s = srcs[arr];
                #pragma unroll
                for (int i = 0; i < 2; i++) {
                    int u = tid + 256 * i;
                    int row = u >> 3, seg = u & 7;
                    uint4 v = *(const uint4*)(s + ((size_t)(b * S_LEN + k0 + row)) * KVD
                                                + kvh * HDIM + seg * 8);
                    *(uint4*)(sm + arr * VOFF + row * AT_STRB + seg * 16) = v;
                }
            }
        }
        __syncthreads();

        if (k0 <= qrow0 + wm + 15) {
            float sc[8][4];
            #pragma unroll
            for (int t = 0; t < 8; t++)
                #pragma unroll
                for (int j = 0; j < 4; j++) sc[t][j] = 0.f;

            #pragma unroll
            for (int g = 0; g < 4; g++) {
                uint32_t kh[4][4];
                #pragma unroll
                for (int kc = 0; kc < 4; kc++) {
                    uint32_t addr = sbase
                        + (g * 16 + (lane & 7) + ((lane >> 4) & 1) * 8) * AT_STRB
                        + (kc * 16 + ((lane >> 3) & 1) * 8) * 2;
                    ldsm4(kh[kc][0], kh[kc][1], kh[kc][2], kh[kc][3], addr);
                }
                #pragma unroll
                for (int kc = 0; kc < 4; kc++) {
                    uint32_t bh0[2] = {kh[kc][0], kh[kc][1]};
                    uint32_t bh1[2] = {kh[kc][2], kh[kc][3]};
                    mma16816(sc[2*g],   qh[kc], bh0);
                    mma16816(sc[2*g],   ql[kc], bh0);
                    mma16816(sc[2*g+1], qh[kc], bh1);
                    mma16816(sc[2*g+1], ql[kc], bh1);
                }
            }

            const int rtop = qrow0 + wm + (lane >> 2);
            const int rbot = rtop + 8;
            if (kt >= nkt - 2) {
                #pragma unroll
                for (int t = 0; t < 8; t++) {
                    int kg = k0 + t * 8 + (lane & 3) * 2;
                    if (kg     > rtop) sc[t][0] = -1e30f;
                    if (kg + 1 > rtop) sc[t][1] = -1e30f;
                    if (kg     > rbot) sc[t][2] = -1e30f;
                    if (kg + 1 > rbot) sc[t][3] = -1e30f;
                }
            }

            float tm0 = -1e30f, tm1 = -1e30f;
            #pragma unroll
            for (int t = 0; t < 8; t++) {
                tm0 = fmaxf(tm0, fmaxf(sc[t][0], sc[t][1]));
                tm1 = fmaxf(tm1, fmaxf(sc[t][2], sc[t][3]));
            }
            tm0 = fmaxf(tm0, __shfl_xor_sync(0xFFFFFFFFu, tm0, 1));
            tm0 = fmaxf(tm0, __shfl_xor_sync(0xFFFFFFFFu, tm0, 2));
            tm1 = fmaxf(tm1, __shfl_xor_sync(0xFFFFFFFFu, tm1, 1));
            tm1 = fmaxf(tm1, __shfl_xor_sync(0xFFFFFFFFu, tm1, 2));
            float mn0 = fmaxf(m0, tm0), mn1 = fmaxf(m1, tm1);
            float c0 = __expf(m0 - mn0), c1 = __expf(m1 - mn1);
            m0 = mn0; m1 = mn1;
            l0 *= c0;  l1 *= c1;
            #pragma unroll
            for (int t = 0; t < 8; t++) {
                ctxa[t][0] *= c0; ctxa[t][1] *= c0;
                ctxa[t][2] *= c1; ctxa[t][3] *= c1;
            }

            float ps0 = 0.f, ps1 = 0.f;
            uint32_t ph[4][4], pl[4][4];
            #pragma unroll
            for (int t = 0; t < 8; t++) {
                float p0 = __expf(sc[t][0] - mn0);
                float p1 = __expf(sc[t][1] - mn0);
                float p2 = __expf(sc[t][2] - mn1);
                float p3 = __expf(sc[t][3] - mn1);
                ps0 += p0 + p1; ps1 += p2 + p3;
                uint32_t hp01 = pack2h(p0, p1);
                uint32_t hp23 = pack2h(p2, p3);
                __half2 h01 = *reinterpret_cast<__half2*>(&hp01);
                __half2 h23 = *reinterpret_cast<__half2*>(&hp23);
                uint32_t lp01 = pack2h(p0 - __low2float(h01), p1 - __high2float(h01));
                uint32_t lp23 = pack2h(p2 - __low2float(h23), p3 - __high2float(h23));
                int kc = t >> 1, hf = (t & 1) * 2;
                ph[kc][hf]     = hp01;  ph[kc][hf + 1] = hp23;
                pl[kc][hf]     = lp01;  pl[kc][hf + 1] = lp23;
            }
            ps0 += __shfl_xor_sync(0xFFFFFFFFu, ps0, 1);
            ps0 += __shfl_xor_sync(0xFFFFFFFFu, ps0, 2);
            ps1 += __shfl_xor_sync(0xFFFFFFFFu, ps1, 1);
            ps1 += __shfl_xor_sync(0xFFFFFFFFu, ps1, 2);
            l0 += ps0; l1 += ps1;

            #pragma unroll
            for (int kc = 0; kc < 4; kc++) {
                #pragma unroll
                for (int g = 0; g < 4; g++) {
                    uint32_t vh[4];
                    uint32_t addr = sbase + VOFF
                        + (kc * 16 + (lane & 7) + ((lane >> 3) & 1) * 8) * AT_STRB
                        + (g * 16 + ((lane >> 4) & 1) * 8) * 2;
                    ldsm4t(vh[0], vh[1], vh[2], vh[3], addr);
                    uint32_t bh0[2] = {vh[0], vh[1]};
                    uint32_t bh1[2] = {vh[2], vh[3]};
                    mma16816(ctxa[2*g],   ph[kc], bh0);
                    mma16816(ctxa[2*g],   pl[kc], bh0);
                    mma16816(ctxa[2*g+1], ph[kc], bh1);
                    mma16816(ctxa[2*g+1], pl[kc], bh1);
                }
            }
        }
    }

    // epilogue: split to fp16 hi|lo, write into ahat stacked layout
    float il0 = 1.f / l0, il1 = 1.f / l1;
    const int rtop = qrow0 + wm + (lane >> 2);
    const size_t row0 = (size_t)(b * S_LEN) + rtop;
    const size_t row1 = row0 + 8;
    __half* hi0 = g_ahat + row0 * KEFF2;   // note: param ahat == g_ahat
    __half* hi1 = g_ahat + row1 * KEFF2;
    #pragma unroll
    for (int t = 0; t < 8; t++) {
        int col = h * HDIM + t * 8 + (lane & 3) * 2;
        store_split2(hi0, hi0 + KDIM, (size_t)col, ctxa[t][0] * il0, ctxa[t][1] * il0);
        store_split2(hi1, hi1 + KDIM, (size_t)col, ctxa[t][2] * il1, ctxa[t][3] * il1);
    }
}

// ---------------- host launch -------------------------------------------------
extern "C" void kernel_launch(void* const* d_in, const int* in_sizes, int n_in,
                              void* d_out, int out_size)
{
    const float* x  = (const float*)d_in[0];
    const float* Wq = (const float*)d_in[1];
    const float* Wk = (const float*)d_in[2];
    const float* Wv = (const float*)d_in[3];
    const float* Wo = (const float*)d_in[4];
    float* out = (float*)d_out;

    __half *ahat, *wq, *wkv, *wo, *qhi, *qlo, *khi, *vhi;
    cudaGetSymbolAddress((void**)&ahat, g_ahat);
    cudaGetSymbolAddress((void**)&wq,   g_wq);
    cudaGetSymbolAddress((void**)&wkv,  g_wkv);
    cudaGetSymbolAddress((void**)&wo,   g_wo);
    cudaGetSymbolAddress((void**)&qhi,  g_qhi);
    cudaGetSymbolAddress((void**)&qlo,  g_qlo);
    cudaGetSymbolAddress((void**)&khi,  g_khi);
    cudaGetSymbolAddress((void**)&vhi,  g_vhi);

    static int smem_set = 0;
    if (!smem_set) {
        cudaFuncSetAttribute(gemm_hmma<0>, cudaFuncAttributeMaxDynamicSharedMemorySize, GSMEM);
        cudaFuncSetAttribute(gemm_hmma<1>, cudaFuncAttributeMaxDynamicSharedMemorySize, GSMEM);
        cudaFuncSetAttribute(gemm_hmma<2>, cudaFuncAttributeMaxDynamicSharedMemorySize, GSMEM);
        smem_set = 1;
    }

    // conversions
    {
        int total = MROWS * KDIM;
        conv_split<<<(total + 255) / 256, 256>>>(x, ahat, total);
        dim3 blk(32, 32);
        conv_wt<<<dim3(D_MODEL / 32, KDIM / 32), blk>>>(Wq, wq, D_MODEL);
        conv_wt<<<dim3(KVD / 32,     KDIM / 32), blk>>>(Wk, wkv, KVD);
        conv_wt<<<dim3(KVD / 32,     KDIM / 32), blk>>>(Wv, wkv + (size_t)KVD * KDIM, KVD);
        conv_wt<<<dim3(D_MODEL / 32, KDIM / 32), blk>>>(Wo, wo, D_MODEL);
        rope_table<<<(S_LEN * 32 + 255) / 256, 256>>>();
    }

    // Q projection with fused RoPE+split epilogue
    gemm_hmma<1><<<dim3(D_MODEL / BN, MROWS / BM), 256, GSMEM>>>(
        ahat, wq, nullptr, qhi, qlo, D_MODEL);
    // fused K|V projection with RoPE/convert epilogue
    gemm_hmma<2><<<dim3(NKV2 / BN, MROWS / BM), 256, GSMEM>>>(
        ahat, wkv, nullptr, khi, vhi, NKV2);

    // attention (writes ahat hi|lo directly)
    attn_hmma<<<dim3(S_LEN / 128, NHEADS, BATCH), 256>>>(qhi, qlo, khi, vhi, ahat);

    // output projection
    gemm_hmma<0><<<dim3(D_MODEL / BN, MROWS / BM), 256, GSMEM>>>(
        ahat, wo, out, nullptr, nullptr, D_MODEL);
}

// round 9
// speedup vs baseline: 1.5720x; 1.1734x over previous
#include <cuda_runtime.h>
#include <cuda_fp16.h>
#include <math.h>
#include <cstdint>

#define BATCH   2
#define S_LEN   2048
#define D_MODEL 2048
#define NHEADS  32
#define NKVH    8
#define HDIM    64
#define GSIZE   (NHEADS / NKVH)
#define KVD     (NKVH * HDIM)        // 512
#define MROWS   (BATCH * S_LEN)      // 4096
#define KDIM    2048
#define KEFF2   (2 * KDIM)           // 4096 stacked K (hi|lo)
#define NKV2    (2 * KVD)            // 1024 fused K|V width

// ---------------- scratch (device globals) ----------------------------------
__device__ __half g_ahat[(size_t)MROWS  * KEFF2];   // x hi|lo stacked
__device__ __half g_chat[(size_t)MROWS  * KDIM];    // ctx hi only
__device__ __half g_wq [(size_t)D_MODEL * KDIM];
__device__ __half g_wkv[(size_t)NKV2    * KDIM];    // [Wk^T ; Wv^T]
__device__ __half g_wo [(size_t)D_MODEL * KDIM];
__device__ float g_cos[S_LEN * 32];
__device__ float g_sin[S_LEN * 32];
__device__ __half g_qhi[MROWS * D_MODEL];
__device__ __half g_qlo[MROWS * D_MODEL];
__device__ __half g_khi[MROWS * KVD];
__device__ __half g_vhi[MROWS * KVD];

// ---------------- helpers ------------------------------------------------
__device__ __forceinline__ uint32_t smem_u32(const void* p) {
    uint32_t a;
    asm("{ .reg .u64 t; cvta.to.shared.u64 t, %1; cvt.u32.u64 %0, t; }"
        : "=r"(a) : "l"(p));
    return a;
}

__device__ __forceinline__ void cp16(uint32_t saddr, const void* gaddr) {
    asm volatile("cp.async.cg.shared.global [%0], [%1], 16;"
                 :: "r"(saddr), "l"(gaddr) : "memory");
}
#define CP_COMMIT() asm volatile("cp.async.commit_group;" ::: "memory")
#define CP_WAIT(n)  asm volatile("cp.async.wait_group %0;" :: "n"(n) : "memory")

__device__ __forceinline__ void ldsm4(uint32_t& r0, uint32_t& r1, uint32_t& r2,
                                      uint32_t& r3, uint32_t addr) {
    asm volatile("ldmatrix.sync.aligned.m8n8.x4.shared.b16 {%0,%1,%2,%3}, [%4];"
                 : "=r"(r0), "=r"(r1), "=r"(r2), "=r"(r3) : "r"(addr));
}
__device__ __forceinline__ void ldsm4t(uint32_t& r0, uint32_t& r1, uint32_t& r2,
                                       uint32_t& r3, uint32_t addr) {
    asm volatile("ldmatrix.sync.aligned.m8n8.x4.trans.shared.b16 {%0,%1,%2,%3}, [%4];"
                 : "=r"(r0), "=r"(r1), "=r"(r2), "=r"(r3) : "r"(addr));
}

__device__ __forceinline__ void mma16816(float* d, const uint32_t* a, const uint32_t* b) {
    asm volatile(
        "mma.sync.aligned.m16n8k16.row.col.f32.f16.f16.f32 "
        "{%0,%1,%2,%3}, {%4,%5,%6,%7}, {%8,%9}, {%0,%1,%2,%3};"
        : "+f"(d[0]), "+f"(d[1]), "+f"(d[2]), "+f"(d[3])
        : "r"(a[0]), "r"(a[1]), "r"(a[2]), "r"(a[3]), "r"(b[0]), "r"(b[1]));
}

__device__ __forceinline__ uint32_t pack2h(float lo_e, float hi_e) {
    __half2 h = __floats2half2_rn(lo_e, hi_e);
    return *reinterpret_cast<uint32_t*>(&h);
}

__device__ __forceinline__ void store_split2(__half* hi, __half* lo, size_t off,
                                             float ya, float yb) {
    __half2 h = __floats2half2_rn(ya, yb);
    *reinterpret_cast<__half2*>(hi + off) = h;
    __half2 l = __floats2half2_rn(ya - __low2float(h), yb - __high2float(h));
    *reinterpret_cast<__half2*>(lo + off) = l;
}

// ---------------- conversion kernels -----------------------------------------
__global__ void conv_split(const float* __restrict__ in, __half* __restrict__ out,
                           int total)
{
    int i = blockIdx.x * blockDim.x + threadIdx.x;
    if (i >= total) return;
    int row = i / KDIM, col = i - row * KDIM;
    float v = in[i];
    __half hi = __float2half_rn(v);
    __half lo = __float2half_rn(v - __half2float(hi));
    size_t base = (size_t)row * KEFF2 + col;
    out[base]        = hi;
    out[base + KDIM] = lo;
}

__global__ void conv_wt(const float* __restrict__ W, __half* __restrict__ out, int N)
{
    __shared__ float tile[32][33];
    int k0 = blockIdx.y * 32, n0 = blockIdx.x * 32;
    int tx = threadIdx.x, ty = threadIdx.y;
    tile[ty][tx] = W[(size_t)(k0 + ty) * N + n0 + tx];
    __syncthreads();
    out[(size_t)(n0 + ty) * KDIM + k0 + tx] = __float2half_rn(tile[tx][ty]);
}

__global__ void rope_table()
{
    int i = blockIdx.x * blockDim.x + threadIdx.x;
    if (i >= S_LEN * 32) return;
    int s = i >> 5, j = i & 31;
    float inv = (float)exp(-(double)j * (log(10000.0) / 32.0));
    float ang = (float)s * inv;
    float c, sn;
    sincosf(ang, &sn, &c);
    g_cos[i] = c;
    g_sin[i] = sn;
}

// ---------------- multistage cp.async HMMA GEMM ------------------------------
// 128x128 CTA, 8 warps (4M x 2N), warp tile 32x64, KC=32, 4 stages.
// KAS = A row stride / K extent. B wraps at KDIM.
// MODE 0: fp32 C; MODE 1: Q epilogue (RoPE+scale+split); MODE 2: KV epilogue.
#define BM 128
#define BN 128
#define KC 32
#define STAGES 4
#define STG_A  10240
#define STG_SZ 20480
#define GSMEM  (STAGES * STG_SZ)   // 81920

template<int MODE, int KAS>
__global__ __launch_bounds__(256)
void gemm_hmma(const __half* __restrict__ A, const __half* __restrict__ B,
               float* __restrict__ C, __half* __restrict__ H1,
               __half* __restrict__ H2, int N)
{
    extern __shared__ char gsm[];
    const uint32_t sbase = smem_u32(gsm);
    constexpr int NCHUNK = KAS / KC;

    const int tid  = threadIdx.x;
    const int wid  = tid >> 5;
    const int lane = tid & 31;
    const int bm   = blockIdx.y * BM;
    const int bn   = blockIdx.x * BN;
    const int wm   = (wid & 3) * 32;
    const int wn   = (wid >> 2) * 64;

    float acc[2][8][4];
    #pragma unroll
    for (int i = 0; i < 2; i++)
        #pragma unroll
        for (int j = 0; j < 8; j++)
            #pragma unroll
            for (int t = 0; t < 4; t++) acc[i][j][t] = 0.f;

    const __half* Ab = A + (size_t)bm * KAS;
    const __half* Bb = B + (size_t)bn * KDIM;

    const int a_row  = wm + (lane & 15);
    const int a_koff = ((lane >> 4) & 1) * 8;
    const int b_row_base = wn + (lane & 7) + ((lane >> 4) & 1) * 8;
    const int b_koff = ((lane >> 3) & 1) * 8;

    auto fill = [&](int c, int slot) {
        const int kposA = c * KC;
        const int kposB = kposA & (KDIM - 1);
        const uint32_t abase = sbase + slot * STG_SZ;
        const uint32_t bbase = abase + STG_A;
        #pragma unroll
        for (int i = 0; i < 2; i++) {
            int u = tid + 256 * i;
            int row = u >> 2, seg = u & 3;
            cp16(abase + row * 80 + seg * 16, Ab + (size_t)row * KAS  + kposA + seg * 8);
            cp16(bbase + row * 80 + seg * 16, Bb + (size_t)row * KDIM + kposB + seg * 8);
        }
    };

    #pragma unroll
    for (int s = 0; s < STAGES - 1; s++) {
        fill(s, s);
        CP_COMMIT();
    }

    for (int c = 0; c < NCHUNK; c++) {
        CP_WAIT(STAGES - 2);
        __syncthreads();

        if (c + STAGES - 1 < NCHUNK)
            fill(c + STAGES - 1, (c + STAGES - 1) % STAGES);
        CP_COMMIT();

        const int slot = c % STAGES;
        const uint32_t abase = sbase + slot * STG_SZ;
        const uint32_t bbase = abase + STG_A;
        #pragma unroll
        for (int ks = 0; ks < 2; ks++) {
            const int kp = ks * 16;
            uint32_t af[2][4];
            #pragma unroll
            for (int mt = 0; mt < 2; mt++) {
                uint32_t addr = abase + (a_row + mt * 16) * 80 + (kp + a_koff) * 2;
                ldsm4(af[mt][0], af[mt][1], af[mt][2], af[mt][3], addr);
            }
            uint32_t bf[8][2];
            #pragma unroll
            for (int bt = 0; bt < 4; bt++) {
                uint32_t addr = bbase + (b_row_base + bt * 16) * 80 + (kp + b_koff) * 2;
                ldsm4(bf[2*bt][0], bf[2*bt][1], bf[2*bt+1][0], bf[2*bt+1][1], addr);
            }
            #pragma unroll
            for (int mt = 0; mt < 2; mt++)
                #pragma unroll
                for (int nt = 0; nt < 8; nt++)
                    mma16816(acc[mt][nt], af[mt], bf[nt]);
        }
    }

    const int cr = lane >> 2;
    const int cc = (lane & 3) * 2;

    if (MODE == 0) {
        #pragma unroll
        for (int mt = 0; mt < 2; mt++) {
            #pragma unroll
            for (int nt = 0; nt < 8; nt++) {
                float* p0 = C + (size_t)(bm + wm + mt * 16 + cr) * N + bn + wn + nt * 8 + cc;
                float* p1 = p0 + 8 * (size_t)N;
                p0[0] = acc[mt][nt][0]; p0[1] = acc[mt][nt][1];
                p1[0] = acc[mt][nt][2]; p1[1] = acc[mt][nt][3];
            }
        }
    } else if (MODE == 1) {
        const int head = (bn + wn) >> 6;
        #pragma unroll
        for (int mt = 0; mt < 2; mt++) {
            #pragma unroll
            for (int r = 0; r < 2; r++) {
                const int row = bm + wm + mt * 16 + cr + r * 8;
                const int s = row & (S_LEN - 1);
                #pragma unroll
                for (int nt = 0; nt < 4; nt++) {
                    const int j = nt * 8 + cc;
                    float c0 = g_cos[(s << 5) + j],     sn0 = g_sin[(s << 5) + j];
                    float c1 = g_cos[(s << 5) + j + 1], sn1 = g_sin[(s << 5) + j + 1];
                    float x1a = acc[mt][nt][2*r],     x1b = acc[mt][nt][2*r + 1];
                    float x2a = acc[mt][nt+4][2*r],   x2b = acc[mt][nt+4][2*r + 1];
                    float y1a = (x1a * c0 - x2a * sn0) * 0.125f;
                    float y1b = (x1b * c1 - x2b * sn1) * 0.125f;
                    float y2a = (x2a * c0 + x1a * sn0) * 0.125f;
                    float y2b = (x2b * c1 + x1b * sn1) * 0.125f;
                    size_t off = (size_t)row * D_MODEL + head * HDIM + j;
                    store_split2(H1, H2, off,      y1a, y1b);
                    store_split2(H1, H2, off + 32, y2a, y2b);
                }
            }
        }
    } else {
        const int hh = (bn + wn) >> 6;
        if (hh < NKVH) {
            #pragma unroll
            for (int mt = 0; mt < 2; mt++) {
                #pragma unroll
                for (int r = 0; r < 2; r++) {
                    const int row = bm + wm + mt * 16 + cr + r * 8;
                    const int s = row & (S_LEN - 1);
                    #pragma unroll
                    for (int nt = 0; nt < 4; nt++) {
                        const int j = nt * 8 + cc;
                        float c0 = g_cos[(s << 5) + j],     sn0 = g_sin[(s << 5) + j];
                        float c1 = g_cos[(s << 5) + j + 1], sn1 = g_sin[(s << 5) + j + 1];
                        float x1a = acc[mt][nt][2*r],   x1b = acc[mt][nt][2*r + 1];
                        float x2a = acc[mt][nt+4][2*r], x2b = acc[mt][nt+4][2*r + 1];
                        size_t off = (size_t)row * KVD + hh * HDIM + j;
                        *reinterpret_cast<__half2*>(H1 + off) =
                            __floats2half2_rn(x1a * c0 - x2a * sn0, x1b * c1 - x2b * sn1);
                        *reinterpret_cast<__half2*>(H1 + off + 32) =
                            __floats2half2_rn(x2a * c0 + x1a * sn0, x2b * c1 + x1b * sn1);
                    }
                }
            }
        } else {
            const int vh = hh - NKVH;
            #pragma unroll
            for (int mt = 0; mt < 2; mt++) {
                #pragma unroll
                for (int r = 0; r < 2; r++) {
                    const int row = bm + wm + mt * 16 + cr + r * 8;
                    #pragma unroll
                    for (int nt = 0; nt < 8; nt++) {
                        size_t off = (size_t)row * KVD + vh * HDIM + nt * 8 + cc;
                        *reinterpret_cast<__half2*>(H2 + off) =
                            __floats2half2_rn(acc[mt][nt][2*r], acc[mt][nt][2*r + 1]);
                    }
                }
            }
        }
    }
}

// ---------------- HMMA causal GQA flash attention ----------------------------
// Q hi+lo frags persistent; cp.async double-buffered K/V tiles.
// Epilogue writes plain fp16 ctx (hi only) into g_chat.
#define AT_STRB 144
#define KVBUF   (2 * 64 * AT_STRB)   // one buffer: K tile + V tile = 18432 B

__global__ __launch_bounds__(256, 1)
void attn_hmma(const __half* __restrict__ qhi, const __half* __restrict__ qlo,
               const __half* __restrict__ khi, const __half* __restrict__ vhi,
               __half* __restrict__ chat)
{
    __shared__ __align__(16) char sm[2 * KVBUF];   // 36864 B (Q phase reuses)

    const int qb  = gridDim.x - 1 - blockIdx.x;
    const int h   = blockIdx.y;
    const int b   = blockIdx.z;
    const int kvh = h / GSIZE;
    const int tid = threadIdx.x;
    const int wid = tid >> 5;
    const int lane = tid & 31;
    const int qrow0 = qb * 128;
    const int wm = wid * 16;

    const uint32_t sbase = smem_u32(sm);
    const int VOFF = 64 * AT_STRB;

    // ---- Q phase (synchronous, whole 36KB as 2x128-row buffers)
    {
        const __half* srcs[2] = {qhi, qlo};
        #pragma unroll
        for (int arr = 0; arr < 2; arr++) {
            const __half* s = srcs[arr];
            #pragma unroll
            for (int i = 0; i < 4; i++) {
                int u = tid + 256 * i;
                int row = u >> 3, seg = u & 7;
                uint4 v = *(const uint4*)(s + ((size_t)(b * S_LEN + qrow0 + row)) * D_MODEL
                                            + h * HDIM + seg * 8);
                *(uint4*)(sm + arr * (128 * AT_STRB) + row * AT_STRB + seg * 16) = v;
            }
        }
    }
    __syncthreads();

    uint32_t qh[4][4], ql[4][4];
    {
        uint32_t arow = (uint32_t)(wm + (lane & 15));
        uint32_t koff = ((lane >> 4) & 1) * 8;
        #pragma unroll
        for (int kc = 0; kc < 4; kc++) {
            uint32_t a0 = sbase + arow * AT_STRB + (kc * 16 + koff) * 2;
            ldsm4(qh[kc][0], qh[kc][1], qh[kc][2], qh[kc][3], a0);
            ldsm4(ql[kc][0], ql[kc][1], ql[kc][2], ql[kc][3], a0 + 128 * AT_STRB);
        }
    }
    __syncthreads();   // all warps done reading Q smem before KV prefetch overwrites

    float m0 = -1e30f, m1 = -1e30f, l0 = 0.f, l1 = 0.f;
    float ctxa[8][4];
    #pragma unroll
    for (int t = 0; t < 8; t++)
        #pragma unroll
        for (int j = 0; j < 4; j++) ctxa[t][j] = 0.f;

    const int nkt = 2 * qb + 2;

    auto fillkv = [&](int kt, int buf) {
        const int k0 = kt * 64;
        const uint32_t base = sbase + buf * KVBUF;
        const __half* srcs[2] = {khi, vhi};
        #pragma unroll
        for (int arr = 0; arr < 2; arr++) {
            const __half* s = srcs[arr];
            #pragma unroll
            for (int i = 0; i < 2; i++) {
                int u = tid + 256 * i;
                int row = u >> 3, seg = u & 7;
                cp16(base + arr * VOFF + row * AT_STRB + seg * 16,
                     s + ((size_t)(b * S_LEN + k0 + row)) * KVD + kvh * HDIM + seg * 8);
            }
        }
    };

    fillkv(0, 0);
    CP_COMMIT();

    for (int kt = 0; kt < nkt; kt++) {
        const int k0 = kt * 64;
        const int buf = kt & 1;
        __syncthreads();   // all warps done reading buf^1 (tile kt-1)
        if (kt + 1 < nkt) {
            fillkv(kt + 1, buf ^ 1);
            CP_COMMIT();
            CP_WAIT(1);    // tile kt landed
        } else {
            CP_WAIT(0);
        }
        __syncthreads();

        const uint32_t kvbase = sbase + buf * KVBUF;

        if (k0 <= qrow0 + wm + 15) {
            float sc[8][4];
            #pragma unroll
            for (int t = 0; t < 8; t++)
                #pragma unroll
                for (int j = 0; j < 4; j++) sc[t][j] = 0.f;

            #pragma unroll
            for (int g = 0; g < 4; g++) {
                uint32_t kh[4][4];
                #pragma unroll
                for (int kc = 0; kc < 4; kc++) {
                    uint32_t addr = kvbase
                        + (g * 16 + (lane & 7) + ((lane >> 4) & 1) * 8) * AT_STRB
                        + (kc * 16 + ((lane >> 3) & 1) * 8) * 2;
                    ldsm4(kh[kc][0], kh[kc][1], kh[kc][2], kh[kc][3], addr);
                }
                #pragma unroll
                for (int kc = 0; kc < 4; kc++) {
                    uint32_t bh0[2] = {kh[kc][0], kh[kc][1]};
                    uint32_t bh1[2] = {kh[kc][2], kh[kc][3]};
                    mma16816(sc[2*g],   qh[kc], bh0);
                    mma16816(sc[2*g],   ql[kc], bh0);
                    mma16816(sc[2*g+1], qh[kc], bh1);
                    mma16816(sc[2*g+1], ql[kc], bh1);
                }
            }

            const int rtop = qrow0 + wm + (lane >> 2);
            const int rbot = rtop + 8;
            if (kt >= nkt - 2) {
                #pragma unroll
                for (int t = 0; t < 8; t++) {
                    int kg = k0 + t * 8 + (lane & 3) * 2;
                    if (kg     > rtop) sc[t][0] = -1e30f;
                    if (kg + 1 > rtop) sc[t][1] = -1e30f;
                    if (kg     > rbot) sc[t][2] = -1e30f;
                    if (kg + 1 > rbot) sc[t][3] = -1e30f;
                }
            }

            float tm0 = -1e30f, tm1 = -1e30f;
            #pragma unroll
            for (int t = 0; t < 8; t++) {
                tm0 = fmaxf(tm0, fmaxf(sc[t][0], sc[t][1]));
                tm1 = fmaxf(tm1, fmaxf(sc[t][2], sc[t][3]));
            }
            tm0 = fmaxf(tm0, __shfl_xor_sync(0xFFFFFFFFu, tm0, 1));
            tm0 = fmaxf(tm0, __shfl_xor_sync(0xFFFFFFFFu, tm0, 2));
            tm1 = fmaxf(tm1, __shfl_xor_sync(0xFFFFFFFFu, tm1, 1));
            tm1 = fmaxf(tm1, __shfl_xor_sync(0xFFFFFFFFu, tm1, 2));
            float mn0 = fmaxf(m0, tm0), mn1 = fmaxf(m1, tm1);
            float c0 = __expf(m0 - mn0), c1 = __expf(m1 - mn1);
            m0 = mn0; m1 = mn1;
            l0 *= c0;  l1 *= c1;
            #pragma unroll
            for (int t = 0; t < 8; t++) {
                ctxa[t][0] *= c0; ctxa[t][1] *= c0;
                ctxa[t][2] *= c1; ctxa[t][3] *= c1;
            }

            float ps0 = 0.f, ps1 = 0.f;
            uint32_t ph[4][4], pl[4][4];
            #pragma unroll
            for (int t = 0; t < 8; t++) {
                float p0 = __expf(sc[t][0] - mn0);
                float p1 = __expf(sc[t][1] - mn0);
                float p2 = __expf(sc[t][2] - mn1);
                float p3 = __expf(sc[t][3] - mn1);
                ps0 += p0 + p1; ps1 += p2 + p3;
                uint32_t hp01 = pack2h(p0, p1);
                uint32_t hp23 = pack2h(p2, p3);
                __half2 h01 = *reinterpret_cast<__half2*>(&hp01);
                __half2 h23 = *reinterpret_cast<__half2*>(&hp23);
                uint32_t lp01 = pack2h(p0 - __low2float(h01), p1 - __high2float(h01));
                uint32_t lp23 = pack2h(p2 - __low2float(h23), p3 - __high2float(h23));
                int kc = t >> 1, hf = (t & 1) * 2;
                ph[kc][hf]     = hp01;  ph[kc][hf + 1] = hp23;
                pl[kc][hf]     = lp01;  pl[kc][hf + 1] = lp23;
            }
            ps0 += __shfl_xor_sync(0xFFFFFFFFu, ps0, 1);
            ps0 += __shfl_xor_sync(0xFFFFFFFFu, ps0, 2);
            ps1 += __shfl_xor_sync(0xFFFFFFFFu, ps1, 1);
            ps1 += __shfl_xor_sync(0xFFFFFFFFu, ps1, 2);
            l0 += ps0; l1 += ps1;

            #pragma unroll
            for (int kc = 0; kc < 4; kc++) {
                #pragma unroll
                for (int g = 0; g < 4; g++) {
                    uint32_t vh[4];
                    uint32_t addr = kvbase + VOFF
                        + (kc * 16 + (lane & 7) + ((lane >> 3) & 1) * 8) * AT_STRB
                        + (g * 16 + ((lane >> 4) & 1) * 8) * 2;
                    ldsm4t(vh[0], vh[1], vh[2], vh[3], addr);
                    uint32_t bh0[2] = {vh[0], vh[1]};
                    uint32_t bh1[2] = {vh[2], vh[3]};
                    mma16816(ctxa[2*g],   ph[kc], bh0);
                    mma16816(ctxa[2*g],   pl[kc], bh0);
                    mma16816(ctxa[2*g+1], ph[kc], bh1);
                    mma16816(ctxa[2*g+1], pl[kc], bh1);
                }
            }
        }
    }

    // epilogue: plain fp16 ctx
    float il0 = 1.f / l0, il1 = 1.f / l1;
    const int rtop = qrow0 + wm + (lane >> 2);
    const size_t row0 = (size_t)(b * S_LEN) + rtop;
    __half* c0p = chat + row0 * KDIM + h * HDIM;
    __half* c1p = c0p + 8 * (size_t)KDIM;
    #pragma unroll
    for (int t = 0; t < 8; t++) {
        int col = t * 8 + (lane & 3) * 2;
        *reinterpret_cast<__half2*>(c0p + col) =
            __floats2half2_rn(ctxa[t][0] * il0, ctxa[t][1] * il0);
        *reinterpret_cast<__half2*>(c1p + col) =
            __floats2half2_rn(ctxa[t][2] * il1, ctxa[t][3] * il1);
    }
}

// ---------------- host launch -------------------------------------------------
extern "C" void kernel_launch(void* const* d_in, const int* in_sizes, int n_in,
                              void* d_out, int out_size)
{
    const float* x  = (const float*)d_in[0];
    const float* Wq = (const float*)d_in[1];
    const float* Wk = (const float*)d_in[2];
    const float* Wv = (const float*)d_in[3];
    const float* Wo = (const float*)d_in[4];
    float* out = (float*)d_out;

    __half *ahat, *chat, *wq, *wkv, *wo, *qhi, *qlo, *khi, *vhi;
    cudaGetSymbolAddress((void**)&ahat, g_ahat);
    cudaGetSymbolAddress((void**)&chat, g_chat);
    cudaGetSymbolAddress((void**)&wq,   g_wq);
    cudaGetSymbolAddress((void**)&wkv,  g_wkv);
    cudaGetSymbolAddress((void**)&wo,   g_wo);
    cudaGetSymbolAddress((void**)&qhi,  g_qhi);
    cudaGetSymbolAddress((void**)&qlo,  g_qlo);
    cudaGetSymbolAddress((void**)&khi,  g_khi);
    cudaGetSymbolAddress((void**)&vhi,  g_vhi);

    static int smem_set = 0;
    if (!smem_set) {
        cudaFuncSetAttribute((const void*)gemm_hmma<0, KDIM>,
                             cudaFuncAttributeMaxDynamicSharedMemorySize, GSMEM);
        cudaFuncSetAttribute((const void*)gemm_hmma<1, KEFF2>,
                             cudaFuncAttributeMaxDynamicSharedMemorySize, GSMEM);
        cudaFuncSetAttribute((const void*)gemm_hmma<2, KEFF2>,
                             cudaFuncAttributeMaxDynamicSharedMemorySize, GSMEM);
        smem_set = 1;
    }

    // conversions
    {
        int total = MROWS * KDIM;
        conv_split<<<(total + 255) / 256, 256>>>(x, ahat, total);
        dim3 blk(32, 32);
        conv_wt<<<dim3(D_MODEL / 32, KDIM / 32), blk>>>(Wq, wq, D_MODEL);
        conv_wt<<<dim3(KVD / 32,     KDIM / 32), blk>>>(Wk, wkv, KVD);
        conv_wt<<<dim3(KVD / 32,     KDIM / 32), blk>>>(Wv, wkv + (size_t)KVD * KDIM, KVD);
        conv_wt<<<dim3(D_MODEL / 32, KDIM / 32), blk>>>(Wo, wo, D_MODEL);
        rope_table<<<(S_LEN * 32 + 255) / 256, 256>>>();
    }

    // projections with fused epilogues
    gemm_hmma<1, KEFF2><<<dim3(D_MODEL / BN, MROWS / BM), 256, GSMEM>>>(
        ahat, wq, nullptr, qhi, qlo, D_MODEL);
    gemm_hmma<2, KEFF2><<<dim3(NKV2 / BN, MROWS / BM), 256, GSMEM>>>(
        ahat, wkv, nullptr, khi, vhi, NKV2);

    // attention (writes fp16 ctx directly)
    attn_hmma<<<dim3(S_LEN / 128, NHEADS, BATCH), 256>>>(qhi, qlo, khi, vhi, chat);

    // output projection (K = 2048, ctx hi only)
    gemm_hmma<0, KDIM><<<dim3(D_MODEL / BN, MROWS / BM), 256, GSMEM>>>(
        chat, wo, out, nullptr, nullptr, D_MODEL);
}

// round 10
// speedup vs baseline: 1.6628x; 1.0577x over previous
#include <cuda_runtime.h>
#include <cuda_fp16.h>
#include <math.h>
#include <cstdint>

#define BATCH   2
#define S_LEN   2048
#define D_MODEL 2048
#define NHEADS  32
#define NKVH    8
#define HDIM    64
#define GSIZE   (NHEADS / NKVH)
#define KVD     (NKVH * HDIM)        // 512
#define MROWS   (BATCH * S_LEN)      // 4096
#define KDIM    2048
#define KEFF2   (2 * KDIM)           // 4096 stacked K (hi|lo)
#define NKV2    (2 * KVD)            // 1024 fused K|V width

// ---------------- scratch (device globals) ----------------------------------
__device__ __half g_ahat[(size_t)MROWS  * KEFF2];   // x hi|lo stacked
__device__ __half g_chat[(size_t)MROWS  * KDIM];    // ctx hi only
__device__ __half g_wq [(size_t)D_MODEL * KDIM];
__device__ __half g_wkv[(size_t)NKV2    * KDIM];    // [Wk^T ; Wv^T]
__device__ __half g_wo [(size_t)D_MODEL * KDIM];
__device__ float g_cos[S_LEN * 32];
__device__ float g_sin[S_LEN * 32];
__device__ __half g_qhi[MROWS * D_MODEL];
__device__ __half g_qlo[MROWS * D_MODEL];
__device__ __half g_khi[MROWS * KVD];
__device__ __half g_vhi[MROWS * KVD];

// ---------------- helpers ------------------------------------------------
__device__ __forceinline__ uint32_t smem_u32(const void* p) {
    uint32_t a;
    asm("{ .reg .u64 t; cvta.to.shared.u64 t, %1; cvt.u32.u64 %0, t; }"
        : "=r"(a) : "l"(p));
    return a;
}

__device__ __forceinline__ void cp16(uint32_t saddr, const void* gaddr) {
    asm volatile("cp.async.cg.shared.global [%0], [%1], 16;"
                 :: "r"(saddr), "l"(gaddr) : "memory");
}
#define CP_COMMIT() asm volatile("cp.async.commit_group;" ::: "memory")
#define CP_WAIT(n)  asm volatile("cp.async.wait_group %0;" :: "n"(n) : "memory")

__device__ __forceinline__ void ldsm4(uint32_t& r0, uint32_t& r1, uint32_t& r2,
                                      uint32_t& r3, uint32_t addr) {
    asm volatile("ldmatrix.sync.aligned.m8n8.x4.shared.b16 {%0,%1,%2,%3}, [%4];"
                 : "=r"(r0), "=r"(r1), "=r"(r2), "=r"(r3) : "r"(addr));
}
__device__ __forceinline__ void ldsm4t(uint32_t& r0, uint32_t& r1, uint32_t& r2,
                                       uint32_t& r3, uint32_t addr) {
    asm volatile("ldmatrix.sync.aligned.m8n8.x4.trans.shared.b16 {%0,%1,%2,%3}, [%4];"
                 : "=r"(r0), "=r"(r1), "=r"(r2), "=r"(r3) : "r"(addr));
}

__device__ __forceinline__ void mma16816(float* d, const uint32_t* a, const uint32_t* b) {
    asm volatile(
        "mma.sync.aligned.m16n8k16.row.col.f32.f16.f16.f32 "
        "{%0,%1,%2,%3}, {%4,%5,%6,%7}, {%8,%9}, {%0,%1,%2,%3};"
        : "+f"(d[0]), "+f"(d[1]), "+f"(d[2]), "+f"(d[3])
        : "r"(a[0]), "r"(a[1]), "r"(a[2]), "r"(a[3]), "r"(b[0]), "r"(b[1]));
}

__device__ __forceinline__ uint32_t pack2h(float lo_e, float hi_e) {
    __half2 h = __floats2half2_rn(lo_e, hi_e);
    return *reinterpret_cast<uint32_t*>(&h);
}

__device__ __forceinline__ void store_split2(__half* hi, __half* lo, size_t off,
                                             float ya, float yb) {
    __half2 h = __floats2half2_rn(ya, yb);
    *reinterpret_cast<__half2*>(hi + off) = h;
    __half2 l = __floats2half2_rn(ya - __low2float(h), yb - __high2float(h));
    *reinterpret_cast<__half2*>(lo + off) = l;
}

// ---------------- conversion kernels -----------------------------------------
__global__ void conv_split(const float* __restrict__ in, __half* __restrict__ out,
                           int total)
{
    int i = blockIdx.x * blockDim.x + threadIdx.x;
    if (i >= total) return;
    int row = i / KDIM, col = i - row * KDIM;
    float v = in[i];
    __half hi = __float2half_rn(v);
    __half lo = __float2half_rn(v - __half2float(hi));
    size_t base = (size_t)row * KEFF2 + col;
    out[base]        = hi;
    out[base + KDIM] = lo;
}

__global__ void conv_wt(const float* __restrict__ W, __half* __restrict__ out, int N)
{
    __shared__ float tile[32][33];
    int k0 = blockIdx.y * 32, n0 = blockIdx.x * 32;
    int tx = threadIdx.x, ty = threadIdx.y;
    tile[ty][tx] = W[(size_t)(k0 + ty) * N + n0 + tx];
    __syncthreads();
    out[(size_t)(n0 + ty) * KDIM + k0 + tx] = __float2half_rn(tile[tx][ty]);
}

__global__ void rope_table()
{
    int i = blockIdx.x * blockDim.x + threadIdx.x;
    if (i >= S_LEN * 32) return;
    int s = i >> 5, j = i & 31;
    float inv = (float)exp(-(double)j * (log(10000.0) / 32.0));
    float ang = (float)s * inv;
    float c, sn;
    sincosf(ang, &sn, &c);
    g_cos[i] = c;
    g_sin[i] = sn;
}

// ---------------- GEMM core (shared by both kernels) --------------------------
// 128x128 CTA, 8 warps (4M x 2N), warp tile 32x64, KC=64, 3 stages.
#define BM 128
#define BN 128
#define KC 64
#define STAGES 3
#define RSB    144                   // bytes per smem row (128 data + 16 pad)
#define STG_A  (128 * RSB)           // 18432
#define STG_SZ (2 * STG_A)           // 36864
#define GSMEM  (STAGES * STG_SZ)     // 110592

// Runs the full K loop and leaves results in acc. Ab/Bb are the CTA-base
// pointers; KAS = A row stride (= K extent); B wraps at KDIM.
template<int KAS>
__device__ __forceinline__ void gemm_core(
    const __half* __restrict__ Ab, const __half* __restrict__ Bb,
    uint32_t sbase, int tid, int lane, int wm, int wn, float acc[2][8][4])
{
    constexpr int NCHUNK = KAS / KC;

    const int a_row  = wm + (lane & 15);
    const int a_koff = ((lane >> 4) & 1) * 8;
    const int b_row_base = wn + (lane & 7) + ((lane >> 4) & 1) * 8;
    const int b_koff = ((lane >> 3) & 1) * 8;

    auto fill = [&](int c, int slot) {
        const int kposA = c * KC;
        const int kposB = kposA & (KDIM - 1);
        const uint32_t abase = sbase + slot * STG_SZ;
        const uint32_t bbase = abase + STG_A;
        #pragma unroll
        for (int i = 0; i < 4; i++) {
            int u = tid + 256 * i;
            int row = u >> 3, seg = u & 7;
            cp16(abase + row * RSB + seg * 16, Ab + (size_t)row * KAS  + kposA + seg * 8);
            cp16(bbase + row * RSB + seg * 16, Bb + (size_t)row * KDIM + kposB + seg * 8);
        }
    };

    #pragma unroll
    for (int s = 0; s < STAGES - 1; s++) {
        fill(s, s);
        CP_COMMIT();
    }

    for (int c = 0; c < NCHUNK; c++) {
        CP_WAIT(STAGES - 2);
        __syncthreads();

        if (c + STAGES - 1 < NCHUNK)
            fill(c + STAGES - 1, (c + STAGES - 1) % STAGES);
        CP_COMMIT();

        const int slot = c % STAGES;
        const uint32_t abase = sbase + slot * STG_SZ;
        const uint32_t bbase = abase + STG_A;
        #pragma unroll
        for (int ks = 0; ks < 4; ks++) {
            const int kp = ks * 16;
            uint32_t af[2][4];
            #pragma unroll
            for (int mt = 0; mt < 2; mt++) {
                uint32_t addr = abase + (a_row + mt * 16) * RSB + (kp + a_koff) * 2;
                ldsm4(af[mt][0], af[mt][1], af[mt][2], af[mt][3], addr);
            }
            uint32_t bf[8][2];
            #pragma unroll
            for (int bt = 0; bt < 4; bt++) {
                uint32_t addr = bbase + (b_row_base + bt * 16) * RSB + (kp + b_koff) * 2;
                ldsm4(bf[2*bt][0], bf[2*bt][1], bf[2*bt+1][0], bf[2*bt+1][1], addr);
            }
            #pragma unroll
            for (int mt = 0; mt < 2; mt++)
                #pragma unroll
                for (int nt = 0; nt < 8; nt++)
                    mma16816(acc[mt][nt], af[mt], bf[nt]);
        }
    }
}

// ---------------- fused QKV projection kernel --------------------------------
// grid.x: tiles 0..15 -> Q (Wq, RoPE+scale+split epilogue)
//         tiles 16..23 -> KV (Wkv; K heads RoPE, V heads convert)
__global__ __launch_bounds__(256)
void qkv_gemm(const __half* __restrict__ A,
              const __half* __restrict__ Wq, const __half* __restrict__ Wkv,
              __half* __restrict__ qhi, __half* __restrict__ qlo,
              __half* __restrict__ khi, __half* __restrict__ vhi)
{
    extern __shared__ char gsm[];
    const uint32_t sbase = smem_u32(gsm);

    const int tid  = threadIdx.x;
    const int wid  = tid >> 5;
    const int lane = tid & 31;
    const int bm   = blockIdx.y * BM;
    const bool isQ = blockIdx.x < (D_MODEL / BN);
    const int bn   = (isQ ? blockIdx.x : blockIdx.x - D_MODEL / BN) * BN;
    const int wm   = (wid & 3) * 32;
    const int wn   = (wid >> 2) * 64;

    float acc[2][8][4];
    #pragma unroll
    for (int i = 0; i < 2; i++)
        #pragma unroll
        for (int j = 0; j < 8; j++)
            #pragma unroll
            for (int t = 0; t < 4; t++) acc[i][j][t] = 0.f;

    const __half* Ab = A + (size_t)bm * KEFF2;
    const __half* Bb = (isQ ? Wq : Wkv) + (size_t)bn * KDIM;

    gemm_core<KEFF2>(Ab, Bb, sbase, tid, lane, wm, wn, acc);

    const int cr = lane >> 2;
    const int cc = (lane & 3) * 2;

    if (isQ) {
        const int head = (bn + wn) >> 6;
        #pragma unroll
        for (int mt = 0; mt < 2; mt++) {
            #pragma unroll
            for (int r = 0; r < 2; r++) {
                const int row = bm + wm + mt * 16 + cr + r * 8;
                const int s = row & (S_LEN - 1);
                #pragma unroll
                for (int nt = 0; nt < 4; nt++) {
                    const int j = nt * 8 + cc;
                    float c0 = g_cos[(s << 5) + j],     sn0 = g_sin[(s << 5) + j];
                    float c1 = g_cos[(s << 5) + j + 1], sn1 = g_sin[(s << 5) + j + 1];
                    float x1a = acc[mt][nt][2*r],     x1b = acc[mt][nt][2*r + 1];
                    float x2a = acc[mt][nt+4][2*r],   x2b = acc[mt][nt+4][2*r + 1];
                    float y1a = (x1a * c0 - x2a * sn0) * 0.125f;
                    float y1b = (x1b * c1 - x2b * sn1) * 0.125f;
                    float y2a = (x2a * c0 + x1a * sn0) * 0.125f;
                    float y2b = (x2b * c1 + x1b * sn1) * 0.125f;
                    size_t off = (size_t)row * D_MODEL + head * HDIM + j;
                    store_split2(qhi, qlo, off,      y1a, y1b);
                    store_split2(qhi, qlo, off + 32, y2a, y2b);
                }
            }
        }
    } else {
        const int hh = (bn + wn) >> 6;
        if (hh < NKVH) {
            #pragma unroll
            for (int mt = 0; mt < 2; mt++) {
                #pragma unroll
                for (int r = 0; r < 2; r++) {
                    const int row = bm + wm + mt * 16 + cr + r * 8;
                    const int s = row & (S_LEN - 1);
                    #pragma unroll
                    for (int nt = 0; nt < 4; nt++) {
                        const int j = nt * 8 + cc;
                        float c0 = g_cos[(s << 5) + j],     sn0 = g_sin[(s << 5) + j];
                        float c1 = g_cos[(s << 5) + j + 1], sn1 = g_sin[(s << 5) + j + 1];
                        float x1a = acc[mt][nt][2*r],   x1b = acc[mt][nt][2*r + 1];
                        float x2a = acc[mt][nt+4][2*r], x2b = acc[mt][nt+4][2*r + 1];
                        size_t off = (size_t)row * KVD + hh * HDIM + j;
                        *reinterpret_cast<__half2*>(khi + off) =
                            __floats2half2_rn(x1a * c0 - x2a * sn0, x1b * c1 - x2b * sn1);
                        *reinterpret_cast<__half2*>(khi + off + 32) =
                            __floats2half2_rn(x2a * c0 + x1a * sn0, x2b * c1 + x1b * sn1);
                    }
                }
            }
        } else {
            const int vh = hh - NKVH;
            #pragma unroll
            for (int mt = 0; mt < 2; mt++) {
                #pragma unroll
                for (int r = 0; r < 2; r++) {
                    const int row = bm + wm + mt * 16 + cr + r * 8;
                    #pragma unroll
                    for (int nt = 0; nt < 8; nt++) {
                        size_t off = (size_t)row * KVD + vh * HDIM + nt * 8 + cc;
                        *reinterpret_cast<__half2*>(vhi + off) =
                            __floats2half2_rn(acc[mt][nt][2*r], acc[mt][nt][2*r + 1]);
                    }
                }
            }
        }
    }
}

// ---------------- output projection kernel -----------------------------------
__global__ __launch_bounds__(256)
void out_gemm(const __half* __restrict__ A, const __half* __restrict__ B,
              float* __restrict__ C)
{
    extern __shared__ char gsm[];
    const uint32_t sbase = smem_u32(gsm);

    const int tid  = threadIdx.x;
    const int wid  = tid >> 5;
    const int lane = tid & 31;
    const int bm   = blockIdx.y * BM;
    const int bn   = blockIdx.x * BN;
    const int wm   = (wid & 3) * 32;
    const int wn   = (wid >> 2) * 64;

    float acc[2][8][4];
    #pragma unroll
    for (int i = 0; i < 2; i++)
        #pragma unroll
        for (int j = 0; j < 8; j++)
            #pragma unroll
            for (int t = 0; t < 4; t++) acc[i][j][t] = 0.f;

    gemm_core<KDIM>(A + (size_t)bm * KDIM, B + (size_t)bn * KDIM,
                    sbase, tid, lane, wm, wn, acc);

    const int cr = lane >> 2;
    const int cc = (lane & 3) * 2;
    #pragma unroll
    for (int mt = 0; mt < 2; mt++) {
        #pragma unroll
        for (int nt = 0; nt < 8; nt++) {
            float* p0 = C + (size_t)(bm + wm + mt * 16 + cr) * D_MODEL + bn + wn + nt * 8 + cc;
            float* p1 = p0 + 8 * (size_t)D_MODEL;
            p0[0] = acc[mt][nt][0]; p0[1] = acc[mt][nt][1];
            p1[0] = acc[mt][nt][2]; p1[1] = acc[mt][nt][3];
        }
    }
}

// ---------------- HMMA causal GQA flash attention (unchanged from R9) --------
#define AT_STRB 144
#define KVBUF   (2 * 64 * AT_STRB)

__global__ __launch_bounds__(256, 1)
void attn_hmma(const __half* __restrict__ qhi, const __half* __restrict__ qlo,
               const __half* __restrict__ khi, const __half* __restrict__ vhi,
               __half* __restrict__ chat)
{
    __shared__ __align__(16) char sm[2 * KVBUF];

    const int qb  = gridDim.x - 1 - blockIdx.x;
    const int h   = blockIdx.y;
    const int b   = blockIdx.z;
    const int kvh = h / GSIZE;
    const int tid = threadIdx.x;
    const int wid = tid >> 5;
    const int lane = tid & 31;
    const int qrow0 = qb * 128;
    const int wm = wid * 16;

    const uint32_t sbase = smem_u32(sm);
    const int VOFF = 64 * AT_STRB;

    {
        const __half* srcs[2] = {qhi, qlo};
        #pragma unroll
        for (int arr = 0; arr < 2; arr++) {
            const __half* s = srcs[arr];
            #pragma unroll
            for (int i = 0; i < 4; i++) {
                int u = tid + 256 * i;
                int row = u >> 3, seg = u & 7;
                uint4 v = *(const uint4*)(s + ((size_t)(b * S_LEN + qrow0 + row)) * D_MODEL
                                            + h * HDIM + seg * 8);
                *(uint4*)(sm + arr * (128 * AT_STRB) + row * AT_STRB + seg * 16) = v;
            }
        }
    }
    __syncthreads();

    uint32_t qh[4][4], ql[4][4];
    {
        uint32_t arow = (uint32_t)(wm + (lane & 15));
        uint32_t koff = ((lane >> 4) & 1) * 8;
        #pragma unroll
        for (int kc = 0; kc < 4; kc++) {
            uint32_t a0 = sbase + arow * AT_STRB + (kc * 16 + koff) * 2;
            ldsm4(qh[kc][0], qh[kc][1], qh[kc][2], qh[kc][3], a0);
            ldsm4(ql[kc][0], ql[kc][1], ql[kc][2], ql[kc][3], a0 + 128 * AT_STRB);
        }
    }
    __syncthreads();

    float m0 = -1e30f, m1 = -1e30f, l0 = 0.f, l1 = 0.f;
    float ctxa[8][4];
    #pragma unroll
    for (int t = 0; t < 8; t++)
        #pragma unroll
        for (int j = 0; j < 4; j++) ctxa[t][j] = 0.f;

    const int nkt = 2 * qb + 2;

    auto fillkv = [&](int kt, int buf) {
        const int k0 = kt * 64;
        const uint32_t base = sbase + buf * KVBUF;
        const __half* srcs[2] = {khi, vhi};
        #pragma unroll
        for (int arr = 0; arr < 2; arr++) {
            const __half* s = srcs[arr];
            #pragma unroll
            for (int i = 0; i < 2; i++) {
                int u = tid + 256 * i;
                int row = u >> 3, seg = u & 7;
                cp16(base + arr * VOFF + row * AT_STRB + seg * 16,
                     s + ((size_t)(b * S_LEN + k0 + row)) * KVD + kvh * HDIM + seg * 8);
            }
        }
    };

    fillkv(0, 0);
    CP_COMMIT();

    for (int kt = 0; kt < nkt; kt++) {
        const int k0 = kt * 64;
        const int buf = kt & 1;
        __syncthreads();
        if (kt + 1 < nkt) {
            fillkv(kt + 1, buf ^ 1);
            CP_COMMIT();
            CP_WAIT(1);
        } else {
            CP_WAIT(0);
        }
        __syncthreads();

        const uint32_t kvbase = sbase + buf * KVBUF;

        if (k0 <= qrow0 + wm + 15) {
            float sc[8][4];
            #pragma unroll
            for (int t = 0; t < 8; t++)
                #pragma unroll
                for (int j = 0; j < 4; j++) sc[t][j] = 0.f;

            #pragma unroll
            for (int g = 0; g < 4; g++) {
                uint32_t kh[4][4];
                #pragma unroll
                for (int kc = 0; kc < 4; kc++) {
                    uint32_t addr = kvbase
                        + (g * 16 + (lane & 7) + ((lane >> 4) & 1) * 8) * AT_STRB
                        + (kc * 16 + ((lane >> 3) & 1) * 8) * 2;
                    ldsm4(kh[kc][0], kh[kc][1], kh[kc][2], kh[kc][3], addr);
                }
                #pragma unroll
                for (int kc = 0; kc < 4; kc++) {
                    uint32_t bh0[2] = {kh[kc][0], kh[kc][1]};
                    uint32_t bh1[2] = {kh[kc][2], kh[kc][3]};
                    mma16816(sc[2*g],   qh[kc], bh0);
                    mma16816(sc[2*g],   ql[kc], bh0);
                    mma16816(sc[2*g+1], qh[kc], bh1);
                    mma16816(sc[2*g+1], ql[kc], bh1);
                }
            }

            const int rtop = qrow0 + wm + (lane >> 2);
            const int rbot = rtop + 8;
            if (kt >= nkt - 2) {
                #pragma unroll
                for (int t = 0; t < 8; t++) {
                    int kg = k0 + t * 8 + (lane & 3) * 2;
                    if (kg     > rtop) sc[t][0] = -1e30f;
                    if (kg + 1 > rtop) sc[t][1] = -1e30f;
                    if (kg     > rbot) sc[t][2] = -1e30f;
                    if (kg + 1 > rbot) sc[t][3] = -1e30f;
                }
            }

            float tm0 = -1e30f, tm1 = -1e30f;
            #pragma unroll
            for (int t = 0; t < 8; t++) {
                tm0 = fmaxf(tm0, fmaxf(sc[t][0], sc[t][1]));
                tm1 = fmaxf(tm1, fmaxf(sc[t][2], sc[t][3]));
            }
            tm0 = fmaxf(tm0, __shfl_xor_sync(0xFFFFFFFFu, tm0, 1));
            tm0 = fmaxf(tm0, __shfl_xor_sync(0xFFFFFFFFu, tm0, 2));
            tm1 = fmaxf(tm1, __shfl_xor_sync(0xFFFFFFFFu, tm1, 1));
            tm1 = fmaxf(tm1, __shfl_xor_sync(0xFFFFFFFFu, tm1, 2));
            float mn0 = fmaxf(m0, tm0), mn1 = fmaxf(m1, tm1);
            float c0 = __expf(m0 - mn0), c1 = __expf(m1 - mn1);
            m0 = mn0; m1 = mn1;
            l0 *= c0;  l1 *= c1;
            #pragma unroll
            for (int t = 0; t < 8; t++) {
                ctxa[t][0] *= c0; ctxa[t][1] *= c0;
                ctxa[t][2] *= c1; ctxa[t][3] *= c1;
            }

            float ps0 = 0.f, ps1 = 0.f;
            uint32_t ph[4][4], pl[4][4];
            #pragma unroll
            for (int t = 0; t < 8; t++) {
                float p0 = __expf(sc[t][0] - mn0);
                float p1 = __expf(sc[t][1] - mn0);
                float p2 = __expf(sc[t][2] - mn1);
                float p3 = __expf(sc[t][3] - mn1);
                ps0 += p0 + p1; ps1 += p2 + p3;
                uint32_t hp01 = pack2h(p0, p1);
                uint32_t hp23 = pack2h(p2, p3);
                __half2 h01 = *reinterpret_cast<__half2*>(&hp01);
                __half2 h23 = *reinterpret_cast<__half2*>(&hp23);
                uint32_t lp01 = pack2h(p0 - __low2float(h01), p1 - __high2float(h01));
                uint32_t lp23 = pack2h(p2 - __low2float(h23), p3 - __high2float(h23));
                int kc = t >> 1, hf = (t & 1) * 2;
                ph[kc][hf]     = hp01;  ph[kc][hf + 1] = hp23;
                pl[kc][hf]     = lp01;  pl[kc][hf + 1] = lp23;
            }
            ps0 += __shfl_xor_sync(0xFFFFFFFFu, ps0, 1);
            ps0 += __shfl_xor_sync(0xFFFFFFFFu, ps0, 2);
            ps1 += __shfl_xor_sync(0xFFFFFFFFu, ps1, 1);
            ps1 += __shfl_xor_sync(0xFFFFFFFFu, ps1, 2);
            l0 += ps0; l1 += ps1;

            #pragma unroll
            for (int kc = 0; kc < 4; kc++) {
                #pragma unroll
                for (int g = 0; g < 4; g++) {
                    uint32_t vh[4];
                    uint32_t addr = kvbase + VOFF
                        + (kc * 16 + (lane & 7) + ((lane >> 3) & 1) * 8) * AT_STRB
                        + (g * 16 + ((lane >> 4) & 1) * 8) * 2;
                    ldsm4t(vh[0], vh[1], vh[2], vh[3], addr);
                    uint32_t bh0[2] = {vh[0], vh[1]};
                    uint32_t bh1[2] = {vh[2], vh[3]};
                    mma16816(ctxa[2*g],   ph[kc], bh0);
                    mma16816(ctxa[2*g],   pl[kc], bh0);
                    mma16816(ctxa[2*g+1], ph[kc], bh1);
                    mma16816(ctxa[2*g+1], pl[kc], bh1);
                }
            }
        }
    }

    float il0 = 1.f / l0, il1 = 1.f / l1;
    const int rtop = qrow0 + wm + (lane >> 2);
    const size_t row0 = (size_t)(b * S_LEN) + rtop;
    __half* c0p = chat + row0 * KDIM + h * HDIM;
    __half* c1p = c0p + 8 * (size_t)KDIM;
    #pragma unroll
    for (int t = 0; t < 8; t++) {
        int col = t * 8 + (lane & 3) * 2;
        *reinterpret_cast<__half2*>(c0p + col) =
            __floats2half2_rn(ctxa[t][0] * il0, ctxa[t][1] * il0);
        *reinterpret_cast<__half2*>(c1p + col) =
            __floats2half2_rn(ctxa[t][2] * il1, ctxa[t][3] * il1);
    }
}

// ---------------- host launch -------------------------------------------------
extern "C" void kernel_launch(void* const* d_in, const int* in_sizes, int n_in,
                              void* d_out, int out_size)
{
    const float* x  = (const float*)d_in[0];
    const float* Wq = (const float*)d_in[1];
    const float* Wk = (const float*)d_in[2];
    const float* Wv = (const float*)d_in[3];
    const float* Wo = (const float*)d_in[4];
    float* out = (float*)d_out;

    __half *ahat, *chat, *wq, *wkv, *wo, *qhi, *qlo, *khi, *vhi;
    cudaGetSymbolAddress((void**)&ahat, g_ahat);
    cudaGetSymbolAddress((void**)&chat, g_chat);
    cudaGetSymbolAddress((void**)&wq,   g_wq);
    cudaGetSymbolAddress((void**)&wkv,  g_wkv);
    cudaGetSymbolAddress((void**)&wo,   g_wo);
    cudaGetSymbolAddress((void**)&qhi,  g_qhi);
    cudaGetSymbolAddress((void**)&qlo,  g_qlo);
    cudaGetSymbolAddress((void**)&khi,  g_khi);
    cudaGetSymbolAddress((void**)&vhi,  g_vhi);

    static int smem_set = 0;
    if (!smem_set) {
        cudaFuncSetAttribute(qkv_gemm, cudaFuncAttributeMaxDynamicSharedMemorySize, GSMEM);
        cudaFuncSetAttribute(out_gemm, cudaFuncAttributeMaxDynamicSharedMemorySize, GSMEM);
        smem_set = 1;
    }

    // conversions
    {
        int total = MROWS * KDIM;
        conv_split<<<(total + 255) / 256, 256>>>(x, ahat, total);
        dim3 blk(32, 32);
        conv_wt<<<dim3(D_MODEL / 32, KDIM / 32), blk>>>(Wq, wq, D_MODEL);
        conv_wt<<<dim3(KVD / 32,     KDIM / 32), blk>>>(Wk, wkv, KVD);
        conv_wt<<<dim3(KVD / 32,     KDIM / 32), blk>>>(Wv, wkv + (size_t)KVD * KDIM, KVD);
        conv_wt<<<dim3(D_MODEL / 32, KDIM / 32), blk>>>(Wo, wo, D_MODEL);
        rope_table<<<(S_LEN * 32 + 255) / 256, 256>>>();
    }

    // fused Q + KV projection (24 n-tiles: 16 Q + 8 KV)
    qkv_gemm<<<dim3((D_MODEL + NKV2) / BN, MROWS / BM), 256, GSMEM>>>(
        ahat, wq, wkv, qhi, qlo, khi, vhi);

    // attention (writes fp16 ctx directly)
    attn_hmma<<<dim3(S_LEN / 128, NHEADS, BATCH), 256>>>(qhi, qlo, khi, vhi, chat);

    // output projection (K = 2048)
    out_gemm<<<dim3(D_MODEL / BN, MROWS / BM), 256, GSMEM>>>(chat, wo, out);
}

// round 11
// speedup vs baseline: 1.8561x; 1.1163x over previous
#include <cuda_runtime.h>
#include <cuda_fp16.h>
#include <math.h>
#include <cstdint>

#define BATCH   2
#define S_LEN   2048
#define D_MODEL 2048
#define NHEADS  32
#define NKVH    8
#define HDIM    64
#define GSIZE   (NHEADS / NKVH)
#define KVD     (NKVH * HDIM)        // 512
#define MROWS   (BATCH * S_LEN)      // 4096
#define KDIM    2048
#define KEFF2   (2 * KDIM)           // 4096 stacked K (hi|lo)
#define NKV2    (2 * KVD)            // 1024 fused K|V width

// ---------------- scratch (device globals) ----------------------------------
__device__ __half g_ahat[(size_t)MROWS  * KEFF2];   // x hi|lo stacked
__device__ __half g_chat[(size_t)MROWS  * KDIM];    // ctx hi only
__device__ __half g_wq [(size_t)D_MODEL * KDIM];
__device__ __half g_wkv[(size_t)NKV2    * KDIM];    // [Wk^T ; Wv^T]
__device__ __half g_wo [(size_t)D_MODEL * KDIM];
__device__ float g_cos[S_LEN * 32];
__device__ float g_sin[S_LEN * 32];
__device__ __half g_qhi[MROWS * D_MODEL];
__device__ __half g_qlo[MROWS * D_MODEL];
__device__ __half g_khi[MROWS * KVD];
__device__ __half g_vhi[MROWS * KVD];

// ---------------- helpers ------------------------------------------------
__device__ __forceinline__ uint32_t smem_u32(const void* p) {
    uint32_t a;
    asm("{ .reg .u64 t; cvta.to.shared.u64 t, %1; cvt.u32.u64 %0, t; }"
        : "=r"(a) : "l"(p));
    return a;
}

__device__ __forceinline__ void cp16(uint32_t saddr, const void* gaddr) {
    asm volatile("cp.async.cg.shared.global [%0], [%1], 16;"
                 :: "r"(saddr), "l"(gaddr) : "memory");
}
#define CP_COMMIT() asm volatile("cp.async.commit_group;" ::: "memory")
#define CP_WAIT(n)  asm volatile("cp.async.wait_group %0;" :: "n"(n) : "memory")

__device__ __forceinline__ void ldsm4(uint32_t& r0, uint32_t& r1, uint32_t& r2,
                                      uint32_t& r3, uint32_t addr) {
    asm volatile("ldmatrix.sync.aligned.m8n8.x4.shared.b16 {%0,%1,%2,%3}, [%4];"
                 : "=r"(r0), "=r"(r1), "=r"(r2), "=r"(r3) : "r"(addr));
}
__device__ __forceinline__ void ldsm4t(uint32_t& r0, uint32_t& r1, uint32_t& r2,
                                       uint32_t& r3, uint32_t addr) {
    asm volatile("ldmatrix.sync.aligned.m8n8.x4.trans.shared.b16 {%0,%1,%2,%3}, [%4];"
                 : "=r"(r0), "=r"(r1), "=r"(r2), "=r"(r3) : "r"(addr));
}

__device__ __forceinline__ void mma16816(float* d, const uint32_t* a, const uint32_t* b) {
    asm volatile(
        "mma.sync.aligned.m16n8k16.row.col.f32.f16.f16.f32 "
        "{%0,%1,%2,%3}, {%4,%5,%6,%7}, {%8,%9}, {%0,%1,%2,%3};"
        : "+f"(d[0]), "+f"(d[1]), "+f"(d[2]), "+f"(d[3])
        : "r"(a[0]), "r"(a[1]), "r"(a[2]), "r"(a[3]), "r"(b[0]), "r"(b[1]));
}

__device__ __forceinline__ uint32_t pack2h(float lo_e, float hi_e) {
    __half2 h = __floats2half2_rn(lo_e, hi_e);
    return *reinterpret_cast<uint32_t*>(&h);
}

__device__ __forceinline__ void store_split2(__half* hi, __half* lo, size_t off,
                                             float ya, float yb) {
    __half2 h = __floats2half2_rn(ya, yb);
    *reinterpret_cast<__half2*>(hi + off) = h;
    __half2 l = __floats2half2_rn(ya - __low2float(h), yb - __high2float(h));
    *reinterpret_cast<__half2*>(lo + off) = l;
}

// ---------------- fused prep kernel -------------------------------------------
// block ranges: [0,32768)       conv_split (x -> ahat hi|lo)
//               [32768,33024)   rope table
//               [33024,43264)   weight transposes (wq 4096 | wk 1024 | wv 1024 | wo 4096)
#define PREP_SPLIT_BLOCKS 32768
#define PREP_ROPE_BLOCKS  256
#define PREP_BLOCKS       (PREP_SPLIT_BLOCKS + PREP_ROPE_BLOCKS + 10240)

__device__ __forceinline__ void wt_body(const float* __restrict__ W,
                                        __half* __restrict__ out, int N,
                                        int bx, int by, float tile[32][33])
{
    int tx = threadIdx.x & 31, tg = threadIdx.x >> 5;
    int k0 = by * 32, n0 = bx * 32;
    #pragma unroll
    for (int i = 0; i < 4; i++) {
        int ty = tg * 4 + i;
        tile[ty][tx] = W[(size_t)(k0 + ty) * N + n0 + tx];
    }
    __syncthreads();
    #pragma unroll
    for (int i = 0; i < 4; i++) {
        int ty = tg * 4 + i;
        out[(size_t)(n0 + ty) * KDIM + k0 + tx] = __float2half_rn(tile[tx][ty]);
    }
}

__global__ __launch_bounds__(256)
void prep(const float* __restrict__ x,
          const float* __restrict__ Wq, const float* __restrict__ Wk,
          const float* __restrict__ Wv, const float* __restrict__ Wo,
          __half* __restrict__ ahat, __half* __restrict__ wq,
          __half* __restrict__ wkv, __half* __restrict__ wo)
{
    __shared__ float tile[32][33];
    const int bid = blockIdx.x;
    const int tid = threadIdx.x;

    if (bid < PREP_SPLIT_BLOCKS) {
        int i = bid * 256 + tid;
        int row = i / KDIM, col = i - row * KDIM;
        float v = x[i];
        __half hi = __float2half_rn(v);
        __half lo = __float2half_rn(v - __half2float(hi));
        size_t base = (size_t)row * KEFF2 + col;
        ahat[base]        = hi;
        ahat[base + KDIM] = lo;
    } else if (bid < PREP_SPLIT_BLOCKS + PREP_ROPE_BLOCKS) {
        int i = (bid - PREP_SPLIT_BLOCKS) * 256 + tid;
        int s = i >> 5, j = i & 31;
        float inv = (float)exp(-(double)j * (log(10000.0) / 32.0));
        float ang = (float)s * inv;
        float c, sn;
        sincosf(ang, &sn, &c);
        g_cos[i] = c;
        g_sin[i] = sn;
    } else {
        int idx = bid - (PREP_SPLIT_BLOCKS + PREP_ROPE_BLOCKS);
        if (idx < 4096) {
            wt_body(Wq, wq, D_MODEL, idx & 63, idx >> 6, tile);
        } else if (idx < 5120) {
            int l = idx - 4096;
            wt_body(Wk, wkv, KVD, l & 15, l >> 4, tile);
        } else if (idx < 6144) {
            int l = idx - 5120;
            wt_body(Wv, wkv + (size_t)KVD * KDIM, KVD, l & 15, l >> 4, tile);
        } else {
            int l = idx - 6144;
            wt_body(Wo, wo, D_MODEL, l & 63, l >> 6, tile);
        }
    }
}

// ---------------- GEMM core ----------------------------------------------------
// 128x128 CTA, 8 warps (4M x 2N), warp tile 32x64, KC=64, 3 stages.
#define BM 128
#define BN 128
#define KC 64
#define STAGES 3
#define RSB    144
#define STG_A  (128 * RSB)
#define STG_SZ (2 * STG_A)
#define GSMEM  (STAGES * STG_SZ)     // 110592

template<int KAS>
__device__ __forceinline__ void gemm_core(
    const __half* __restrict__ Ab, const __half* __restrict__ Bb,
    uint32_t sbase, int tid, int lane, int wm, int wn, float acc[2][8][4])
{
    constexpr int NCHUNK = KAS / KC;

    const int a_row  = wm + (lane & 15);
    const int a_koff = ((lane >> 4) & 1) * 8;
    const int b_row_base = wn + (lane & 7) + ((lane >> 4) & 1) * 8;
    const int b_koff = ((lane >> 3) & 1) * 8;

    auto fill = [&](int c, int slot) {
        const int kposA = c * KC;
        const int kposB = kposA & (KDIM - 1);
        const uint32_t abase = sbase + slot * STG_SZ;
        const uint32_t bbase = abase + STG_A;
        #pragma unroll
        for (int i = 0; i < 4; i++) {
            int u = tid + 256 * i;
            int row = u >> 3, seg = u & 7;
            cp16(abase + row * RSB + seg * 16, Ab + (size_t)row * KAS  + kposA + seg * 8);
            cp16(bbase + row * RSB + seg * 16, Bb + (size_t)row * KDIM + kposB + seg * 8);
        }
    };

    #pragma unroll
    for (int s = 0; s < STAGES - 1; s++) {
        fill(s, s);
        CP_COMMIT();
    }

    for (int c = 0; c < NCHUNK; c++) {
        CP_WAIT(STAGES - 2);
        __syncthreads();

        if (c + STAGES - 1 < NCHUNK)
            fill(c + STAGES - 1, (c + STAGES - 1) % STAGES);
        CP_COMMIT();

        const int slot = c % STAGES;
        const uint32_t abase = sbase + slot * STG_SZ;
        const uint32_t bbase = abase + STG_A;
        #pragma unroll
        for (int ks = 0; ks < 4; ks++) {
            const int kp = ks * 16;
            uint32_t af[2][4];
            #pragma unroll
            for (int mt = 0; mt < 2; mt++) {
                uint32_t addr = abase + (a_row + mt * 16) * RSB + (kp + a_koff) * 2;
                ldsm4(af[mt][0], af[mt][1], af[mt][2], af[mt][3], addr);
            }
            uint32_t bf[8][2];
            #pragma unroll
            for (int bt = 0; bt < 4; bt++) {
                uint32_t addr = bbase + (b_row_base + bt * 16) * RSB + (kp + b_koff) * 2;
                ldsm4(bf[2*bt][0], bf[2*bt][1], bf[2*bt+1][0], bf[2*bt+1][1], addr);
            }
            #pragma unroll
            for (int mt = 0; mt < 2; mt++)
                #pragma unroll
                for (int nt = 0; nt < 8; nt++)
                    mma16816(acc[mt][nt], af[mt], bf[nt]);
        }
    }
}

// ---------------- fused QKV projection kernel --------------------------------
__global__ __launch_bounds__(256)
void qkv_gemm(const __half* __restrict__ A,
              const __half* __restrict__ Wq, const __half* __restrict__ Wkv,
              __half* __restrict__ qhi, __half* __restrict__ qlo,
              __half* __restrict__ khi, __half* __restrict__ vhi)
{
    extern __shared__ char gsm[];
    const uint32_t sbase = smem_u32(gsm);

    const int tid  = threadIdx.x;
    const int wid  = tid >> 5;
    const int lane = tid & 31;
    const int bm   = blockIdx.y * BM;
    const bool isQ = blockIdx.x < (D_MODEL / BN);
    const int bn   = (isQ ? blockIdx.x : blockIdx.x - D_MODEL / BN) * BN;
    const int wm   = (wid & 3) * 32;
    const int wn   = (wid >> 2) * 64;

    float acc[2][8][4];
    #pragma unroll
    for (int i = 0; i < 2; i++)
        #pragma unroll
        for (int j = 0; j < 8; j++)
            #pragma unroll
            for (int t = 0; t < 4; t++) acc[i][j][t] = 0.f;

    const __half* Ab = A + (size_t)bm * KEFF2;
    const __half* Bb = (isQ ? Wq : Wkv) + (size_t)bn * KDIM;

    gemm_core<KEFF2>(Ab, Bb, sbase, tid, lane, wm, wn, acc);

    const int cr = lane >> 2;
    const int cc = (lane & 3) * 2;

    if (isQ) {
        const int head = (bn + wn) >> 6;
        #pragma unroll
        for (int mt = 0; mt < 2; mt++) {
            #pragma unroll
            for (int r = 0; r < 2; r++) {
                const int row = bm + wm + mt * 16 + cr + r * 8;
                const int s = row & (S_LEN - 1);
                #pragma unroll
                for (int nt = 0; nt < 4; nt++) {
                    const int j = nt * 8 + cc;
                    float c0 = g_cos[(s << 5) + j],     sn0 = g_sin[(s << 5) + j];
                    float c1 = g_cos[(s << 5) + j + 1], sn1 = g_sin[(s << 5) + j + 1];
                    float x1a = acc[mt][nt][2*r],     x1b = acc[mt][nt][2*r + 1];
                    float x2a = acc[mt][nt+4][2*r],   x2b = acc[mt][nt+4][2*r + 1];
                    float y1a = (x1a * c0 - x2a * sn0) * 0.125f;
                    float y1b = (x1b * c1 - x2b * sn1) * 0.125f;
                    float y2a = (x2a * c0 + x1a * sn0) * 0.125f;
                    float y2b = (x2b * c1 + x1b * sn1) * 0.125f;
                    size_t off = (size_t)row * D_MODEL + head * HDIM + j;
                    store_split2(qhi, qlo, off,      y1a, y1b);
                    store_split2(qhi, qlo, off + 32, y2a, y2b);
                }
            }
        }
    } else {
        const int hh = (bn + wn) >> 6;
        if (hh < NKVH) {
            #pragma unroll
            for (int mt = 0; mt < 2; mt++) {
                #pragma unroll
                for (int r = 0; r < 2; r++) {
                    const int row = bm + wm + mt * 16 + cr + r * 8;
                    const int s = row & (S_LEN - 1);
                    #pragma unroll
                    for (int nt = 0; nt < 4; nt++) {
                        const int j = nt * 8 + cc;
                        float c0 = g_cos[(s << 5) + j],     sn0 = g_sin[(s << 5) + j];
                        float c1 = g_cos[(s << 5) + j + 1], sn1 = g_sin[(s << 5) + j + 1];
                        float x1a = acc[mt][nt][2*r],   x1b = acc[mt][nt][2*r + 1];
                        float x2a = acc[mt][nt+4][2*r], x2b = acc[mt][nt+4][2*r + 1];
                        size_t off = (size_t)row * KVD + hh * HDIM + j;
                        *reinterpret_cast<__half2*>(khi + off) =
                            __floats2half2_rn(x1a * c0 - x2a * sn0, x1b * c1 - x2b * sn1);
                        *reinterpret_cast<__half2*>(khi + off + 32) =
                            __floats2half2_rn(x2a * c0 + x1a * sn0, x2b * c1 + x1b * sn1);
                    }
                }
            }
        } else {
            const int vh = hh - NKVH;
            #pragma unroll
            for (int mt = 0; mt < 2; mt++) {
                #pragma unroll
                for (int r = 0; r < 2; r++) {
                    const int row = bm + wm + mt * 16 + cr + r * 8;
                    #pragma unroll
                    for (int nt = 0; nt < 8; nt++) {
                        size_t off = (size_t)row * KVD + vh * HDIM + nt * 8 + cc;
                        *reinterpret_cast<__half2*>(vhi + off) =
                            __floats2half2_rn(acc[mt][nt][2*r], acc[mt][nt][2*r + 1]);
                    }
                }
            }
        }
    }
}

// ---------------- output projection kernel -----------------------------------
__global__ __launch_bounds__(256)
void out_gemm(const __half* __restrict__ A, const __half* __restrict__ B,
              float* __restrict__ C)
{
    extern __shared__ char gsm[];
    const uint32_t sbase = smem_u32(gsm);

    const int tid  = threadIdx.x;
    const int wid  = tid >> 5;
    const int lane = tid & 31;
    const int bm   = blockIdx.y * BM;
    const int bn   = blockIdx.x * BN;
    const int wm   = (wid & 3) * 32;
    const int wn   = (wid >> 2) * 64;

    float acc[2][8][4];
    #pragma unroll
    for (int i = 0; i < 2; i++)
        #pragma unroll
        for (int j = 0; j < 8; j++)
            #pragma unroll
            for (int t = 0; t < 4; t++) acc[i][j][t] = 0.f;

    gemm_core<KDIM>(A + (size_t)bm * KDIM, B + (size_t)bn * KDIM,
                    sbase, tid, lane, wm, wn, acc);

    const int cr = lane >> 2;
    const int cc = (lane & 3) * 2;
    #pragma unroll
    for (int mt = 0; mt < 2; mt++) {
        #pragma unroll
        for (int nt = 0; nt < 8; nt++) {
            float* p0 = C + (size_t)(bm + wm + mt * 16 + cr) * D_MODEL + bn + wn + nt * 8 + cc;
            float* p1 = p0 + 8 * (size_t)D_MODEL;
            p0[0] = acc[mt][nt][0]; p0[1] = acc[mt][nt][1];
            p1[0] = acc[mt][nt][2]; p1[1] = acc[mt][nt][3];
        }
    }
}

// ---------------- HMMA causal GQA flash attention ----------------------------
// Q hi+lo, K hi, V hi, P hi-only in PV.
#define AT_STRB 144
#define KVBUF   (2 * 64 * AT_STRB)

__global__ __launch_bounds__(256, 2)
void attn_hmma(const __half* __restrict__ qhi, const __half* __restrict__ qlo,
               const __half* __restrict__ khi, const __half* __restrict__ vhi,
               __half* __restrict__ chat)
{
    __shared__ __align__(16) char sm[2 * KVBUF];

    const int qb  = gridDim.x - 1 - blockIdx.x;
    const int h   = blockIdx.y;
    const int b   = blockIdx.z;
    const int kvh = h / GSIZE;
    const int tid = threadIdx.x;
    const int wid = tid >> 5;
    const int lane = tid & 31;
    const int qrow0 = qb * 128;
    const int wm = wid * 16;

    const uint32_t sbase = smem_u32(sm);
    const int VOFF = 64 * AT_STRB;

    {
        const __half* srcs[2] = {qhi, qlo};
        #pragma unroll
        for (int arr = 0; arr < 2; arr++) {
            const __half* s = srcs[arr];
            #pragma unroll
            for (int i = 0; i < 4; i++) {
                int u = tid + 256 * i;
                int row = u >> 3, seg = u & 7;
                uint4 v = *(const uint4*)(s + ((size_t)(b * S_LEN + qrow0 + row)) * D_MODEL
                                            + h * HDIM + seg * 8);
                *(uint4*)(sm + arr * (128 * AT_STRB) + row * AT_STRB + seg * 16) = v;
            }
        }
    }
    __syncthreads();

    uint32_t qh[4][4], ql[4][4];
    {
        uint32_t arow = (uint32_t)(wm + (lane & 15));
        uint32_t koff = ((lane >> 4) & 1) * 8;
        #pragma unroll
        for (int kc = 0; kc < 4; kc++) {
            uint32_t a0 = sbase + arow * AT_STRB + (kc * 16 + koff) * 2;
            ldsm4(qh[kc][0], qh[kc][1], qh[kc][2], qh[kc][3], a0);
            ldsm4(ql[kc][0], ql[kc][1], ql[kc][2], ql[kc][3], a0 + 128 * AT_STRB);
        }
    }
    __syncthreads();

    float m0 = -1e30f, m1 = -1e30f, l0 = 0.f, l1 = 0.f;
    float ctxa[8][4];
    #pragma unroll
    for (int t = 0; t < 8; t++)
        #pragma unroll
        for (int j = 0; j < 4; j++) ctxa[t][j] = 0.f;

    const int nkt = 2 * qb + 2;

    auto fillkv = [&](int kt, int buf) {
        const int k0 = kt * 64;
        const uint32_t base = sbase + buf * KVBUF;
        const __half* srcs[2] = {khi, vhi};
        #pragma unroll
        for (int arr = 0; arr < 2; arr++) {
            const __half* s = srcs[arr];
            #pragma unroll
            for (int i = 0; i < 2; i++) {
                int u = tid + 256 * i;
                int row = u >> 3, seg = u & 7;
                cp16(base + arr * VOFF + row * AT_STRB + seg * 16,
                     s + ((size_t)(b * S_LEN + k0 + row)) * KVD + kvh * HDIM + seg * 8);
            }
        }
    };

    fillkv(0, 0);
    CP_COMMIT();

    for (int kt = 0; kt < nkt; kt++) {
        const int k0 = kt * 64;
        const int buf = kt & 1;
        __syncthreads();
        if (kt + 1 < nkt) {
            fillkv(kt + 1, buf ^ 1);
            CP_COMMIT();
            CP_WAIT(1);
        } else {
            CP_WAIT(0);
        }
        __syncthreads();

        const uint32_t kvbase = sbase + buf * KVBUF;

        if (k0 <= qrow0 + wm + 15) {
            float sc[8][4];
            #pragma unroll
            for (int t = 0; t < 8; t++)
                #pragma unroll
                for (int j = 0; j < 4; j++) sc[t][j] = 0.f;

            #pragma unroll
            for (int g = 0; g < 4; g++) {
                uint32_t kh[4][4];
                #pragma unroll
                for (int kc = 0; kc < 4; kc++) {
                    uint32_t addr = kvbase
                        + (g * 16 + (lane & 7) + ((lane >> 4) & 1) * 8) * AT_STRB
                        + (kc * 16 + ((lane >> 3) & 1) * 8) * 2;
                    ldsm4(kh[kc][0], kh[kc][1], kh[kc][2], kh[kc][3], addr);
                }
                #pragma unroll
                for (int kc = 0; kc < 4; kc++) {
                    uint32_t bh0[2] = {kh[kc][0], kh[kc][1]};
                    uint32_t bh1[2] = {kh[kc][2], kh[kc][3]};
                    mma16816(sc[2*g],   qh[kc], bh0);
                    mma16816(sc[2*g],   ql[kc], bh0);
                    mma16816(sc[2*g+1], qh[kc], bh1);
                    mma16816(sc[2*g+1], ql[kc], bh1);
                }
            }

            const int rtop = qrow0 + wm + (lane >> 2);
            const int rbot = rtop + 8;
            if (kt >= nkt - 2) {
                #pragma unroll
                for (int t = 0; t < 8; t++) {
                    int kg = k0 + t * 8 + (lane & 3) * 2;
                    if (kg     > rtop) sc[t][0] = -1e30f;
                    if (kg + 1 > rtop) sc[t][1] = -1e30f;
                    if (kg     > rbot) sc[t][2] = -1e30f;
                    if (kg + 1 > rbot) sc[t][3] = -1e30f;
                }
            }

            float tm0 = -1e30f, tm1 = -1e30f;
            #pragma unroll
            for (int t = 0; t < 8; t++) {
                tm0 = fmaxf(tm0, fmaxf(sc[t][0], sc[t][1]));
                tm1 = fmaxf(tm1, fmaxf(sc[t][2], sc[t][3]));
            }
            tm0 = fmaxf(tm0, __shfl_xor_sync(0xFFFFFFFFu, tm0, 1));
            tm0 = fmaxf(tm0, __shfl_xor_sync(0xFFFFFFFFu, tm0, 2));
            tm1 = fmaxf(tm1, __shfl_xor_sync(0xFFFFFFFFu, tm1, 1));
            tm1 = fmaxf(tm1, __shfl_xor_sync(0xFFFFFFFFu, tm1, 2));
            float mn0 = fmaxf(m0, tm0), mn1 = fmaxf(m1, tm1);
            float c0 = __expf(m0 - mn0), c1 = __expf(m1 - mn1);
            m0 = mn0; m1 = mn1;
            l0 *= c0;  l1 *= c1;
            #pragma unroll
            for (int t = 0; t < 8; t++) {
                ctxa[t][0] *= c0; ctxa[t][1] *= c0;
                ctxa[t][2] *= c1; ctxa[t][3] *= c1;
            }

            float ps0 = 0.f, ps1 = 0.f;
            uint32_t ph[4][4];
            #pragma unroll
            for (int t = 0; t < 8; t++) {
                float p0 = __expf(sc[t][0] - mn0);
                float p1 = __expf(sc[t][1] - mn0);
                float p2 = __expf(sc[t][2] - mn1);
                float p3 = __expf(sc[t][3] - mn1);
                ps0 += p0 + p1; ps1 += p2 + p3;
                int kc = t >> 1, hf = (t & 1) * 2;
                ph[kc][hf]     = pack2h(p0, p1);
                ph[kc][hf + 1] = pack2h(p2, p3);
            }
            ps0 += __shfl_xor_sync(0xFFFFFFFFu, ps0, 1);
            ps0 += __shfl_xor_sync(0xFFFFFFFFu, ps0, 2);
            ps1 += __shfl_xor_sync(0xFFFFFFFFu, ps1, 1);
            ps1 += __shfl_xor_sync(0xFFFFFFFFu, ps1, 2);
            l0 += ps0; l1 += ps1;

            #pragma unroll
            for (int kc = 0; kc < 4; kc++) {
                #pragma unroll
                for (int g = 0; g < 4; g++) {
                    uint32_t vh[4];
                    uint32_t addr = kvbase + VOFF
                        + (kc * 16 + (lane & 7) + ((lane >> 3) & 1) * 8) * AT_STRB
                        + (g * 16 + ((lane >> 4) & 1) * 8) * 2;
                    ldsm4t(vh[0], vh[1], vh[2], vh[3], addr);
                    uint32_t bh0[2] = {vh[0], vh[1]};
                    uint32_t bh1[2] = {vh[2], vh[3]};
                    mma16816(ctxa[2*g],   ph[kc], bh0);
                    mma16816(ctxa[2*g+1], ph[kc], bh1);
                }
            }
        }
    }

    float il0 = 1.f / l0, il1 = 1.f / l1;
    const int rtop = qrow0 + wm + (lane >> 2);
    const size_t row0 = (size_t)(b * S_LEN) + rtop;
    __half* c0p = chat + row0 * KDIM + h * HDIM;
    __half* c1p = c0p + 8 * (size_t)KDIM;
    #pragma unroll
    for (int t = 0; t < 8; t++) {
        int col = t * 8 + (lane & 3) * 2;
        *reinterpret_cast<__half2*>(c0p + col) =
            __floats2half2_rn(ctxa[t][0] * il0, ctxa[t][1] * il0);
        *reinterpret_cast<__half2*>(c1p + col) =
            __floats2half2_rn(ctxa[t][2] * il1, ctxa[t][3] * il1);
    }
}

// ---------------- host launch -------------------------------------------------
extern "C" void kernel_launch(void* const* d_in, const int* in_sizes, int n_in,
                              void* d_out, int out_size)
{
    const float* x  = (const float*)d_in[0];
    const float* Wq = (const float*)d_in[1];
    const float* Wk = (const float*)d_in[2];
    const float* Wv = (const float*)d_in[3];
    const float* Wo = (const float*)d_in[4];
    float* out = (float*)d_out;

    __half *ahat, *chat, *wq, *wkv, *wo, *qhi, *qlo, *khi, *vhi;
    cudaGetSymbolAddress((void**)&ahat, g_ahat);
    cudaGetSymbolAddress((void**)&chat, g_chat);
    cudaGetSymbolAddress((void**)&wq,   g_wq);
    cudaGetSymbolAddress((void**)&wkv,  g_wkv);
    cudaGetSymbolAddress((void**)&wo,   g_wo);
    cudaGetSymbolAddress((void**)&qhi,  g_qhi);
    cudaGetSymbolAddress((void**)&qlo,  g_qlo);
    cudaGetSymbolAddress((void**)&khi,  g_khi);
    cudaGetSymbolAddress((void**)&vhi,  g_vhi);

    static int smem_set = 0;
    if (!smem_set) {
        cudaFuncSetAttribute(qkv_gemm, cudaFuncAttributeMaxDynamicSharedMemorySize, GSMEM);
        cudaFuncSetAttribute(out_gemm, cudaFuncAttributeMaxDynamicSharedMemorySize, GSMEM);
        smem_set = 1;
    }

    // fused prep: conv_split + rope table + all weight transposes
    prep<<<PREP_BLOCKS, 256>>>(x, Wq, Wk, Wv, Wo, ahat, wq, wkv, wo);

    // fused Q + KV projection (24 n-tiles: 16 Q + 8 KV)
    qkv_gemm<<<dim3((D_MODEL + NKV2) / BN, MROWS / BM), 256, GSMEM>>>(
        ahat, wq, wkv, qhi, qlo, khi, vhi);

    // attention (writes fp16 ctx directly)
    attn_hmma<<<dim3(S_LEN / 128, NHEADS, BATCH), 256>>>(qhi, qlo, khi, vhi, chat);

    // output projection (K = 2048)
    out_gemm<<<dim3(D_MODEL / BN, MROWS / BM), 256, GSMEM>>>(chat, wo, out);
}

// round 12
// speedup vs baseline: 1.8740x; 1.0096x over previous
#include <cuda_runtime.h>
#include <cuda_fp16.h>
#include <math.h>
#include <cstdint>

#define BATCH   2
#define S_LEN   2048
#define D_MODEL 2048
#define NHEADS  32
#define NKVH    8
#define HDIM    64
#define GSIZE   (NHEADS / NKVH)
#define KVD     (NKVH * HDIM)        // 512
#define MROWS   (BATCH * S_LEN)      // 4096
#define KDIM    2048
#define KEFF2   (2 * KDIM)           // 4096 stacked K (hi|lo)
#define NKV2    (2 * KVD)            // 1024 fused K|V width

// ---------------- scratch (device globals) ----------------------------------
__device__ __half g_ahat[(size_t)MROWS  * KEFF2];
__device__ __half g_chat[(size_t)MROWS  * KDIM];
__device__ __half g_wq [(size_t)D_MODEL * KDIM];
__device__ __half g_wkv[(size_t)NKV2    * KDIM];
__device__ __half g_wo [(size_t)D_MODEL * KDIM];
__device__ float g_cos[S_LEN * 32];
__device__ float g_sin[S_LEN * 32];
__device__ __half g_qhi[MROWS * D_MODEL];
__device__ __half g_qlo[MROWS * D_MODEL];
__device__ __half g_khi[MROWS * KVD];
__device__ __half g_vhi[MROWS * KVD];

// ---------------- helpers ------------------------------------------------
__device__ __forceinline__ uint32_t smem_u32(const void* p) {
    uint32_t a;
    asm("{ .reg .u64 t; cvta.to.shared.u64 t, %1; cvt.u32.u64 %0, t; }"
        : "=r"(a) : "l"(p));
    return a;
}

__device__ __forceinline__ void cp16(uint32_t saddr, const void* gaddr) {
    asm volatile("cp.async.cg.shared.global [%0], [%1], 16;"
                 :: "r"(saddr), "l"(gaddr) : "memory");
}
#define CP_COMMIT() asm volatile("cp.async.commit_group;" ::: "memory")
#define CP_WAIT(n)  asm volatile("cp.async.wait_group %0;" :: "n"(n) : "memory")

__device__ __forceinline__ void ldsm4(uint32_t& r0, uint32_t& r1, uint32_t& r2,
                                      uint32_t& r3, uint32_t addr) {
    asm volatile("ldmatrix.sync.aligned.m8n8.x4.shared.b16 {%0,%1,%2,%3}, [%4];"
                 : "=r"(r0), "=r"(r1), "=r"(r2), "=r"(r3) : "r"(addr));
}
__device__ __forceinline__ void ldsm4t(uint32_t& r0, uint32_t& r1, uint32_t& r2,
                                       uint32_t& r3, uint32_t addr) {
    asm volatile("ldmatrix.sync.aligned.m8n8.x4.trans.shared.b16 {%0,%1,%2,%3}, [%4];"
                 : "=r"(r0), "=r"(r1), "=r"(r2), "=r"(r3) : "r"(addr));
}

__device__ __forceinline__ void mma16816(float* d, const uint32_t* a, const uint32_t* b) {
    asm volatile(
        "mma.sync.aligned.m16n8k16.row.col.f32.f16.f16.f32 "
        "{%0,%1,%2,%3}, {%4,%5,%6,%7}, {%8,%9}, {%0,%1,%2,%3};"
        : "+f"(d[0]), "+f"(d[1]), "+f"(d[2]), "+f"(d[3])
        : "r"(a[0]), "r"(a[1]), "r"(a[2]), "r"(a[3]), "r"(b[0]), "r"(b[1]));
}

__device__ __forceinline__ uint32_t pack2h(float lo_e, float hi_e) {
    __half2 h = __floats2half2_rn(lo_e, hi_e);
    return *reinterpret_cast<uint32_t*>(&h);
}

__device__ __forceinline__ void store_split2(__half* hi, __half* lo, size_t off,
                                             float ya, float yb) {
    __half2 h = __floats2half2_rn(ya, yb);
    *reinterpret_cast<__half2*>(hi + off) = h;
    __half2 l = __floats2half2_rn(ya - __low2float(h), yb - __high2float(h));
    *reinterpret_cast<__half2*>(lo + off) = l;
}

// ---------------- fused prep kernel -------------------------------------------
#define PREP_SPLIT_BLOCKS 32768
#define PREP_ROPE_BLOCKS  256
#define PREP_BLOCKS       (PREP_SPLIT_BLOCKS + PREP_ROPE_BLOCKS + 10240)

__device__ __forceinline__ void wt_body(const float* __restrict__ W,
                                        __half* __restrict__ out, int N,
                                        int bx, int by, float tile[32][33])
{
    int tx = threadIdx.x & 31, tg = threadIdx.x >> 5;
    int k0 = by * 32, n0 = bx * 32;
    #pragma unroll
    for (int i = 0; i < 4; i++) {
        int ty = tg * 4 + i;
        tile[ty][tx] = W[(size_t)(k0 + ty) * N + n0 + tx];
    }
    __syncthreads();
    #pragma unroll
    for (int i = 0; i < 4; i++) {
        int ty = tg * 4 + i;
        out[(size_t)(n0 + ty) * KDIM + k0 + tx] = __float2half_rn(tile[tx][ty]);
    }
}

__global__ __launch_bounds__(256)
void prep(const float* __restrict__ x,
          const float* __restrict__ Wq, const float* __restrict__ Wk,
          const float* __restrict__ Wv, const float* __restrict__ Wo,
          __half* __restrict__ ahat, __half* __restrict__ wq,
          __half* __restrict__ wkv, __half* __restrict__ wo)
{
    __shared__ float tile[32][33];
    const int bid = blockIdx.x;
    const int tid = threadIdx.x;

    if (bid < PREP_SPLIT_BLOCKS) {
        int i = bid * 256 + tid;
        int row = i / KDIM, col = i - row * KDIM;
        float v = x[i];
        __half hi = __float2half_rn(v);
        __half lo = __float2half_rn(v - __half2float(hi));
        size_t base = (size_t)row * KEFF2 + col;
        ahat[base]        = hi;
        ahat[base + KDIM] = lo;
    } else if (bid < PREP_SPLIT_BLOCKS + PREP_ROPE_BLOCKS) {
        int i = (bid - PREP_SPLIT_BLOCKS) * 256 + tid;
        int s = i >> 5, j = i & 31;
        float inv = (float)exp(-(double)j * (log(10000.0) / 32.0));
        float ang = (float)s * inv;
        float c, sn;
        sincosf(ang, &sn, &c);
        g_cos[i] = c;
        g_sin[i] = sn;
    } else {
        int idx = bid - (PREP_SPLIT_BLOCKS + PREP_ROPE_BLOCKS);
        if (idx < 4096) {
            wt_body(Wq, wq, D_MODEL, idx & 63, idx >> 6, tile);
        } else if (idx < 5120) {
            int l = idx - 4096;
            wt_body(Wk, wkv, KVD, l & 15, l >> 4, tile);
        } else if (idx < 6144) {
            int l = idx - 5120;
            wt_body(Wv, wkv + (size_t)KVD * KDIM, KVD, l & 15, l >> 4, tile);
        } else {
            int l = idx - 6144;
            wt_body(Wo, wo, D_MODEL, l & 63, l >> 6, tile);
        }
    }
}

// ---------------- GEMM core ----------------------------------------------------
// 128x128 CTA, 4 warps (2M x 2N), warp tile 64x64, KC=64, 3 stages, 128 threads.
#define BM 128
#define BN 128
#define KC 64
#define STAGES 3
#define RSB    144
#define STG_A  (128 * RSB)
#define STG_SZ (2 * STG_A)
#define GSMEM  (STAGES * STG_SZ)     // 110592
#define GTHREADS 128

template<int KAS>
__device__ __forceinline__ void gemm_core(
    const __half* __restrict__ Ab, const __half* __restrict__ Bb,
    uint32_t sbase, int tid, int lane, int wm, int wn, float acc[4][8][4])
{
    constexpr int NCHUNK = KAS / KC;

    const int a_row  = wm + (lane & 15);
    const int a_koff = ((lane >> 4) & 1) * 8;
    const int b_row_base = wn + (lane & 7) + ((lane >> 4) & 1) * 8;
    const int b_koff = ((lane >> 3) & 1) * 8;

    auto fill = [&](int c, int slot) {
        const int kposA = c * KC;
        const int kposB = kposA & (KDIM - 1);
        const uint32_t abase = sbase + slot * STG_SZ;
        const uint32_t bbase = abase + STG_A;
        #pragma unroll
        for (int i = 0; i < 8; i++) {
            int u = tid + GTHREADS * i;
            int row = u >> 3, seg = u & 7;
            cp16(abase + row * RSB + seg * 16, Ab + (size_t)row * KAS  + kposA + seg * 8);
            cp16(bbase + row * RSB + seg * 16, Bb + (size_t)row * KDIM + kposB + seg * 8);
        }
    };

    #pragma unroll
    for (int s = 0; s < STAGES - 1; s++) {
        fill(s, s);
        CP_COMMIT();
    }

    for (int c = 0; c < NCHUNK; c++) {
        CP_WAIT(STAGES - 2);
        __syncthreads();

        if (c + STAGES - 1 < NCHUNK)
            fill(c + STAGES - 1, (c + STAGES - 1) % STAGES);
        CP_COMMIT();

        const int slot = c % STAGES;
        const uint32_t abase = sbase + slot * STG_SZ;
        const uint32_t bbase = abase + STG_A;
        #pragma unroll
        for (int ks = 0; ks < 4; ks++) {
            const int kp = ks * 16;
            uint32_t af[4][4];
            #pragma unroll
            for (int mt = 0; mt < 4; mt++) {
                uint32_t addr = abase + (a_row + mt * 16) * RSB + (kp + a_koff) * 2;
                ldsm4(af[mt][0], af[mt][1], af[mt][2], af[mt][3], addr);
            }
            uint32_t bf[8][2];
            #pragma unroll
            for (int bt = 0; bt < 4; bt++) {
                uint32_t addr = bbase + (b_row_base + bt * 16) * RSB + (kp + b_koff) * 2;
                ldsm4(bf[2*bt][0], bf[2*bt][1], bf[2*bt+1][0], bf[2*bt+1][1], addr);
            }
            #pragma unroll
            for (int mt = 0; mt < 4; mt++)
                #pragma unroll
                for (int nt = 0; nt < 8; nt++)
                    mma16816(acc[mt][nt], af[mt], bf[nt]);
        }
    }
}

// ---------------- fused QKV projection kernel --------------------------------
__global__ __launch_bounds__(GTHREADS)
void qkv_gemm(const __half* __restrict__ A,
              const __half* __restrict__ Wq, const __half* __restrict__ Wkv,
              __half* __restrict__ qhi, __half* __restrict__ qlo,
              __half* __restrict__ khi, __half* __restrict__ vhi)
{
    extern __shared__ char gsm[];
    const uint32_t sbase = smem_u32(gsm);

    const int tid  = threadIdx.x;
    const int wid  = tid >> 5;
    const int lane = tid & 31;
    const int bm   = blockIdx.y * BM;
    const bool isQ = blockIdx.x < (D_MODEL / BN);
    const int bn   = (isQ ? blockIdx.x : blockIdx.x - D_MODEL / BN) * BN;
    const int wm   = (wid & 1) * 64;
    const int wn   = (wid >> 1) * 64;

    float acc[4][8][4];
    #pragma unroll
    for (int i = 0; i < 4; i++)
        #pragma unroll
        for (int j = 0; j < 8; j++)
            #pragma unroll
            for (int t = 0; t < 4; t++) acc[i][j][t] = 0.f;

    const __half* Ab = A + (size_t)bm * KEFF2;
    const __half* Bb = (isQ ? Wq : Wkv) + (size_t)bn * KDIM;

    gemm_core<KEFF2>(Ab, Bb, sbase, tid, lane, wm, wn, acc);

    const int cr = lane >> 2;
    const int cc = (lane & 3) * 2;

    if (isQ) {
        const int head = (bn + wn) >> 6;
        #pragma unroll
        for (int mt = 0; mt < 4; mt++) {
            #pragma unroll
            for (int r = 0; r < 2; r++) {
                const int row = bm + wm + mt * 16 + cr + r * 8;
                const int s = row & (S_LEN - 1);
                #pragma unroll
                for (int nt = 0; nt < 4; nt++) {
                    const int j = nt * 8 + cc;
                    float c0 = g_cos[(s << 5) + j],     sn0 = g_sin[(s << 5) + j];
                    float c1 = g_cos[(s << 5) + j + 1], sn1 = g_sin[(s << 5) + j + 1];
                    float x1a = acc[mt][nt][2*r],     x1b = acc[mt][nt][2*r + 1];
                    float x2a = acc[mt][nt+4][2*r],   x2b = acc[mt][nt+4][2*r + 1];
                    float y1a = (x1a * c0 - x2a * sn0) * 0.125f;
                    float y1b = (x1b * c1 - x2b * sn1) * 0.125f;
                    float y2a = (x2a * c0 + x1a * sn0) * 0.125f;
                    float y2b = (x2b * c1 + x1b * sn1) * 0.125f;
                    size_t off = (size_t)row * D_MODEL + head * HDIM + j;
                    store_split2(qhi, qlo, off,      y1a, y1b);
                    store_split2(qhi, qlo, off + 32, y2a, y2b);
                }
            }
        }
    } else {
        const int hh = (bn + wn) >> 6;
        if (hh < NKVH) {
            #pragma unroll
            for (int mt = 0; mt < 4; mt++) {
                #pragma unroll
                for (int r = 0; r < 2; r++) {
                    const int row = bm + wm + mt * 16 + cr + r * 8;
                    const int s = row & (S_LEN - 1);
                    #pragma unroll
                    for (int nt = 0; nt < 4; nt++) {
                        const int j = nt * 8 + cc;
                        float c0 = g_cos[(s << 5) + j],     sn0 = g_sin[(s << 5) + j];
                        float c1 = g_cos[(s << 5) + j + 1], sn1 = g_sin[(s << 5) + j + 1];
                        float x1a = acc[mt][nt][2*r],   x1b = acc[mt][nt][2*r + 1];
                        float x2a = acc[mt][nt+4][2*r], x2b = acc[mt][nt+4][2*r + 1];
                        size_t off = (size_t)row * KVD + hh * HDIM + j;
                        *reinterpret_cast<__half2*>(khi + off) =
                            __floats2half2_rn(x1a * c0 - x2a * sn0, x1b * c1 - x2b * sn1);
                        *reinterpret_cast<__half2*>(khi + off + 32) =
                            __floats2half2_rn(x2a * c0 + x1a * sn0, x2b * c1 + x1b * sn1);
                    }
                }
            }
        } else {
            const int vh = hh - NKVH;
            #pragma unroll
            for (int mt = 0; mt < 4; mt++) {
                #pragma unroll
                for (int r = 0; r < 2; r++) {
                    const int row = bm + wm + mt * 16 + cr + r * 8;
                    #pragma unroll
                    for (int nt = 0; nt < 8; nt++) {
                        size_t off = (size_t)row * KVD + vh * HDIM + nt * 8 + cc;
                        *reinterpret_cast<__half2*>(vhi + off) =
                            __floats2half2_rn(acc[mt][nt][2*r], acc[mt][nt][2*r + 1]);
                    }
                }
            }
        }
    }
}

// ---------------- output projection kernel -----------------------------------
__global__ __launch_bounds__(GTHREADS)
void out_gemm(const __half* __restrict__ A, const __half* __restrict__ B,
              float* __restrict__ C)
{
    extern __shared__ char gsm[];
    const uint32_t sbase = smem_u32(gsm);

    const int tid  = threadIdx.x;
    const int wid  = tid >> 5;
    const int lane = tid & 31;
    const int bm   = blockIdx.y * BM;
    const int bn   = blockIdx.x * BN;
    const int wm   = (wid & 1) * 64;
    const int wn   = (wid >> 1) * 64;

    float acc[4][8][4];
    #pragma unroll
    for (int i = 0; i < 4; i++)
        #pragma unroll
        for (int j = 0; j < 8; j++)
            #pragma unroll
            for (int t = 0; t < 4; t++) acc[i][j][t] = 0.f;

    gemm_core<KDIM>(A + (size_t)bm * KDIM, B + (size_t)bn * KDIM,
                    sbase, tid, lane, wm, wn, acc);

    const int cr = lane >> 2;
    const int cc = (lane & 3) * 2;
    #pragma unroll
    for (int mt = 0; mt < 4; mt++) {
        #pragma unroll
        for (int nt = 0; nt < 8; nt++) {
            float* p0 = C + (size_t)(bm + wm + mt * 16 + cr) * D_MODEL + bn + wn + nt * 8 + cc;
            float* p1 = p0 + 8 * (size_t)D_MODEL;
            p0[0] = acc[mt][nt][0]; p0[1] = acc[mt][nt][1];
            p1[0] = acc[mt][nt][2]; p1[1] = acc[mt][nt][3];
        }
    }
}

// ---------------- HMMA causal GQA flash attention (unchanged from R11) -------
#define AT_STRB 144
#define KVBUF   (2 * 64 * AT_STRB)

__global__ __launch_bounds__(256, 2)
void attn_hmma(const __half* __restrict__ qhi, const __half* __restrict__ qlo,
               const __half* __restrict__ khi, const __half* __restrict__ vhi,
               __half* __restrict__ chat)
{
    __shared__ __align__(16) char sm[2 * KVBUF];

    const int qb  = gridDim.x - 1 - blockIdx.x;
    const int h   = blockIdx.y;
    const int b   = blockIdx.z;
    const int kvh = h / GSIZE;
    const int tid = threadIdx.x;
    const int wid = tid >> 5;
    const int lane = tid & 31;
    const int qrow0 = qb * 128;
    const int wm = wid * 16;

    const uint32_t sbase = smem_u32(sm);
    const int VOFF = 64 * AT_STRB;

    {
        const __half* srcs[2] = {qhi, qlo};
        #pragma unroll
        for (int arr = 0; arr < 2; arr++) {
            const __half* s = srcs[arr];
            #pragma unroll
            for (int i = 0; i < 4; i++) {
                int u = tid + 256 * i;
                int row = u >> 3, seg = u & 7;
                uint4 v = *(const uint4*)(s + ((size_t)(b * S_LEN + qrow0 + row)) * D_MODEL
                                            + h * HDIM + seg * 8);
                *(uint4*)(sm + arr * (128 * AT_STRB) + row * AT_STRB + seg * 16) = v;
            }
        }
    }
    __syncthreads();

    uint32_t qh[4][4], ql[4][4];
    {
        uint32_t arow = (uint32_t)(wm + (lane & 15));
        uint32_t koff = ((lane >> 4) & 1) * 8;
        #pragma unroll
        for (int kc = 0; kc < 4; kc++) {
            uint32_t a0 = sbase + arow * AT_STRB + (kc * 16 + koff) * 2;
            ldsm4(qh[kc][0], qh[kc][1], qh[kc][2], qh[kc][3], a0);
            ldsm4(ql[kc][0], ql[kc][1], ql[kc][2], ql[kc][3], a0 + 128 * AT_STRB);
        }
    }
    __syncthreads();

    float m0 = -1e30f, m1 = -1e30f, l0 = 0.f, l1 = 0.f;
    float ctxa[8][4];
    #pragma unroll
    for (int t = 0; t < 8; t++)
        #pragma unroll
        for (int j = 0; j < 4; j++) ctxa[t][j] = 0.f;

    const int nkt = 2 * qb + 2;

    auto fillkv = [&](int kt, int buf) {
        const int k0 = kt * 64;
        const uint32_t base = sbase + buf * KVBUF;
        const __half* srcs[2] = {khi, vhi};
        #pragma unroll
        for (int arr = 0; arr < 2; arr++) {
            const __half* s = srcs[arr];
            #pragma unroll
            for (int i = 0; i < 2; i++) {
                int u = tid + 256 * i;
                int row = u >> 3, seg = u & 7;
                cp16(base + arr * VOFF + row * AT_STRB + seg * 16,
                     s + ((size_t)(b * S_LEN + k0 + row)) * KVD + kvh * HDIM + seg * 8);
            }
        }
    };

    fillkv(0, 0);
    CP_COMMIT();

    for (int kt = 0; kt < nkt; kt++) {
        const int k0 = kt * 64;
        const int buf = kt & 1;
        __syncthreads();
        if (kt + 1 < nkt) {
            fillkv(kt + 1, buf ^ 1);
            CP_COMMIT();
            CP_WAIT(1);
        } else {
            CP_WAIT(0);
        }
        __syncthreads();

        const uint32_t kvbase = sbase + buf * KVBUF;

        if (k0 <= qrow0 + wm + 15) {
            float sc[8][4];
            #pragma unroll
            for (int t = 0; t < 8; t++)
                #pragma unroll
                for (int j = 0; j < 4; j++) sc[t][j] = 0.f;

            #pragma unroll
            for (int g = 0; g < 4; g++) {
                uint32_t kh[4][4];
                #pragma unroll
                for (int kc = 0; kc < 4; kc++) {
                    uint32_t addr = kvbase
                        + (g * 16 + (lane & 7) + ((lane >> 4) & 1) * 8) * AT_STRB
                        + (kc * 16 + ((lane >> 3) & 1) * 8) * 2;
                    ldsm4(kh[kc][0], kh[kc][1], kh[kc][2], kh[kc][3], addr);
                }
                #pragma unroll
                for (int kc = 0; kc < 4; kc++) {
                    uint32_t bh0[2] = {kh[kc][0], kh[kc][1]};
                    uint32_t bh1[2] = {kh[kc][2], kh[kc][3]};
                    mma16816(sc[2*g],   qh[kc], bh0);
                    mma16816(sc[2*g],   ql[kc], bh0);
                    mma16816(sc[2*g+1], qh[kc], bh1);
                    mma16816(sc[2*g+1], ql[kc], bh1);
                }
            }

            const int rtop = qrow0 + wm + (lane >> 2);
            const int rbot = rtop + 8;
            if (kt >= nkt - 2) {
                #pragma unroll
                for (int t = 0; t < 8; t++) {
                    int kg = k0 + t * 8 + (lane & 3) * 2;
                    if (kg     > rtop) sc[t][0] = -1e30f;
                    if (kg + 1 > rtop) sc[t][1] = -1e30f;
                    if (kg     > rbot) sc[t][2] = -1e30f;
                    if (kg + 1 > rbot) sc[t][3] = -1e30f;
                }
            }

            float tm0 = -1e30f, tm1 = -1e30f;
            #pragma unroll
            for (int t = 0; t < 8; t++) {
                tm0 = fmaxf(tm0, fmaxf(sc[t][0], sc[t][1]));
                tm1 = fmaxf(tm1, fmaxf(sc[t][2], sc[t][3]));
            }
            tm0 = fmaxf(tm0, __shfl_xor_sync(0xFFFFFFFFu, tm0, 1));
            tm0 = fmaxf(tm0, __shfl_xor_sync(0xFFFFFFFFu, tm0, 2));
            tm1 = fmaxf(tm1, __shfl_xor_sync(0xFFFFFFFFu, tm1, 1));
            tm1 = fmaxf(tm1, __shfl_xor_sync(0xFFFFFFFFu, tm1, 2));
            float mn0 = fmaxf(m0, tm0), mn1 = fmaxf(m1, tm1);
            float c0 = __expf(m0 - mn0), c1 = __expf(m1 - mn1);
            m0 = mn0; m1 = mn1;
            l0 *= c0;  l1 *= c1;
            #pragma unroll
            for (int t = 0; t < 8; t++) {
                ctxa[t][0] *= c0; ctxa[t][1] *= c0;
                ctxa[t][2] *= c1; ctxa[t][3] *= c1;
            }

            float ps0 = 0.f, ps1 = 0.f;
            uint32_t ph[4][4];
            #pragma unroll
            for (int t = 0; t < 8; t++) {
                float p0 = __expf(sc[t][0] - mn0);
                float p1 = __expf(sc[t][1] - mn0);
                float p2 = __expf(sc[t][2] - mn1);
                float p3 = __expf(sc[t][3] - mn1);
                ps0 += p0 + p1; ps1 += p2 + p3;
                int kc = t >> 1, hf = (t & 1) * 2;
                ph[kc][hf]     = pack2h(p0, p1);
                ph[kc][hf + 1] = pack2h(p2, p3);
            }
            ps0 += __shfl_xor_sync(0xFFFFFFFFu, ps0, 1);
            ps0 += __shfl_xor_sync(0xFFFFFFFFu, ps0, 2);
            ps1 += __shfl_xor_sync(0xFFFFFFFFu, ps1, 1);
            ps1 += __shfl_xor_sync(0xFFFFFFFFu, ps1, 2);
            l0 += ps0; l1 += ps1;

            #pragma unroll
            for (int kc = 0; kc < 4; kc++) {
                #pragma unroll
                for (int g = 0; g < 4; g++) {
                    uint32_t vh[4];
                    uint32_t addr = kvbase + VOFF
                        + (kc * 16 + (lane & 7) + ((lane >> 3) & 1) * 8) * AT_STRB
                        + (g * 16 + ((lane >> 4) & 1) * 8) * 2;
                    ldsm4t(vh[0], vh[1], vh[2], vh[3], addr);
                    uint32_t bh0[2] = {vh[0], vh[1]};
                    uint32_t bh1[2] = {vh[2], vh[3]};
                    mma16816(ctxa[2*g],   ph[kc], bh0);
                    mma16816(ctxa[2*g+1], ph[kc], bh1);
                }
            }
        }
    }

    float il0 = 1.f / l0, il1 = 1.f / l1;
    const int rtop = qrow0 + wm + (lane >> 2);
    const size_t row0 = (size_t)(b * S_LEN) + rtop;
    __half* c0p = chat + row0 * KDIM + h * HDIM;
    __half* c1p = c0p + 8 * (size_t)KDIM;
    #pragma unroll
    for (int t = 0; t < 8; t++) {
        int col = t * 8 + (lane & 3) * 2;
        *reinterpret_cast<__half2*>(c0p + col) =
            __floats2half2_rn(ctxa[t][0] * il0, ctxa[t][1] * il0);
        *reinterpret_cast<__half2*>(c1p + col) =
            __floats2half2_rn(ctxa[t][2] * il1, ctxa[t][3] * il1);
    }
}

// ---------------- host launch -------------------------------------------------
extern "C" void kernel_launch(void* const* d_in, const int* in_sizes, int n_in,
                              void* d_out, int out_size)
{
    const float* x  = (const float*)d_in[0];
    const float* Wq = (const float*)d_in[1];
    const float* Wk = (const float*)d_in[2];
    const float* Wv = (const float*)d_in[3];
    const float* Wo = (const float*)d_in[4];
    float* out = (float*)d_out;

    __half *ahat, *chat, *wq, *wkv, *wo, *qhi, *qlo, *khi, *vhi;
    cudaGetSymbolAddress((void**)&ahat, g_ahat);
    cudaGetSymbolAddress((void**)&chat, g_chat);
    cudaGetSymbolAddress((void**)&wq,   g_wq);
    cudaGetSymbolAddress((void**)&wkv,  g_wkv);
    cudaGetSymbolAddress((void**)&wo,   g_wo);
    cudaGetSymbolAddress((void**)&qhi,  g_qhi);
    cudaGetSymbolAddress((void**)&qlo,  g_qlo);
    cudaGetSymbolAddress((void**)&khi,  g_khi);
    cudaGetSymbolAddress((void**)&vhi,  g_vhi);

    static int smem_set = 0;
    if (!smem_set) {
        cudaFuncSetAttribute(qkv_gemm, cudaFuncAttributeMaxDynamicSharedMemorySize, GSMEM);
        cudaFuncSetAttribute(out_gemm, cudaFuncAttributeMaxDynamicSharedMemorySize, GSMEM);
        smem_set = 1;
    }

    // fused prep
    prep<<<PREP_BLOCKS, 256>>>(x, Wq, Wk, Wv, Wo, ahat, wq, wkv, wo);

    // fused Q + KV projection (24 n-tiles: 16 Q + 8 KV), 128 threads/CTA
    qkv_gemm<<<dim3((D_MODEL + NKV2) / BN, MROWS / BM), GTHREADS, GSMEM>>>(
        ahat, wq, wkv, qhi, qlo, khi, vhi);

    // attention
    attn_hmma<<<dim3(S_LEN / 128, NHEADS, BATCH), 256>>>(qhi, qlo, khi, vhi, chat);

    // output projection (K = 2048)
    out_gemm<<<dim3(D_MODEL / BN, MROWS / BM), GTHREADS, GSMEM>>>(chat, wo, out);
}

// round 13
// speedup vs baseline: 2.4371x; 1.3005x over previous
#include <cuda_runtime.h>
#include <cuda_fp16.h>
#include <math.h>
#include <cstdint>

#define BATCH   2
#define S_LEN   2048
#define D_MODEL 2048
#define NHEADS  32
#define NKVH    8
#define HDIM    64
#define GSIZE   (NHEADS / NKVH)
#define KVD     (NKVH * HDIM)        // 512
#define MROWS   (BATCH * S_LEN)      // 4096
#define KDIM    2048
#define NKV2    (2 * KVD)            // 1024 fused K|V width

// ---------------- scratch (device globals) ----------------------------------
__device__ __half g_ahat[(size_t)MROWS  * KDIM];    // x hi only
__device__ __half g_chat[(size_t)MROWS  * KDIM];    // ctx hi only
__device__ __half g_wq [(size_t)D_MODEL * KDIM];
__device__ __half g_wkv[(size_t)NKV2    * KDIM];
__device__ __half g_wo [(size_t)D_MODEL * KDIM];
__device__ float g_cos[S_LEN * 32];
__device__ float g_sin[S_LEN * 32];
__device__ __half g_qhi[MROWS * D_MODEL];
__device__ __half g_qlo[MROWS * D_MODEL];
__device__ __half g_khi[MROWS * KVD];
__device__ __half g_vhi[MROWS * KVD];

// ---------------- helpers ------------------------------------------------
__device__ __forceinline__ uint32_t smem_u32(const void* p) {
    uint32_t a;
    asm("{ .reg .u64 t; cvta.to.shared.u64 t, %1; cvt.u32.u64 %0, t; }"
        : "=r"(a) : "l"(p));
    return a;
}

__device__ __forceinline__ void cp16(uint32_t saddr, const void* gaddr) {
    asm volatile("cp.async.cg.shared.global [%0], [%1], 16;"
                 :: "r"(saddr), "l"(gaddr) : "memory");
}
#define CP_COMMIT() asm volatile("cp.async.commit_group;" ::: "memory")
#define CP_WAIT(n)  asm volatile("cp.async.wait_group %0;" :: "n"(n) : "memory")

__device__ __forceinline__ void ldsm4(uint32_t& r0, uint32_t& r1, uint32_t& r2,
                                      uint32_t& r3, uint32_t addr) {
    asm volatile("ldmatrix.sync.aligned.m8n8.x4.shared.b16 {%0,%1,%2,%3}, [%4];"
                 : "=r"(r0), "=r"(r1), "=r"(r2), "=r"(r3) : "r"(addr));
}
__device__ __forceinline__ void ldsm4t(uint32_t& r0, uint32_t& r1, uint32_t& r2,
                                       uint32_t& r3, uint32_t addr) {
    asm volatile("ldmatrix.sync.aligned.m8n8.x4.trans.shared.b16 {%0,%1,%2,%3}, [%4];"
                 : "=r"(r0), "=r"(r1), "=r"(r2), "=r"(r3) : "r"(addr));
}

__device__ __forceinline__ void mma16816(float* d, const uint32_t* a, const uint32_t* b) {
    asm volatile(
        "mma.sync.aligned.m16n8k16.row.col.f32.f16.f16.f32 "
        "{%0,%1,%2,%3}, {%4,%5,%6,%7}, {%8,%9}, {%0,%1,%2,%3};"
        : "+f"(d[0]), "+f"(d[1]), "+f"(d[2]), "+f"(d[3])
        : "r"(a[0]), "r"(a[1]), "r"(a[2]), "r"(a[3]), "r"(b[0]), "r"(b[1]));
}

__device__ __forceinline__ uint32_t pack2h(float lo_e, float hi_e) {
    __half2 h = __floats2half2_rn(lo_e, hi_e);
    return *reinterpret_cast<uint32_t*>(&h);
}

__device__ __forceinline__ void store_split2(__half* hi, __half* lo, size_t off,
                                             float ya, float yb) {
    __half2 h = __floats2half2_rn(ya, yb);
    *reinterpret_cast<__half2*>(hi + off) = h;
    __half2 l = __floats2half2_rn(ya - __low2float(h), yb - __high2float(h));
    *reinterpret_cast<__half2*>(lo + off) = l;
}

// ---------------- fused prep kernel -------------------------------------------
#define PREP_SPLIT_BLOCKS 32768
#define PREP_ROPE_BLOCKS  256
#define PREP_BLOCKS       (PREP_SPLIT_BLOCKS + PREP_ROPE_BLOCKS + 10240)

__device__ __forceinline__ void wt_body(const float* __restrict__ W,
                                        __half* __restrict__ out, int N,
                                        int bx, int by, float tile[32][33])
{
    int tx = threadIdx.x & 31, tg = threadIdx.x >> 5;
    int k0 = by * 32, n0 = bx * 32;
    #pragma unroll
    for (int i = 0; i < 4; i++) {
        int ty = tg * 4 + i;
        tile[ty][tx] = W[(size_t)(k0 + ty) * N + n0 + tx];
    }
    __syncthreads();
    #pragma unroll
    for (int i = 0; i < 4; i++) {
        int ty = tg * 4 + i;
        out[(size_t)(n0 + ty) * KDIM + k0 + tx] = __float2half_rn(tile[tx][ty]);
    }
}

__global__ __launch_bounds__(256)
void prep(const float* __restrict__ x,
          const float* __restrict__ Wq, const float* __restrict__ Wk,
          const float* __restrict__ Wv, const float* __restrict__ Wo,
          __half* __restrict__ ahat, __half* __restrict__ wq,
          __half* __restrict__ wkv, __half* __restrict__ wo)
{
    __shared__ float tile[32][33];
    const int bid = blockIdx.x;
    const int tid = threadIdx.x;

    if (bid < PREP_SPLIT_BLOCKS) {
        int i = bid * 256 + tid;
        ahat[i] = __float2half_rn(x[i]);
    } else if (bid < PREP_SPLIT_BLOCKS + PREP_ROPE_BLOCKS) {
        int i = (bid - PREP_SPLIT_BLOCKS) * 256 + tid;
        int s = i >> 5, j = i & 31;
        float inv = (float)exp(-(double)j * (log(10000.0) / 32.0));
        float ang = (float)s * inv;
        float c, sn;
        sincosf(ang, &sn, &c);
        g_cos[i] = c;
        g_sin[i] = sn;
    } else {
        int idx = bid - (PREP_SPLIT_BLOCKS + PREP_ROPE_BLOCKS);
        if (idx < 4096) {
            wt_body(Wq, wq, D_MODEL, idx & 63, idx >> 6, tile);
        } else if (idx < 5120) {
            int l = idx - 4096;
            wt_body(Wk, wkv, KVD, l & 15, l >> 4, tile);
        } else if (idx < 6144) {
            int l = idx - 5120;
            wt_body(Wv, wkv + (size_t)KVD * KDIM, KVD, l & 15, l >> 4, tile);
        } else {
            int l = idx - 6144;
            wt_body(Wo, wo, D_MODEL, l & 63, l >> 6, tile);
        }
    }
}

// ---------------- GEMM core ----------------------------------------------------
// 128x128 CTA, 4 warps (2M x 2N), warp tile 64x64, KC=64, 3 stages, 128 threads.
#define BM 128
#define BN 128
#define KC 64
#define STAGES 3
#define RSB    144
#define STG_A  (128 * RSB)
#define STG_SZ (2 * STG_A)
#define GSMEM  (STAGES * STG_SZ)     // 110592
#define GTHREADS 128

__device__ __forceinline__ void gemm_core(
    const __half* __restrict__ Ab, const __half* __restrict__ Bb,
    uint32_t sbase, int tid, int lane, int wm, int wn, float acc[4][8][4])
{
    constexpr int NCHUNK = KDIM / KC;

    const int a_row  = wm + (lane & 15);
    const int a_koff = ((lane >> 4) & 1) * 8;
    const int b_row_base = wn + (lane & 7) + ((lane >> 4) & 1) * 8;
    const int b_koff = ((lane >> 3) & 1) * 8;

    auto fill = [&](int c, int slot) {
        const int kpos = c * KC;
        const uint32_t abase = sbase + slot * STG_SZ;
        const uint32_t bbase = abase + STG_A;
        #pragma unroll
        for (int i = 0; i < 8; i++) {
            int u = tid + GTHREADS * i;
            int row = u >> 3, seg = u & 7;
            cp16(abase + row * RSB + seg * 16, Ab + (size_t)row * KDIM + kpos + seg * 8);
            cp16(bbase + row * RSB + seg * 16, Bb + (size_t)row * KDIM + kpos + seg * 8);
        }
    };

    #pragma unroll
    for (int s = 0; s < STAGES - 1; s++) {
        fill(s, s);
        CP_COMMIT();
    }

    for (int c = 0; c < NCHUNK; c++) {
        CP_WAIT(STAGES - 2);
        __syncthreads();

        if (c + STAGES - 1 < NCHUNK)
            fill(c + STAGES - 1, (c + STAGES - 1) % STAGES);
        CP_COMMIT();

        const int slot = c % STAGES;
        const uint32_t abase = sbase + slot * STG_SZ;
        const uint32_t bbase = abase + STG_A;
        #pragma unroll
        for (int ks = 0; ks < 4; ks++) {
            const int kp = ks * 16;
            uint32_t af[4][4];
            #pragma unroll
            for (int mt = 0; mt < 4; mt++) {
                uint32_t addr = abase + (a_row + mt * 16) * RSB + (kp + a_koff) * 2;
                ldsm4(af[mt][0], af[mt][1], af[mt][2], af[mt][3], addr);
            }
            uint32_t bf[8][2];
            #pragma unroll
            for (int bt = 0; bt < 4; bt++) {
                uint32_t addr = bbase + (b_row_base + bt * 16) * RSB + (kp + b_koff) * 2;
                ldsm4(bf[2*bt][0], bf[2*bt][1], bf[2*bt+1][0], bf[2*bt+1][1], addr);
            }
            #pragma unroll
            for (int mt = 0; mt < 4; mt++)
                #pragma unroll
                for (int nt = 0; nt < 8; nt++)
                    mma16816(acc[mt][nt], af[mt], bf[nt]);
        }
    }
}

// ---------------- fused QKV projection kernel --------------------------------
__global__ __launch_bounds__(GTHREADS)
void qkv_gemm(const __half* __restrict__ A,
              const __half* __restrict__ Wq, const __half* __restrict__ Wkv,
              __half* __restrict__ qhi, __half* __restrict__ qlo,
              __half* __restrict__ khi, __half* __restrict__ vhi)
{
    extern __shared__ char gsm[];
    const uint32_t sbase = smem_u32(gsm);

    const int tid  = threadIdx.x;
    const int wid  = tid >> 5;
    const int lane = tid & 31;
    const int bm   = blockIdx.y * BM;
    const bool isQ = blockIdx.x < (D_MODEL / BN);
    const int bn   = (isQ ? blockIdx.x : blockIdx.x - D_MODEL / BN) * BN;
    const int wm   = (wid & 1) * 64;
    const int wn   = (wid >> 1) * 64;

    float acc[4][8][4];
    #pragma unroll
    for (int i = 0; i < 4; i++)
        #pragma unroll
        for (int j = 0; j < 8; j++)
            #pragma unroll
            for (int t = 0; t < 4; t++) acc[i][j][t] = 0.f;

    const __half* Ab = A + (size_t)bm * KDIM;
    const __half* Bb = (isQ ? Wq : Wkv) + (size_t)bn * KDIM;

    gemm_core(Ab, Bb, sbase, tid, lane, wm, wn, acc);

    const int cr = lane >> 2;
    const int cc = (lane & 3) * 2;

    if (isQ) {
        const int head = (bn + wn) >> 6;
        #pragma unroll
        for (int mt = 0; mt < 4; mt++) {
            #pragma unroll
            for (int r = 0; r < 2; r++) {
                const int row = bm + wm + mt * 16 + cr + r * 8;
                const int s = row & (S_LEN - 1);
                #pragma unroll
                for (int nt = 0; nt < 4; nt++) {
                    const int j = nt * 8 + cc;
                    float c0 = g_cos[(s << 5) + j],     sn0 = g_sin[(s << 5) + j];
                    float c1 = g_cos[(s << 5) + j + 1], sn1 = g_sin[(s << 5) + j + 1];
                    float x1a = acc[mt][nt][2*r],     x1b = acc[mt][nt][2*r + 1];
                    float x2a = acc[mt][nt+4][2*r],   x2b = acc[mt][nt+4][2*r + 1];
                    float y1a = (x1a * c0 - x2a * sn0) * 0.125f;
                    float y1b = (x1b * c1 - x2b * sn1) * 0.125f;
                    float y2a = (x2a * c0 + x1a * sn0) * 0.125f;
                    float y2b = (x2b * c1 + x1b * sn1) * 0.125f;
                    size_t off = (size_t)row * D_MODEL + head * HDIM + j;
                    store_split2(qhi, qlo, off,      y1a, y1b);
                    store_split2(qhi, qlo, off + 32, y2a, y2b);
                }
            }
        }
    } else {
        const int hh = (bn + wn) >> 6;
        if (hh < NKVH) {
            #pragma unroll
            for (int mt = 0; mt < 4; mt++) {
                #pragma unroll
                for (int r = 0; r < 2; r++) {
                    const int row = bm + wm + mt * 16 + cr + r * 8;
                    const int s = row & (S_LEN - 1);
                    #pragma unroll
                    for (int nt = 0; nt < 4; nt++) {
                        const int j = nt * 8 + cc;
                        float c0 = g_cos[(s << 5) + j],     sn0 = g_sin[(s << 5) + j];
                        float c1 = g_cos[(s << 5) + j + 1], sn1 = g_sin[(s << 5) + j + 1];
                        float x1a = acc[mt][nt][2*r],   x1b = acc[mt][nt][2*r + 1];
                        float x2a = acc[mt][nt+4][2*r], x2b = acc[mt][nt+4][2*r + 1];
                        size_t off = (size_t)row * KVD + hh * HDIM + j;
                        *reinterpret_cast<__half2*>(khi + off) =
                            __floats2half2_rn(x1a * c0 - x2a * sn0, x1b * c1 - x2b * sn1);
                        *reinterpret_cast<__half2*>(khi + off + 32) =
                            __floats2half2_rn(x2a * c0 + x1a * sn0, x2b * c1 + x1b * sn1);
                    }
                }
            }
        } else {
            const int vh = hh - NKVH;
            #pragma unroll
            for (int mt = 0; mt < 4; mt++) {
                #pragma unroll
                for (int r = 0; r < 2; r++) {
                    const int row = bm + wm + mt * 16 + cr + r * 8;
                    #pragma unroll
                    for (int nt = 0; nt < 8; nt++) {
                        size_t off = (size_t)row * KVD + vh * HDIM + nt * 8 + cc;
                        *reinterpret_cast<__half2*>(vhi + off) =
                            __floats2half2_rn(acc[mt][nt][2*r], acc[mt][nt][2*r + 1]);
                    }
                }
            }
        }
    }
}

// ---------------- output projection kernel -----------------------------------
__global__ __launch_bounds__(GTHREADS)
void out_gemm(const __half* __restrict__ A, const __half* __restrict__ B,
              float* __restrict__ C)
{
    extern __shared__ char gsm[];
    const uint32_t sbase = smem_u32(gsm);

    const int tid  = threadIdx.x;
    const int wid  = tid >> 5;
    const int lane = tid & 31;
    const int bm   = blockIdx.y * BM;
    const int bn   = blockIdx.x * BN;
    const int wm   = (wid & 1) * 64;
    const int wn   = (wid >> 1) * 64;

    float acc[4][8][4];
    #pragma unroll
    for (int i = 0; i < 4; i++)
        #pragma unroll
        for (int j = 0; j < 8; j++)
            #pragma unroll
            for (int t = 0; t < 4; t++) acc[i][j][t] = 0.f;

    gemm_core(A + (size_t)bm * KDIM, B + (size_t)bn * KDIM,
              sbase, tid, lane, wm, wn, acc);

    const int cr = lane >> 2;
    const int cc = (lane & 3) * 2;
    #pragma unroll
    for (int mt = 0; mt < 4; mt++) {
        #pragma unroll
        for (int nt = 0; nt < 8; nt++) {
            float* p0 = C + (size_t)(bm + wm + mt * 16 + cr) * D_MODEL + bn + wn + nt * 8 + cc;
            float* p1 = p0 + 8 * (size_t)D_MODEL;
            p0[0] = acc[mt][nt][0]; p0[1] = acc[mt][nt][1];
            p1[0] = acc[mt][nt][2]; p1[1] = acc[mt][nt][3];
        }
    }
}

// ---------------- HMMA causal GQA flash attention (unchanged from R12) -------
#define AT_STRB 144
#define KVBUF   (2 * 64 * AT_STRB)

__global__ __launch_bounds__(256, 2)
void attn_hmma(const __half* __restrict__ qhi, const __half* __restrict__ qlo,
               const __half* __restrict__ khi, const __half* __restrict__ vhi,
               __half* __restrict__ chat)
{
    __shared__ __align__(16) char sm[2 * KVBUF];

    const int qb  = gridDim.x - 1 - blockIdx.x;
    const int h   = blockIdx.y;
    const int b   = blockIdx.z;
    const int kvh = h / GSIZE;
    const int tid = threadIdx.x;
    const int wid = tid >> 5;
    const int lane = tid & 31;
    const int qrow0 = qb * 128;
    const int wm = wid * 16;

    const uint32_t sbase = smem_u32(sm);
    const int VOFF = 64 * AT_STRB;

    {
        const __half* srcs[2] = {qhi, qlo};
        #pragma unroll
        for (int arr = 0; arr < 2; arr++) {
            const __half* s = srcs[arr];
            #pragma unroll
            for (int i = 0; i < 4; i++) {
                int u = tid + 256 * i;
                int row = u >> 3, seg = u & 7;
                uint4 v = *(const uint4*)(s + ((size_t)(b * S_LEN + qrow0 + row)) * D_MODEL
                                            + h * HDIM + seg * 8);
                *(uint4*)(sm + arr * (128 * AT_STRB) + row * AT_STRB + seg * 16) = v;
            }
        }
    }
    __syncthreads();

    uint32_t qh[4][4], ql[4][4];
    {
        uint32_t arow = (uint32_t)(wm + (lane & 15));
        uint32_t koff = ((lane >> 4) & 1) * 8;
        #pragma unroll
        for (int kc = 0; kc < 4; kc++) {
            uint32_t a0 = sbase + arow * AT_STRB + (kc * 16 + koff) * 2;
            ldsm4(qh[kc][0], qh[kc][1], qh[kc][2], qh[kc][3], a0);
            ldsm4(ql[kc][0], ql[kc][1], ql[kc][2], ql[kc][3], a0 + 128 * AT_STRB);
        }
    }
    __syncthreads();

    float m0 = -1e30f, m1 = -1e30f, l0 = 0.f, l1 = 0.f;
    float ctxa[8][4];
    #pragma unroll
    for (int t = 0; t < 8; t++)
        #pragma unroll
        for (int j = 0; j < 4; j++) ctxa[t][j] = 0.f;

    const int nkt = 2 * qb + 2;

    auto fillkv = [&](int kt, int buf) {
        const int k0 = kt * 64;
        const uint32_t base = sbase + buf * KVBUF;
        const __half* srcs[2] = {khi, vhi};
        #pragma unroll
        for (int arr = 0; arr < 2; arr++) {
            const __half* s = srcs[arr];
            #pragma unroll
            for (int i = 0; i < 2; i++) {
                int u = tid + 256 * i;
                int row = u >> 3, seg = u & 7;
                cp16(base + arr * VOFF + row * AT_STRB + seg * 16,
                     s + ((size_t)(b * S_LEN + k0 + row)) * KVD + kvh * HDIM + seg * 8);
            }
        }
    };

    fillkv(0, 0);
    CP_COMMIT();

    for (int kt = 0; kt < nkt; kt++) {
        const int k0 = kt * 64;
        const int buf = kt & 1;
        __syncthreads();
        if (kt + 1 < nkt) {
            fillkv(kt + 1, buf ^ 1);
            CP_COMMIT();
            CP_WAIT(1);
        } else {
            CP_WAIT(0);
        }
        __syncthreads();

        const uint32_t kvbase = sbase + buf * KVBUF;

        if (k0 <= qrow0 + wm + 15) {
            float sc[8][4];
            #pragma unroll
            for (int t = 0; t < 8; t++)
                #pragma unroll
                for (int j = 0; j < 4; j++) sc[t][j] = 0.f;

            #pragma unroll
            for (int g = 0; g < 4; g++) {
                uint32_t kh[4][4];
                #pragma unroll
                for (int kc = 0; kc < 4; kc++) {
                    uint32_t addr = kvbase
                        + (g * 16 + (lane & 7) + ((lane >> 4) & 1) * 8) * AT_STRB
                        + (kc * 16 + ((lane >> 3) & 1) * 8) * 2;
                    ldsm4(kh[kc][0], kh[kc][1], kh[kc][2], kh[kc][3], addr);
                }
                #pragma unroll
                for (int kc = 0; kc < 4; kc++) {
                    uint32_t bh0[2] = {kh[kc][0], kh[kc][1]};
                    uint32_t bh1[2] = {kh[kc][2], kh[kc][3]};
                    mma16816(sc[2*g],   qh[kc], bh0);
                    mma16816(sc[2*g],   ql[kc], bh0);
                    mma16816(sc[2*g+1], qh[kc], bh1);
                    mma16816(sc[2*g+1], ql[kc], bh1);
                }
            }

            const int rtop = qrow0 + wm + (lane >> 2);
            const int rbot = rtop + 8;
            if (kt >= nkt - 2) {
                #pragma unroll
                for (int t = 0; t < 8; t++) {
                    int kg = k0 + t * 8 + (lane & 3) * 2;
                    if (kg     > rtop) sc[t][0] = -1e30f;
                    if (kg + 1 > rtop) sc[t][1] = -1e30f;
                    if (kg     > rbot) sc[t][2] = -1e30f;
                    if (kg + 1 > rbot) sc[t][3] = -1e30f;
                }
            }

            float tm0 = -1e30f, tm1 = -1e30f;
            #pragma unroll
            for (int t = 0; t < 8; t++) {
                tm0 = fmaxf(tm0, fmaxf(sc[t][0], sc[t][1]));
                tm1 = fmaxf(tm1, fmaxf(sc[t][2], sc[t][3]));
            }
            tm0 = fmaxf(tm0, __shfl_xor_sync(0xFFFFFFFFu, tm0, 1));
            tm0 = fmaxf(tm0, __shfl_xor_sync(0xFFFFFFFFu, tm0, 2));
            tm1 = fmaxf(tm1, __shfl_xor_sync(0xFFFFFFFFu, tm1, 1));
            tm1 = fmaxf(tm1, __shfl_xor_sync(0xFFFFFFFFu, tm1, 2));
            float mn0 = fmaxf(m0, tm0), mn1 = fmaxf(m1, tm1);
            float c0 = __expf(m0 - mn0), c1 = __expf(m1 - mn1);
            m0 = mn0; m1 = mn1;
            l0 *= c0;  l1 *= c1;
            #pragma unroll
            for (int t = 0; t < 8; t++) {
                ctxa[t][0] *= c0; ctxa[t][1] *= c0;
                ctxa[t][2] *= c1; ctxa[t][3] *= c1;
            }

            float ps0 = 0.f, ps1 = 0.f;
            uint32_t ph[4][4];
            #pragma unroll
            for (int t = 0; t < 8; t++) {
                float p0 = __expf(sc[t][0] - mn0);
                float p1 = __expf(sc[t][1] - mn0);
                float p2 = __expf(sc[t][2] - mn1);
                float p3 = __expf(sc[t][3] - mn1);
                ps0 += p0 + p1; ps1 += p2 + p3;
                int kc = t >> 1, hf = (t & 1) * 2;
                ph[kc][hf]     = pack2h(p0, p1);
                ph[kc][hf + 1] = pack2h(p2, p3);
            }
            ps0 += __shfl_xor_sync(0xFFFFFFFFu, ps0, 1);
            ps0 += __shfl_xor_sync(0xFFFFFFFFu, ps0, 2);
            ps1 += __shfl_xor_sync(0xFFFFFFFFu, ps1, 1);
            ps1 += __shfl_xor_sync(0xFFFFFFFFu, ps1, 2);
            l0 += ps0; l1 += ps1;

            #pragma unroll
            for (int kc = 0; kc < 4; kc++) {
                #pragma unroll
                for (int g = 0; g < 4; g++) {
                    uint32_t vh[4];
                    uint32_t addr = kvbase + VOFF
                        + (kc * 16 + (lane & 7) + ((lane >> 3) & 1) * 8) * AT_STRB
                        + (g * 16 + ((lane >> 4) & 1) * 8) * 2;
                    ldsm4t(vh[0], vh[1], vh[2], vh[3], addr);
                    uint32_t bh0[2] = {vh[0], vh[1]};
                    uint32_t bh1[2] = {vh[2], vh[3]};
                    mma16816(ctxa[2*g],   ph[kc], bh0);
                    mma16816(ctxa[2*g+1], ph[kc], bh1);
                }
            }
        }
    }

    float il0 = 1.f / l0, il1 = 1.f / l1;
    const int rtop = qrow0 + wm + (lane >> 2);
    const size_t row0 = (size_t)(b * S_LEN) + rtop;
    __half* c0p = chat + row0 * KDIM + h * HDIM;
    __half* c1p = c0p + 8 * (size_t)KDIM;
    #pragma unroll
    for (int t = 0; t < 8; t++) {
        int col = t * 8 + (lane & 3) * 2;
        *reinterpret_cast<__half2*>(c0p + col) =
            __floats2half2_rn(ctxa[t][0] * il0, ctxa[t][1] * il0);
        *reinterpret_cast<__half2*>(c1p + col) =
            __floats2half2_rn(ctxa[t][2] * il1, ctxa[t][3] * il1);
    }
}

// ---------------- host launch -------------------------------------------------
extern "C" void kernel_launch(void* const* d_in, const int* in_sizes, int n_in,
                              void* d_out, int out_size)
{
    const float* x  = (const float*)d_in[0];
    const float* Wq = (const float*)d_in[1];
    const float* Wk = (const float*)d_in[2];
    const float* Wv = (const float*)d_in[3];
    const float* Wo = (const float*)d_in[4];
    float* out = (float*)d_out;

    __half *ahat, *chat, *wq, *wkv, *wo, *qhi, *qlo, *khi, *vhi;
    cudaGetSymbolAddress((void**)&ahat, g_ahat);
    cudaGetSymbolAddress((void**)&chat, g_chat);
    cudaGetSymbolAddress((void**)&wq,   g_wq);
    cudaGetSymbolAddress((void**)&wkv,  g_wkv);
    cudaGetSymbolAddress((void**)&wo,   g_wo);
    cudaGetSymbolAddress((void**)&qhi,  g_qhi);
    cudaGetSymbolAddress((void**)&qlo,  g_qlo);
    cudaGetSymbolAddress((void**)&khi,  g_khi);
    cudaGetSymbolAddress((void**)&vhi,  g_vhi);

    static int smem_set = 0;
    if (!smem_set) {
        cudaFuncSetAttribute(qkv_gemm, cudaFuncAttributeMaxDynamicSharedMemorySize, GSMEM);
        cudaFuncSetAttribute(out_gemm, cudaFuncAttributeMaxDynamicSharedMemorySize, GSMEM);
        smem_set = 1;
    }

    // fused prep
    prep<<<PREP_BLOCKS, 256>>>(x, Wq, Wk, Wv, Wo, ahat, wq, wkv, wo);

    // fused Q + KV projection (24 n-tiles: 16 Q + 8 KV), K = 2048
    qkv_gemm<<<dim3((D_MODEL + NKV2) / BN, MROWS / BM), GTHREADS, GSMEM>>>(
        ahat, wq, wkv, qhi, qlo, khi, vhi);

    // attention
    attn_hmma<<<dim3(S_LEN / 128, NHEADS, BATCH), 256>>>(qhi, qlo, khi, vhi, chat);

    // output projection (K = 2048)
    out_gemm<<<dim3(D_MODEL / BN, MROWS / BM), GTHREADS, GSMEM>>>(chat, wo, out);
}

// round 14
// speedup vs baseline: 2.6382x; 1.0825x over previous
#include <cuda_runtime.h>
#include <cuda_fp16.h>
#include <math.h>
#include <cstdint>

#define BATCH   2
#define S_LEN   2048
#define D_MODEL 2048
#define NHEADS  32
#define NKVH    8
#define HDIM    64
#define GSIZE   (NHEADS / NKVH)
#define KVD     (NKVH * HDIM)        // 512
#define MROWS   (BATCH * S_LEN)      // 4096
#define KDIM    2048
#define NKV2    (2 * KVD)            // 1024 fused K|V width

// ---------------- scratch (device globals) ----------------------------------
__device__ __half g_ahat[(size_t)MROWS  * KDIM];    // x hi only
__device__ __half g_chat[(size_t)MROWS  * KDIM];    // ctx hi only
__device__ __half g_wq [(size_t)D_MODEL * KDIM];
__device__ __half g_wkv[(size_t)NKV2    * KDIM];
__device__ __half g_wo [(size_t)D_MODEL * KDIM];
__device__ float g_cos[S_LEN * 32];
__device__ float g_sin[S_LEN * 32];
__device__ __half g_q16[MROWS * D_MODEL];
__device__ __half g_khi[MROWS * KVD];
__device__ __half g_vhi[MROWS * KVD];

// ---------------- helpers ------------------------------------------------
__device__ __forceinline__ uint32_t smem_u32(const void* p) {
    uint32_t a;
    asm("{ .reg .u64 t; cvta.to.shared.u64 t, %1; cvt.u32.u64 %0, t; }"
        : "=r"(a) : "l"(p));
    return a;
}

__device__ __forceinline__ void cp16(uint32_t saddr, const void* gaddr) {
    asm volatile("cp.async.cg.shared.global [%0], [%1], 16;"
                 :: "r"(saddr), "l"(gaddr) : "memory");
}
#define CP_COMMIT() asm volatile("cp.async.commit_group;" ::: "memory")
#define CP_WAIT(n)  asm volatile("cp.async.wait_group %0;" :: "n"(n) : "memory")

__device__ __forceinline__ void ldsm4(uint32_t& r0, uint32_t& r1, uint32_t& r2,
                                      uint32_t& r3, uint32_t addr) {
    asm volatile("ldmatrix.sync.aligned.m8n8.x4.shared.b16 {%0,%1,%2,%3}, [%4];"
                 : "=r"(r0), "=r"(r1), "=r"(r2), "=r"(r3) : "r"(addr));
}
__device__ __forceinline__ void ldsm4t(uint32_t& r0, uint32_t& r1, uint32_t& r2,
                                       uint32_t& r3, uint32_t addr) {
    asm volatile("ldmatrix.sync.aligned.m8n8.x4.trans.shared.b16 {%0,%1,%2,%3}, [%4];"
                 : "=r"(r0), "=r"(r1), "=r"(r2), "=r"(r3) : "r"(addr));
}

__device__ __forceinline__ void mma16816(float* d, const uint32_t* a, const uint32_t* b) {
    asm volatile(
        "mma.sync.aligned.m16n8k16.row.col.f32.f16.f16.f32 "
        "{%0,%1,%2,%3}, {%4,%5,%6,%7}, {%8,%9}, {%0,%1,%2,%3};"
        : "+f"(d[0]), "+f"(d[1]), "+f"(d[2]), "+f"(d[3])
        : "r"(a[0]), "r"(a[1]), "r"(a[2]), "r"(a[3]), "r"(b[0]), "r"(b[1]));
}

__device__ __forceinline__ uint32_t pack2h(float lo_e, float hi_e) {
    __half2 h = __floats2half2_rn(lo_e, hi_e);
    return *reinterpret_cast<uint32_t*>(&h);
}

// ---------------- fused prep kernel -------------------------------------------
#define PREP_SPLIT_BLOCKS 32768
#define PREP_ROPE_BLOCKS  256
#define PREP_BLOCKS       (PREP_SPLIT_BLOCKS + PREP_ROPE_BLOCKS + 10240)

__device__ __forceinline__ void wt_body(const float* __restrict__ W,
                                        __half* __restrict__ out, int N,
                                        int bx, int by, float tile[32][33])
{
    int tx = threadIdx.x & 31, tg = threadIdx.x >> 5;
    int k0 = by * 32, n0 = bx * 32;
    #pragma unroll
    for (int i = 0; i < 4; i++) {
        int ty = tg * 4 + i;
        tile[ty][tx] = W[(size_t)(k0 + ty) * N + n0 + tx];
    }
    __syncthreads();
    #pragma unroll
    for (int i = 0; i < 4; i++) {
        int ty = tg * 4 + i;
        out[(size_t)(n0 + ty) * KDIM + k0 + tx] = __float2half_rn(tile[tx][ty]);
    }
}

__global__ __launch_bounds__(256)
void prep(const float* __restrict__ x,
          const float* __restrict__ Wq, const float* __restrict__ Wk,
          const float* __restrict__ Wv, const float* __restrict__ Wo,
          __half* __restrict__ ahat, __half* __restrict__ wq,
          __half* __restrict__ wkv, __half* __restrict__ wo)
{
    __shared__ float tile[32][33];
    const int bid = blockIdx.x;
    const int tid = threadIdx.x;

    if (bid < PREP_SPLIT_BLOCKS) {
        int i = bid * 256 + tid;
        ahat[i] = __float2half_rn(x[i]);
    } else if (bid < PREP_SPLIT_BLOCKS + PREP_ROPE_BLOCKS) {
        int i = (bid - PREP_SPLIT_BLOCKS) * 256 + tid;
        int s = i >> 5, j = i & 31;
        float inv = (float)exp(-(double)j * (log(10000.0) / 32.0));
        float ang = (float)s * inv;
        float c, sn;
        sincosf(ang, &sn, &c);
        g_cos[i] = c;
        g_sin[i] = sn;
    } else {
        int idx = bid - (PREP_SPLIT_BLOCKS + PREP_ROPE_BLOCKS);
        if (idx < 4096) {
            wt_body(Wq, wq, D_MODEL, idx & 63, idx >> 6, tile);
        } else if (idx < 5120) {
            int l = idx - 4096;
            wt_body(Wk, wkv, KVD, l & 15, l >> 4, tile);
        } else if (idx < 6144) {
            int l = idx - 5120;
            wt_body(Wv, wkv + (size_t)KVD * KDIM, KVD, l & 15, l >> 4, tile);
        } else {
            int l = idx - 6144;
            wt_body(Wo, wo, D_MODEL, l & 63, l >> 6, tile);
        }
    }
}

// ---------------- GEMM core ----------------------------------------------------
// 128x128 CTA, 4 warps (2M x 2N), warp tile 64x64, KC=64, 3 stages, 128 threads.
#define BM 128
#define BN 128
#define KC 64
#define STAGES 3
#define RSB    144
#define STG_A  (128 * RSB)
#define STG_SZ (2 * STG_A)
#define GSMEM  (STAGES * STG_SZ)     // 110592
#define GTHREADS 128

__device__ __forceinline__ void gemm_core(
    const __half* __restrict__ Ab, const __half* __restrict__ Bb,
    uint32_t sbase, int tid, int lane, int wm, int wn, float acc[4][8][4])
{
    constexpr int NCHUNK = KDIM / KC;

    const int a_row  = wm + (lane & 15);
    const int a_koff = ((lane >> 4) & 1) * 8;
    const int b_row_base = wn + (lane & 7) + ((lane >> 4) & 1) * 8;
    const int b_koff = ((lane >> 3) & 1) * 8;

    auto fill = [&](int c, int slot) {
        const int kpos = c * KC;
        const uint32_t abase = sbase + slot * STG_SZ;
        const uint32_t bbase = abase + STG_A;
        #pragma unroll
        for (int i = 0; i < 8; i++) {
            int u = tid + GTHREADS * i;
            int row = u >> 3, seg = u & 7;
            cp16(abase + row * RSB + seg * 16, Ab + (size_t)row * KDIM + kpos + seg * 8);
            cp16(bbase + row * RSB + seg * 16, Bb + (size_t)row * KDIM + kpos + seg * 8);
        }
    };

    #pragma unroll
    for (int s = 0; s < STAGES - 1; s++) {
        fill(s, s);
        CP_COMMIT();
    }

    for (int c = 0; c < NCHUNK; c++) {
        CP_WAIT(STAGES - 2);
        __syncthreads();

        if (c + STAGES - 1 < NCHUNK)
            fill(c + STAGES - 1, (c + STAGES - 1) % STAGES);
        CP_COMMIT();

        const int slot = c % STAGES;
        const uint32_t abase = sbase + slot * STG_SZ;
        const uint32_t bbase = abase + STG_A;
        #pragma unroll
        for (int ks = 0; ks < 4; ks++) {
            const int kp = ks * 16;
            uint32_t af[4][4];
            #pragma unroll
            for (int mt = 0; mt < 4; mt++) {
                uint32_t addr = abase + (a_row + mt * 16) * RSB + (kp + a_koff) * 2;
                ldsm4(af[mt][0], af[mt][1], af[mt][2], af[mt][3], addr);
            }
            uint32_t bf[8][2];
            #pragma unroll
            for (int bt = 0; bt < 4; bt++) {
                uint32_t addr = bbase + (b_row_base + bt * 16) * RSB + (kp + b_koff) * 2;
                ldsm4(bf[2*bt][0], bf[2*bt][1], bf[2*bt+1][0], bf[2*bt+1][1], addr);
            }
            #pragma unroll
            for (int mt = 0; mt < 4; mt++)
                #pragma unroll
                for (int nt = 0; nt < 8; nt++)
                    mma16816(acc[mt][nt], af[mt], bf[nt]);
        }
    }
}

// ---------------- fused QKV projection kernel --------------------------------
__global__ __launch_bounds__(GTHREADS)
void qkv_gemm(const __half* __restrict__ A,
              const __half* __restrict__ Wq, const __half* __restrict__ Wkv,
              __half* __restrict__ q16,
              __half* __restrict__ khi, __half* __restrict__ vhi)
{
    extern __shared__ char gsm[];
    const uint32_t sbase = smem_u32(gsm);

    const int tid  = threadIdx.x;
    const int wid  = tid >> 5;
    const int lane = tid & 31;
    const int bm   = blockIdx.y * BM;
    const bool isQ = blockIdx.x < (D_MODEL / BN);
    const int bn   = (isQ ? blockIdx.x : blockIdx.x - D_MODEL / BN) * BN;
    const int wm   = (wid & 1) * 64;
    const int wn   = (wid >> 1) * 64;

    float acc[4][8][4];
    #pragma unroll
    for (int i = 0; i < 4; i++)
        #pragma unroll
        for (int j = 0; j < 8; j++)
            #pragma unroll
            for (int t = 0; t < 4; t++) acc[i][j][t] = 0.f;

    const __half* Ab = A + (size_t)bm * KDIM;
    const __half* Bb = (isQ ? Wq : Wkv) + (size_t)bn * KDIM;

    gemm_core(Ab, Bb, sbase, tid, lane, wm, wn, acc);

    const int cr = lane >> 2;
    const int cc = (lane & 3) * 2;

    if (isQ) {
        const int head = (bn + wn) >> 6;
        #pragma unroll
        for (int mt = 0; mt < 4; mt++) {
            #pragma unroll
            for (int r = 0; r < 2; r++) {
                const int row = bm + wm + mt * 16 + cr + r * 8;
                const int s = row & (S_LEN - 1);
                #pragma unroll
                for (int nt = 0; nt < 4; nt++) {
                    const int j = nt * 8 + cc;
                    float c0 = g_cos[(s << 5) + j],     sn0 = g_sin[(s << 5) + j];
                    float c1 = g_cos[(s << 5) + j + 1], sn1 = g_sin[(s << 5) + j + 1];
                    float x1a = acc[mt][nt][2*r],     x1b = acc[mt][nt][2*r + 1];
                    float x2a = acc[mt][nt+4][2*r],   x2b = acc[mt][nt+4][2*r + 1];
                    float y1a = (x1a * c0 - x2a * sn0) * 0.125f;
                    float y1b = (x1b * c1 - x2b * sn1) * 0.125f;
                    float y2a = (x2a * c0 + x1a * sn0) * 0.125f;
                    float y2b = (x2b * c1 + x1b * sn1) * 0.125f;
                    size_t off = (size_t)row * D_MODEL + head * HDIM + j;
                    *reinterpret_cast<__half2*>(q16 + off)      = __floats2half2_rn(y1a, y1b);
                    *reinterpret_cast<__half2*>(q16 + off + 32) = __floats2half2_rn(y2a, y2b);
                }
            }
        }
    } else {
        const int hh = (bn + wn) >> 6;
        if (hh < NKVH) {
            #pragma unroll
            for (int mt = 0; mt < 4; mt++) {
                #pragma unroll
                for (int r = 0; r < 2; r++) {
                    const int row = bm + wm + mt * 16 + cr + r * 8;
                    const int s = row & (S_LEN - 1);
                    #pragma unroll
                    for (int nt = 0; nt < 4; nt++) {
                        const int j = nt * 8 + cc;
                        float c0 = g_cos[(s << 5) + j],     sn0 = g_sin[(s << 5) + j];
                        float c1 = g_cos[(s << 5) + j + 1], sn1 = g_sin[(s << 5) + j + 1];
                        float x1a = acc[mt][nt][2*r],   x1b = acc[mt][nt][2*r + 1];
                        float x2a = acc[mt][nt+4][2*r], x2b = acc[mt][nt+4][2*r + 1];
                        size_t off = (size_t)row * KVD + hh * HDIM + j;
                        *reinterpret_cast<__half2*>(khi + off) =
                            __floats2half2_rn(x1a * c0 - x2a * sn0, x1b * c1 - x2b * sn1);
                        *reinterpret_cast<__half2*>(khi + off + 32) =
                            __floats2half2_rn(x2a * c0 + x1a * sn0, x2b * c1 + x1b * sn1);
                    }
                }
            }
        } else {
            const int vh = hh - NKVH;
            #pragma unroll
            for (int mt = 0; mt < 4; mt++) {
                #pragma unroll
                for (int r = 0; r < 2; r++) {
                    const int row = bm + wm + mt * 16 + cr + r * 8;
                    #pragma unroll
                    for (int nt = 0; nt < 8; nt++) {
                        size_t off = (size_t)row * KVD + vh * HDIM + nt * 8 + cc;
                        *reinterpret_cast<__half2*>(vhi + off) =
                            __floats2half2_rn(acc[mt][nt][2*r], acc[mt][nt][2*r + 1]);
                    }
                }
            }
        }
    }
}

// ---------------- output projection kernel -----------------------------------
__global__ __launch_bounds__(GTHREADS)
void out_gemm(const __half* __restrict__ A, const __half* __restrict__ B,
              float* __restrict__ C)
{
    extern __shared__ char gsm[];
    const uint32_t sbase = smem_u32(gsm);

    const int tid  = threadIdx.x;
    const int wid  = tid >> 5;
    const int lane = tid & 31;
    const int bm   = blockIdx.y * BM;
    const int bn   = blockIdx.x * BN;
    const int wm   = (wid & 1) * 64;
    const int wn   = (wid >> 1) * 64;

    float acc[4][8][4];
    #pragma unroll
    for (int i = 0; i < 4; i++)
        #pragma unroll
        for (int j = 0; j < 8; j++)
            #pragma unroll
            for (int t = 0; t < 4; t++) acc[i][j][t] = 0.f;

    gemm_core(A + (size_t)bm * KDIM, B + (size_t)bn * KDIM,
              sbase, tid, lane, wm, wn, acc);

    const int cr = lane >> 2;
    const int cc = (lane & 3) * 2;
    #pragma unroll
    for (int mt = 0; mt < 4; mt++) {
        #pragma unroll
        for (int nt = 0; nt < 8; nt++) {
            float* p0 = C + (size_t)(bm + wm + mt * 16 + cr) * D_MODEL + bn + wn + nt * 8 + cc;
            float* p1 = p0 + 8 * (size_t)D_MODEL;
            p0[0] = acc[mt][nt][0]; p0[1] = acc[mt][nt][1];
            p1[0] = acc[mt][nt][2]; p1[1] = acc[mt][nt][3];
        }
    }
}

// ---------------- HMMA causal GQA flash attention ----------------------------
// All-fp16-hi: Q, K, V, P single precision-fp16 operands; fp32 accum/softmax.
#define AT_STRB 144
#define KVBUF   (2 * 64 * AT_STRB)

__global__ __launch_bounds__(256, 2)
void attn_hmma(const __half* __restrict__ q16,
               const __half* __restrict__ khi, const __half* __restrict__ vhi,
               __half* __restrict__ chat)
{
    __shared__ __align__(16) char sm[2 * KVBUF];

    const int qb  = gridDim.x - 1 - blockIdx.x;
    const int h   = blockIdx.y;
    const int b   = blockIdx.z;
    const int kvh = h / GSIZE;
    const int tid = threadIdx.x;
    const int wid = tid >> 5;
    const int lane = tid & 31;
    const int qrow0 = qb * 128;
    const int wm = wid * 16;

    const uint32_t sbase = smem_u32(sm);
    const int VOFF = 64 * AT_STRB;

    // ---- Q phase: 128 rows fp16 into smem (18432 B)
    {
        #pragma unroll
        for (int i = 0; i < 4; i++) {
            int u = tid + 256 * i;
            int row = u >> 3, seg = u & 7;
            uint4 v = *(const uint4*)(q16 + ((size_t)(b * S_LEN + qrow0 + row)) * D_MODEL
                                          + h * HDIM + seg * 8);
            *(uint4*)(sm + row * AT_STRB + seg * 16) = v;
        }
    }
    __syncthreads();

    uint32_t qh[4][4];
    {
        uint32_t arow = (uint32_t)(wm + (lane & 15));
        uint32_t koff = ((lane >> 4) & 1) * 8;
        #pragma unroll
        for (int kc = 0; kc < 4; kc++) {
            uint32_t a0 = sbase + arow * AT_STRB + (kc * 16 + koff) * 2;
            ldsm4(qh[kc][0], qh[kc][1], qh[kc][2], qh[kc][3], a0);
        }
    }
    __syncthreads();

    float m0 = -1e30f, m1 = -1e30f, l0 = 0.f, l1 = 0.f;
    float ctxa[8][4];
    #pragma unroll
    for (int t = 0; t < 8; t++)
        #pragma unroll
        for (int j = 0; j < 4; j++) ctxa[t][j] = 0.f;

    const int nkt = 2 * qb + 2;

    auto fillkv = [&](int kt, int buf) {
        const int k0 = kt * 64;
        const uint32_t base = sbase + buf * KVBUF;
        const __half* srcs[2] = {khi, vhi};
        #pragma unroll
        for (int arr = 0; arr < 2; arr++) {
            const __half* s = srcs[arr];
            #pragma unroll
            for (int i = 0; i < 2; i++) {
                int u = tid + 256 * i;
                int row = u >> 3, seg = u & 7;
                cp16(base + arr * VOFF + row * AT_STRB + seg * 16,
                     s + ((size_t)(b * S_LEN + k0 + row)) * KVD + kvh * HDIM + seg * 8);
            }
        }
    };

    fillkv(0, 0);
    CP_COMMIT();

    for (int kt = 0; kt < nkt; kt++) {
        const int k0 = kt * 64;
        const int buf = kt & 1;
        __syncthreads();
        if (kt + 1 < nkt) {
            fillkv(kt + 1, buf ^ 1);
            CP_COMMIT();
            CP_WAIT(1);
        } else {
            CP_WAIT(0);
        }
        __syncthreads();

        const uint32_t kvbase = sbase + buf * KVBUF;

        if (k0 <= qrow0 + wm + 15) {
            float sc[8][4];
            #pragma unroll
            for (int t = 0; t < 8; t++)
                #pragma unroll
                for (int j = 0; j < 4; j++) sc[t][j] = 0.f;

            #pragma unroll
            for (int g = 0; g < 4; g++) {
                uint32_t kh[4][4];
                #pragma unroll
                for (int kc = 0; kc < 4; kc++) {
                    uint32_t addr = kvbase
                        + (g * 16 + (lane & 7) + ((lane >> 4) & 1) * 8) * AT_STRB
                        + (kc * 16 + ((lane >> 3) & 1) * 8) * 2;
                    ldsm4(kh[kc][0], kh[kc][1], kh[kc][2], kh[kc][3], addr);
                }
                #pragma unroll
                for (int kc = 0; kc < 4; kc++) {
                    uint32_t bh0[2] = {kh[kc][0], kh[kc][1]};
                    uint32_t bh1[2] = {kh[kc][2], kh[kc][3]};
                    mma16816(sc[2*g],   qh[kc], bh0);
                    mma16816(sc[2*g+1], qh[kc], bh1);
                }
            }

            const int rtop = qrow0 + wm + (lane >> 2);
            const int rbot = rtop + 8;
            if (kt >= nkt - 2) {
                #pragma unroll
                for (int t = 0; t < 8; t++) {
                    int kg = k0 + t * 8 + (lane & 3) * 2;
                    if (kg     > rtop) sc[t][0] = -1e30f;
                    if (kg + 1 > rtop) sc[t][1] = -1e30f;
                    if (kg     > rbot) sc[t][2] = -1e30f;
                    if (kg + 1 > rbot) sc[t][3] = -1e30f;
                }
            }

            float tm0 = -1e30f, tm1 = -1e30f;
            #pragma unroll
            for (int t = 0; t < 8; t++) {
                tm0 = fmaxf(tm0, fmaxf(sc[t][0], sc[t][1]));
                tm1 = fmaxf(tm1, fmaxf(sc[t][2], sc[t][3]));
            }
            tm0 = fmaxf(tm0, __shfl_xor_sync(0xFFFFFFFFu, tm0, 1));
            tm0 = fmaxf(tm0, __shfl_xor_sync(0xFFFFFFFFu, tm0, 2));
            tm1 = fmaxf(tm1, __shfl_xor_sync(0xFFFFFFFFu, tm1, 1));
            tm1 = fmaxf(tm1, __shfl_xor_sync(0xFFFFFFFFu, tm1, 2));
            float mn0 = fmaxf(m0, tm0), mn1 = fmaxf(m1, tm1);
            float c0 = __expf(m0 - mn0), c1 = __expf(m1 - mn1);
            m0 = mn0; m1 = mn1;
            l0 *= c0;  l1 *= c1;
            #pragma unroll
            for (int t = 0; t < 8; t++) {
                ctxa[t][0] *= c0; ctxa[t][1] *= c0;
                ctxa[t][2] *= c1; ctxa[t][3] *= c1;
            }

            float ps0 = 0.f, ps1 = 0.f;
            uint32_t ph[4][4];
            #pragma unroll
            for (int t = 0; t < 8; t++) {
                float p0 = __expf(sc[t][0] - mn0);
                float p1 = __expf(sc[t][1] - mn0);
                float p2 = __expf(sc[t][2] - mn1);
                float p3 = __expf(sc[t][3] - mn1);
                ps0 += p0 + p1; ps1 += p2 + p3;
                int kc = t >> 1, hf = (t & 1) * 2;
                ph[kc][hf]     = pack2h(p0, p1);
                ph[kc][hf + 1] = pack2h(p2, p3);
            }
            ps0 += __shfl_xor_sync(0xFFFFFFFFu, ps0, 1);
            ps0 += __shfl_xor_sync(0xFFFFFFFFu, ps0, 2);
            ps1 += __shfl_xor_sync(0xFFFFFFFFu, ps1, 1);
            ps1 += __shfl_xor_sync(0xFFFFFFFFu, ps1, 2);
            l0 += ps0; l1 += ps1;

            #pragma unroll
            for (int kc = 0; kc < 4; kc++) {
                #pragma unroll
                for (int g = 0; g < 4; g++) {
                    uint32_t vh[4];
                    uint32_t addr = kvbase + VOFF
                        + (kc * 16 + (lane & 7) + ((lane >> 3) & 1) * 8) * AT_STRB
                        + (g * 16 + ((lane >> 4) & 1) * 8) * 2;
                    ldsm4t(vh[0], vh[1], vh[2], vh[3], addr);
                    uint32_t bh0[2] = {vh[0], vh[1]};
                    uint32_t bh1[2] = {vh[2], vh[3]};
                    mma16816(ctxa[2*g],   ph[kc], bh0);
                    mma16816(ctxa[2*g+1], ph[kc], bh1);
                }
            }
        }
    }

    float il0 = 1.f / l0, il1 = 1.f / l1;
    const int rtop = qrow0 + wm + (lane >> 2);
    const size_t row0 = (size_t)(b * S_LEN) + rtop;
    __half* c0p = chat + row0 * KDIM + h * HDIM;
    __half* c1p = c0p + 8 * (size_t)KDIM;
    #pragma unroll
    for (int t = 0; t < 8; t++) {
        int col = t * 8 + (lane & 3) * 2;
        *reinterpret_cast<__half2*>(c0p + col) =
            __floats2half2_rn(ctxa[t][0] * il0, ctxa[t][1] * il0);
        *reinterpret_cast<__half2*>(c1p + col) =
            __floats2half2_rn(ctxa[t][2] * il1, ctxa[t][3] * il1);
    }
}

// ---------------- host launch -------------------------------------------------
extern "C" void kernel_launch(void* const* d_in, const int* in_sizes, int n_in,
                              void* d_out, int out_size)
{
    const float* x  = (const float*)d_in[0];
    const float* Wq = (const float*)d_in[1];
    const float* Wk = (const float*)d_in[2];
    const float* Wv = (const float*)d_in[3];
    const float* Wo = (const float*)d_in[4];
    float* out = (float*)d_out;

    __half *ahat, *chat, *wq, *wkv, *wo, *q16, *khi, *vhi;
    cudaGetSymbolAddress((void**)&ahat, g_ahat);
    cudaGetSymbolAddress((void**)&chat, g_chat);
    cudaGetSymbolAddress((void**)&wq,   g_wq);
    cudaGetSymbolAddress((void**)&wkv,  g_wkv);
    cudaGetSymbolAddress((void**)&wo,   g_wo);
    cudaGetSymbolAddress((void**)&q16,  g_q16);
    cudaGetSymbolAddress((void**)&khi,  g_khi);
    cudaGetSymbolAddress((void**)&vhi,  g_vhi);

    static int smem_set = 0;
    if (!smem_set) {
        cudaFuncSetAttribute(qkv_gemm, cudaFuncAttributeMaxDynamicSharedMemorySize, GSMEM);
        cudaFuncSetAttribute(out_gemm, cudaFuncAttributeMaxDynamicSharedMemorySize, GSMEM);
        smem_set = 1;
    }

    // fused prep
    prep<<<PREP_BLOCKS, 256>>>(x, Wq, Wk, Wv, Wo, ahat, wq, wkv, wo);

    // fused Q + KV projection (24 n-tiles: 16 Q + 8 KV), K = 2048
    qkv_gemm<<<dim3((D_MODEL + NKV2) / BN, MROWS / BM), GTHREADS, GSMEM>>>(
        ahat, wq, wkv, q16, khi, vhi);

    // attention (all fp16-hi operands)
    attn_hmma<<<dim3(S_LEN / 128, NHEADS, BATCH), 256>>>(q16, khi, vhi, chat);

    // output projection (K = 2048)
    out_gemm<<<dim3(D_MODEL / BN, MROWS / BM), GTHREADS, GSMEM>>>(chat, wo, out);
}